// round 3
// baseline (speedup 1.0000x reference)
#include <cuda_runtime.h>
#include <math.h>

// ---------------------------------------------------------------------------
// Problem constants
// ---------------------------------------------------------------------------
#define S_LEN   2048
#define D_MODEL 2048
#define NHEADS  16
#define HDIM    128
#define BATCH   2
#define NTOK    (BATCH * S_LEN)   // 4096
#define QKV_N   (3 * D_MODEL)     // 6144

// ---------------------------------------------------------------------------
// Scratch (device globals -- no allocation allowed in kernel_launch)
// ---------------------------------------------------------------------------
__device__ float g_q[BATCH * NHEADS * S_LEN * HDIM];     // 33.5 MB
__device__ float g_k[BATCH * NHEADS * S_LEN * HDIM];
__device__ float g_v[BATCH * NHEADS * S_LEN * HDIM];
__device__ float g_attn[NTOK * D_MODEL];                 // 33.5 MB

// ---------------------------------------------------------------------------
// SGEMM: C[M,N] = A[M,K] @ B[K,N], all row-major fp32.
// 128x128 block tile, BK=16, 256 threads, 8x8 per thread, double buffered.
// MODE 0: plain store to C.
// MODE 1: scatter epilogue into Q/K/V [B][H][S][hd] layout (N == 6144).
// ---------------------------------------------------------------------------
#define BM 128
#define BN 128
#define BK 16

template <int MODE>
__global__ __launch_bounds__(256)
void sgemm_kernel(const float* __restrict__ A, const float* __restrict__ B,
                  float* __restrict__ C,
                  float* __restrict__ Cq, float* __restrict__ Ck,
                  float* __restrict__ Cv,
                  int N, int K)
{
    __shared__ float As[2][BK][BM + 4];   // transposed, padded vs bank conflicts
    __shared__ float Bs[2][BK][BN];

    const int tid = threadIdx.x;
    const int tx  = tid & 15;   // 0..15 -> N direction
    const int ty  = tid >> 4;   // 0..15 -> M direction

    const int brow = blockIdx.y;
    const int bcol = blockIdx.x;

    const float* Ab = A + brow * BM * K;
    const float* Bb = B + bcol * BN;

    // global->smem load mapping
    const int am = tid >> 2;          // 0..63 (and +64)
    const int ak = (tid & 3) << 2;    // 0,4,8,12
    const int bk = tid >> 5;          // 0..7 (and +8)
    const int bn = (tid & 31) << 2;   // 0..124

    float acc[8][8];
#pragma unroll
    for (int i = 0; i < 8; i++)
#pragma unroll
        for (int j = 0; j < 8; j++) acc[i][j] = 0.0f;

    float4 ra0, ra1, rb0, rb1;

    // preload tile 0
    ra0 = *(const float4*)(Ab + am * K + ak);
    ra1 = *(const float4*)(Ab + (am + 64) * K + ak);
    rb0 = *(const float4*)(Bb + bk * N + bn);
    rb1 = *(const float4*)(Bb + (bk + 8) * N + bn);
    As[0][ak + 0][am] = ra0.x; As[0][ak + 1][am] = ra0.y;
    As[0][ak + 2][am] = ra0.z; As[0][ak + 3][am] = ra0.w;
    As[0][ak + 0][am + 64] = ra1.x; As[0][ak + 1][am + 64] = ra1.y;
    As[0][ak + 2][am + 64] = ra1.z; As[0][ak + 3][am + 64] = ra1.w;
    *(float4*)&Bs[0][bk][bn]     = rb0;
    *(float4*)&Bs[0][bk + 8][bn] = rb1;
    __syncthreads();

    const int T = K / BK;
    for (int t = 0; t < T; t++) {
        const int buf = t & 1;
        if (t + 1 < T) {
            const float* Ap = Ab + (t + 1) * BK;
            const float* Bp = Bb + (t + 1) * BK * N;
            ra0 = *(const float4*)(Ap + am * K + ak);
            ra1 = *(const float4*)(Ap + (am + 64) * K + ak);
            rb0 = *(const float4*)(Bp + bk * N + bn);
            rb1 = *(const float4*)(Bp + (bk + 8) * N + bn);
        }
#pragma unroll
        for (int k = 0; k < BK; k++) {
            float a[8], b[8];
            *(float4*)&a[0] = *(float4*)&As[buf][k][ty * 8];
            *(float4*)&a[4] = *(float4*)&As[buf][k][ty * 8 + 4];
            *(float4*)&b[0] = *(float4*)&Bs[buf][k][tx * 8];
            *(float4*)&b[4] = *(float4*)&Bs[buf][k][tx * 8 + 4];
#pragma unroll
            for (int i = 0; i < 8; i++)
#pragma unroll
                for (int j = 0; j < 8; j++)
                    acc[i][j] += a[i] * b[j];
        }
        if (t + 1 < T) {
            const int nb = 1 - buf;
            As[nb][ak + 0][am] = ra0.x; As[nb][ak + 1][am] = ra0.y;
            As[nb][ak + 2][am] = ra0.z; As[nb][ak + 3][am] = ra0.w;
            As[nb][ak + 0][am + 64] = ra1.x; As[nb][ak + 1][am + 64] = ra1.y;
            As[nb][ak + 2][am + 64] = ra1.z; As[nb][ak + 3][am + 64] = ra1.w;
            *(float4*)&Bs[nb][bk][bn]     = rb0;
            *(float4*)&Bs[nb][bk + 8][bn] = rb1;
            __syncthreads();
        }
    }

    if (MODE == 0) {
#pragma unroll
        for (int i = 0; i < 8; i++) {
            int row = brow * BM + ty * 8 + i;
            float* cp = C + row * N + bcol * BN + tx * 8;
            *(float4*)cp       = make_float4(acc[i][0], acc[i][1], acc[i][2], acc[i][3]);
            *(float4*)(cp + 4) = make_float4(acc[i][4], acc[i][5], acc[i][6], acc[i][7]);
        }
    } else {
        // qkv scatter: each 128-col tile belongs to exactly one (which, head)
        const int col0  = bcol * BN;            // 0..6143, multiple of 128
        const int which = col0 >> 11;           // 0=q,1=k,2=v
        const int h     = (col0 & 2047) >> 7;   // head
        float* dst = (which == 0) ? Cq : ((which == 1) ? Ck : Cv);
#pragma unroll
        for (int i = 0; i < 8; i++) {
            int row = brow * BM + ty * 8 + i;   // token index
            int bb  = row >> 11;                // batch
            int ss  = row & 2047;               // seq pos
            float* dp = dst + (((bb * NHEADS + h) * S_LEN) + ss) * HDIM + tx * 8;
            *(float4*)dp       = make_float4(acc[i][0], acc[i][1], acc[i][2], acc[i][3]);
            *(float4*)(dp + 4) = make_float4(acc[i][4], acc[i][5], acc[i][6], acc[i][7]);
        }
    }
}

// ---------------------------------------------------------------------------
// RoPE (interleaved pairs), in place on Q and K.
// grid.x = B*H*S, block = 64 threads (one pair each).
//
// token_positions dtype is ambiguous: the reference declares int64, but JAX
// with x64 disabled silently stores int32. Read the buffer as int32 words and
// detect the layout: for little-endian int64 arange, every odd word is the
// zero high-half (p32[1]==0); for int32 arange, p32[1]==1. Never reads past
// the smaller (int32) buffer unless int64 layout was positively detected.
// ---------------------------------------------------------------------------
__global__ void rope_kernel(float* __restrict__ Xq, float* __restrict__ Xk,
                            const int* __restrict__ pos32)
{
    const int r = blockIdx.x;            // (b*H + h)*S + s
    const int s = r & (S_LEN - 1);
    const int j = threadIdx.x;           // 0..63

    const bool is64 = (pos32[1] == 0);   // high half of element 0 under int64
    const int  p    = is64 ? pos32[2 * s] : pos32[s];

    float inv = powf(10000.0f, -(float)(2 * j) * (1.0f / 128.0f));
    float ang = (float)p * inv;
    float sn, cs;
    sincosf(ang, &sn, &cs);              // accurate range reduction (ang up to ~2047)

    float* q = Xq + r * HDIM + 2 * j;
    float x1 = q[0], x2 = q[1];
    q[0] = x1 * cs - x2 * sn;
    q[1] = x1 * sn + x2 * cs;

    float* k = Xk + r * HDIM + 2 * j;
    x1 = k[0]; x2 = k[1];
    k[0] = x1 * cs - x2 * sn;
    k[1] = x1 * sn + x2 * cs;
}

// ---------------------------------------------------------------------------
// Flash attention (fp32, causal, online softmax).
// One block = 64 query rows of one (b,h). 256 threads (16x16).
// Score tile: 4x4 per thread. O tile: 4 rows x 8 cols per thread.
// ---------------------------------------------------------------------------
#define FB_Q 64
#define FB_K 64
#define QSTR 132           // HDIM + 4 padding
#define PSTR 68            // FB_K + 4 padding

#define FLASH_SMEM_FLOATS (3 * FB_Q * QSTR + FB_Q * PSTR + 3 * FB_Q + FB_Q * 16)
#define FLASH_SMEM_BYTES  (FLASH_SMEM_FLOATS * 4)

__global__ __launch_bounds__(256)
void flash_kernel(const float* __restrict__ Q, const float* __restrict__ K,
                  const float* __restrict__ V, float* __restrict__ O)
{
    extern __shared__ float sm[];
    float* sQ    = sm;                       // 64 x 132
    float* sK    = sQ + FB_Q * QSTR;         // 64 x 132
    float* sV    = sK + FB_Q * QSTR;         // 64 x 132
    float* sP    = sV + FB_Q * QSTR;         // 64 x 68
    float* s_m   = sP + FB_Q * PSTR;         // 64
    float* s_l   = s_m + FB_Q;               // 64
    float* s_a   = s_l + FB_Q;               // 64
    float* s_red = s_a + FB_Q;               // 64 x 16

    const int tid = threadIdx.x;
    const int tx  = tid & 15;
    const int ty  = tid >> 4;

    const int qb = blockIdx.x;
    const int h  = blockIdx.y;
    const int b  = blockIdx.z;

    const float* Qb = Q + (((b * NHEADS + h) * S_LEN) + qb * FB_Q) * HDIM;
    const float* Kb = K + ((b * NHEADS + h) * S_LEN) * HDIM;
    const float* Vb = V + ((b * NHEADS + h) * S_LEN) * HDIM;

    // load Q tile (64 x 128 = 2048 float4s, 8 per thread)
#pragma unroll
    for (int i = 0; i < 8; i++) {
        int idx = tid + i * 256;
        int row = idx >> 5;
        int c4  = (idx & 31) << 2;
        *(float4*)&sQ[row * QSTR + c4] = *(const float4*)&Qb[row * HDIM + c4];
    }
    if (tid < FB_Q) { s_m[tid] = -1e30f; s_l[tid] = 0.0f; }

    float acc[4][8];
#pragma unroll
    for (int i = 0; i < 4; i++)
#pragma unroll
        for (int j = 0; j < 8; j++) acc[i][j] = 0.0f;

    const float scale = 0.088388347648318447f;  // 1/sqrt(128)

    for (int kt = 0; kt <= qb; kt++) {
        __syncthreads();   // protect smem reuse (and Q load on first iter)

        const float* Kt = Kb + kt * FB_K * HDIM;
        const float* Vt = Vb + kt * FB_K * HDIM;
#pragma unroll
        for (int i = 0; i < 8; i++) {
            int idx = tid + i * 256;
            int row = idx >> 5;
            int c4  = (idx & 31) << 2;
            *(float4*)&sK[row * QSTR + c4] = *(const float4*)&Kt[row * HDIM + c4];
            *(float4*)&sV[row * QSTR + c4] = *(const float4*)&Vt[row * HDIM + c4];
        }
        __syncthreads();

        // --- scores: 4x4 per thread over d=128 ---
        float sc[4][4];
#pragma unroll
        for (int i = 0; i < 4; i++)
#pragma unroll
            for (int j = 0; j < 4; j++) sc[i][j] = 0.0f;

#pragma unroll 8
        for (int d4 = 0; d4 < HDIM; d4 += 4) {
            float4 qv[4], kv[4];
#pragma unroll
            for (int i = 0; i < 4; i++)
                qv[i] = *(float4*)&sQ[(ty * 4 + i) * QSTR + d4];
#pragma unroll
            for (int j = 0; j < 4; j++)
                kv[j] = *(float4*)&sK[(tx * 4 + j) * QSTR + d4];
#pragma unroll
            for (int i = 0; i < 4; i++)
#pragma unroll
                for (int j = 0; j < 4; j++)
                    sc[i][j] += qv[i].x * kv[j].x + qv[i].y * kv[j].y
                              + qv[i].z * kv[j].z + qv[i].w * kv[j].w;
        }

        // scale + causal mask + per-thread row max
        float tmax[4];
#pragma unroll
        for (int i = 0; i < 4; i++) {
            tmax[i] = -1e30f;
#pragma unroll
            for (int j = 0; j < 4; j++) {
                sc[i][j] *= scale;
                if (kt == qb && (tx * 4 + j) > (ty * 4 + i)) sc[i][j] = -1e30f;
                tmax[i] = fmaxf(tmax[i], sc[i][j]);
            }
        }
#pragma unroll
        for (int i = 0; i < 4; i++) s_red[(ty * 4 + i) * 16 + tx] = tmax[i];
        __syncthreads();

        if (tid < FB_Q) {
            float mold = s_m[tid];
            float mnew = mold;
#pragma unroll
            for (int u = 0; u < 16; u++) mnew = fmaxf(mnew, s_red[tid * 16 + u]);
            s_a[tid] = __expf(mold - mnew);
            s_m[tid] = mnew;
        }
        __syncthreads();

        // P = exp(sc - m_new), partial row sums
        float psum[4];
#pragma unroll
        for (int i = 0; i < 4; i++) {
            float mnew = s_m[ty * 4 + i];
            psum[i] = 0.0f;
#pragma unroll
            for (int j = 0; j < 4; j++) {
                float p = __expf(sc[i][j] - mnew);
                sP[(ty * 4 + i) * PSTR + (tx * 4 + j)] = p;
                psum[i] += p;
            }
        }
#pragma unroll
        for (int i = 0; i < 4; i++) s_red[(ty * 4 + i) * 16 + tx] = psum[i];
        __syncthreads();

        if (tid < FB_Q) {
            float sum = 0.0f;
#pragma unroll
            for (int u = 0; u < 16; u++) sum += s_red[tid * 16 + u];
            s_l[tid] = s_l[tid] * s_a[tid] + sum;
        }

        // rescale accumulators, then O += P @ V
#pragma unroll
        for (int i = 0; i < 4; i++) {
            float a = s_a[ty * 4 + i];
#pragma unroll
            for (int j = 0; j < 8; j++) acc[i][j] *= a;
        }
#pragma unroll 4
        for (int kk = 0; kk < FB_K; kk++) {
            float pr[4];
#pragma unroll
            for (int i = 0; i < 4; i++) pr[i] = sP[(ty * 4 + i) * PSTR + kk];
            float4 v0 = *(float4*)&sV[kk * QSTR + tx * 8];
            float4 v1 = *(float4*)&sV[kk * QSTR + tx * 8 + 4];
#pragma unroll
            for (int i = 0; i < 4; i++) {
                acc[i][0] += pr[i] * v0.x;  acc[i][1] += pr[i] * v0.y;
                acc[i][2] += pr[i] * v0.z;  acc[i][3] += pr[i] * v0.w;
                acc[i][4] += pr[i] * v1.x;  acc[i][5] += pr[i] * v1.y;
                acc[i][6] += pr[i] * v1.z;  acc[i][7] += pr[i] * v1.w;
            }
        }
    }

    __syncthreads();   // make last s_l update visible to all threads

    // epilogue: normalize and write into [B][S][H*hd] layout for GEMM2
#pragma unroll
    for (int i = 0; i < 4; i++) {
        float invl = 1.0f / s_l[ty * 4 + i];
        int s_global = qb * FB_Q + ty * 4 + i;
        float* dst = O + ((b * S_LEN + s_global) * D_MODEL) + h * HDIM + tx * 8;
        *(float4*)dst = make_float4(acc[i][0] * invl, acc[i][1] * invl,
                                    acc[i][2] * invl, acc[i][3] * invl);
        *(float4*)(dst + 4) = make_float4(acc[i][4] * invl, acc[i][5] * invl,
                                          acc[i][6] * invl, acc[i][7] * invl);
    }
}

// ---------------------------------------------------------------------------
// Launch
// ---------------------------------------------------------------------------
extern "C" void kernel_launch(void* const* d_in, const int* in_sizes, int n_in,
                              void* d_out, int out_size)
{
    const float* x       = (const float*)d_in[0];
    const int*   pos32   = (const int*)d_in[1];   // int32 view; layout detected in-kernel
    const float* w_qkv   = (const float*)d_in[2];
    const float* w_o     = (const float*)d_in[3];
    float* out           = (float*)d_out;

    float *q, *k, *v, *attn;
    cudaGetSymbolAddress((void**)&q,    g_q);
    cudaGetSymbolAddress((void**)&k,    g_k);
    cudaGetSymbolAddress((void**)&v,    g_v);
    cudaGetSymbolAddress((void**)&attn, g_attn);

    // 1) QKV projection with scatter epilogue
    sgemm_kernel<1><<<dim3(QKV_N / BN, NTOK / BM), 256>>>(
        x, w_qkv, nullptr, q, k, v, QKV_N, D_MODEL);

    // 2) RoPE on Q and K (in place)
    rope_kernel<<<BATCH * NHEADS * S_LEN, 64>>>(q, k, pos32);

    // 3) causal flash attention
    cudaFuncSetAttribute(flash_kernel,
                         cudaFuncAttributeMaxDynamicSharedMemorySize,
                         FLASH_SMEM_BYTES);
    flash_kernel<<<dim3(S_LEN / FB_Q, NHEADS, BATCH), 256, FLASH_SMEM_BYTES>>>(
        q, k, v, attn);

    // 4) output projection
    sgemm_kernel<0><<<dim3(D_MODEL / BN, NTOK / BM), 256>>>(
        attn, w_o, out, nullptr, nullptr, nullptr, D_MODEL, D_MODEL);
}

// round 4
// speedup vs baseline: 1.6141x; 1.6141x over previous
#include <cuda_runtime.h>
#include <math.h>
#include <stdint.h>

// ---------------------------------------------------------------------------
// Problem constants
// ---------------------------------------------------------------------------
#define S_LEN   2048
#define D_MODEL 2048
#define NHEADS  16
#define HDIM    128
#define BATCH   2
#define NTOK    (BATCH * S_LEN)   // 4096
#define QKV_N   (3 * D_MODEL)     // 6144

// ---------------------------------------------------------------------------
// Scratch (device globals -- no allocation allowed in kernel_launch)
// ---------------------------------------------------------------------------
__device__ float g_q[BATCH * NHEADS * S_LEN * HDIM];     // 33.5 MB
__device__ float g_k[BATCH * NHEADS * S_LEN * HDIM];
__device__ float g_v[BATCH * NHEADS * S_LEN * HDIM];
__device__ float g_attn[NTOK * D_MODEL];                 // 33.5 MB

// ---------------------------------------------------------------------------
// tf32 helpers
// ---------------------------------------------------------------------------
__device__ __forceinline__ float f2tf(float x) {
    uint32_t u;
    asm("cvt.rna.tf32.f32 %0, %1;" : "=r"(u) : "f"(x));
    return __uint_as_float(u);
}
__device__ __forceinline__ float4 cvt4(float4 v) {
    v.x = f2tf(v.x); v.y = f2tf(v.y); v.z = f2tf(v.z); v.w = f2tf(v.w);
    return v;
}
__device__ __forceinline__ void mma_tf32(float c[4],
                                         uint32_t a0, uint32_t a1,
                                         uint32_t a2, uint32_t a3,
                                         uint32_t b0, uint32_t b1) {
    asm volatile(
        "mma.sync.aligned.m16n8k8.row.col.f32.tf32.tf32.f32 "
        "{%0,%1,%2,%3}, {%4,%5,%6,%7}, {%8,%9}, {%0,%1,%2,%3};"
        : "+f"(c[0]), "+f"(c[1]), "+f"(c[2]), "+f"(c[3])
        : "r"(a0), "r"(a1), "r"(a2), "r"(a3), "r"(b0), "r"(b1));
}

// ---------------------------------------------------------------------------
// tf32 tensor-core GEMM: C[M,N] = A[M,K] @ B[K,N], row-major fp32 in/out.
// Block tile 128x128x16, 256 threads (8 warps, 4x2), warp tile 32x64.
// MMA m16n8k8 tf32; inputs rounded to tf32 (cvt.rna) at the smem-store stage.
// MODE 0: plain store to C.   MODE 1: scatter into Q/K/V [B][H][S][hd].
// ---------------------------------------------------------------------------
#define TBM 128
#define TBN 128
#define TBK 16
#define ASTR 20     // As row stride (floats): banks (20g+q)%32 all distinct
#define BSTR 136    // Bs row stride (floats): banks (8q+g)%32 all distinct

template <int MODE>
__global__ __launch_bounds__(256)
void tf32_gemm(const float* __restrict__ A, const float* __restrict__ B,
               float* __restrict__ C,
               float* __restrict__ Cq, float* __restrict__ Ck,
               float* __restrict__ Cv,
               int N, int K)
{
    __shared__ float As[2][TBM][ASTR];   // 20,480 B
    __shared__ float Bs[2][TBK][BSTR];   // 17,408 B

    const int tid  = threadIdx.x;
    const int lane = tid & 31;
    const int wid  = tid >> 5;
    const int wm   = wid >> 1;          // 0..3  (M direction)
    const int wn   = wid & 1;           // 0..1  (N direction)
    const int g    = lane >> 2;         // groupID 0..7
    const int q    = lane & 3;          // threadID_in_group 0..3

    const int brow = blockIdx.y;
    const int bcol = blockIdx.x;

    const float* Ab = A + brow * TBM * K;
    const float* Bb = B + bcol * TBN;

    // global->smem load mapping
    const int ar = tid >> 2;            // A rows ar, ar+64
    const int ac = (tid & 3) << 2;      // A col4 0,4,8,12
    const int br = tid >> 5;            // B rows br, br+8
    const int bc = (tid & 31) << 2;     // B col4 0..124

    float acc[2][8][4];
#pragma unroll
    for (int i = 0; i < 2; i++)
#pragma unroll
        for (int j = 0; j < 8; j++)
#pragma unroll
            for (int r = 0; r < 4; r++) acc[i][j][r] = 0.0f;

    // preload tile 0 (convert to tf32 at store)
    {
        float4 a0v = cvt4(*(const float4*)(Ab + ar * K + ac));
        float4 a1v = cvt4(*(const float4*)(Ab + (ar + 64) * K + ac));
        float4 b0v = cvt4(*(const float4*)(Bb + br * N + bc));
        float4 b1v = cvt4(*(const float4*)(Bb + (br + 8) * N + bc));
        *(float4*)&As[0][ar][ac]      = a0v;
        *(float4*)&As[0][ar + 64][ac] = a1v;
        *(float4*)&Bs[0][br][bc]      = b0v;
        *(float4*)&Bs[0][br + 8][bc]  = b1v;
    }
    __syncthreads();

    const int T = K / TBK;
    float4 pa0, pa1, pb0, pb1;

    for (int t = 0; t < T; t++) {
        const int buf = t & 1;
        if (t + 1 < T) {
            const float* Ap = Ab + (t + 1) * TBK;
            const float* Bp = Bb + (t + 1) * TBK * N;
            pa0 = *(const float4*)(Ap + ar * K + ac);
            pa1 = *(const float4*)(Ap + (ar + 64) * K + ac);
            pb0 = *(const float4*)(Bp + br * N + bc);
            pb1 = *(const float4*)(Bp + (br + 8) * N + bc);
        }

#pragma unroll
        for (int k8 = 0; k8 < TBK; k8 += 8) {
            uint32_t af[2][4];
#pragma unroll
            for (int tm = 0; tm < 2; tm++) {
                const int rA = wm * 32 + tm * 16 + g;
                af[tm][0] = __float_as_uint(As[buf][rA]    [k8 + q]);
                af[tm][1] = __float_as_uint(As[buf][rA + 8][k8 + q]);
                af[tm][2] = __float_as_uint(As[buf][rA]    [k8 + q + 4]);
                af[tm][3] = __float_as_uint(As[buf][rA + 8][k8 + q + 4]);
            }
            uint32_t bf[8][2];
#pragma unroll
            for (int tn = 0; tn < 8; tn++) {
                const int nB = wn * 64 + tn * 8 + g;
                bf[tn][0] = __float_as_uint(Bs[buf][k8 + q][nB]);
                bf[tn][1] = __float_as_uint(Bs[buf][k8 + q + 4][nB]);
            }
#pragma unroll
            for (int tm = 0; tm < 2; tm++)
#pragma unroll
                for (int tn = 0; tn < 8; tn++)
                    mma_tf32(acc[tm][tn],
                             af[tm][0], af[tm][1], af[tm][2], af[tm][3],
                             bf[tn][0], bf[tn][1]);
        }

        if (t + 1 < T) {
            const int nb = 1 - buf;
            *(float4*)&As[nb][ar][ac]      = cvt4(pa0);
            *(float4*)&As[nb][ar + 64][ac] = cvt4(pa1);
            *(float4*)&Bs[nb][br][bc]      = cvt4(pb0);
            *(float4*)&Bs[nb][br + 8][bc]  = cvt4(pb1);
            __syncthreads();
        }
    }

    // ---------------- epilogue ----------------
    if (MODE == 0) {
#pragma unroll
        for (int tm = 0; tm < 2; tm++) {
            const int row = brow * TBM + wm * 32 + tm * 16 + g;
#pragma unroll
            for (int tn = 0; tn < 8; tn++) {
                const int col = bcol * TBN + wn * 64 + tn * 8 + 2 * q;
                *(float2*)&C[row * N + col] =
                    make_float2(acc[tm][tn][0], acc[tm][tn][1]);
                *(float2*)&C[(row + 8) * N + col] =
                    make_float2(acc[tm][tn][2], acc[tm][tn][3]);
            }
        }
    } else {
        // whole 128-col tile belongs to one (which, head)
        const int col0  = bcol * TBN;
        const int which = col0 >> 11;          // 0=q,1=k,2=v
        const int h     = (col0 & 2047) >> 7;  // head
        float* dst = (which == 0) ? Cq : ((which == 1) ? Ck : Cv);
#pragma unroll
        for (int tm = 0; tm < 2; tm++) {
            const int rowtok = brow * TBM + wm * 32 + tm * 16 + g;
            const int bb = rowtok >> 11;
            const int ss = rowtok & 2047;
            float* base0 = dst + (((bb * NHEADS + h) * S_LEN) + ss) * HDIM;
            const int rt8 = rowtok + 8;
            const int bb8 = rt8 >> 11;
            const int ss8 = rt8 & 2047;
            float* base8 = dst + (((bb8 * NHEADS + h) * S_LEN) + ss8) * HDIM;
#pragma unroll
            for (int tn = 0; tn < 8; tn++) {
                const int colh = wn * 64 + tn * 8 + 2 * q;
                *(float2*)&base0[colh] = make_float2(acc[tm][tn][0], acc[tm][tn][1]);
                *(float2*)&base8[colh] = make_float2(acc[tm][tn][2], acc[tm][tn][3]);
            }
        }
    }
}

// ---------------------------------------------------------------------------
// RoPE (interleaved pairs), in place on Q and K.
// token_positions may be int64 or (JAX x64-disabled) int32; detect layout.
// ---------------------------------------------------------------------------
__global__ void rope_kernel(float* __restrict__ Xq, float* __restrict__ Xk,
                            const int* __restrict__ pos32)
{
    const int r = blockIdx.x;            // (b*H + h)*S + s
    const int s = r & (S_LEN - 1);
    const int j = threadIdx.x;           // 0..63

    const bool is64 = (pos32[1] == 0);   // high half of element 0 under int64
    const int  p    = is64 ? pos32[2 * s] : pos32[s];

    float inv = powf(10000.0f, -(float)(2 * j) * (1.0f / 128.0f));
    float ang = (float)p * inv;
    float sn, cs;
    sincosf(ang, &sn, &cs);

    float* qp = Xq + r * HDIM + 2 * j;
    float x1 = qp[0], x2 = qp[1];
    qp[0] = x1 * cs - x2 * sn;
    qp[1] = x1 * sn + x2 * cs;

    float* kp = Xk + r * HDIM + 2 * j;
    x1 = kp[0]; x2 = kp[1];
    kp[0] = x1 * cs - x2 * sn;
    kp[1] = x1 * sn + x2 * cs;
}

// ---------------------------------------------------------------------------
// Flash attention (fp32, causal, online softmax).  (unchanged from R3 pass)
// ---------------------------------------------------------------------------
#define FB_Q 64
#define FB_K 64
#define QSTR 132           // HDIM + 4 padding
#define PSTR 68            // FB_K + 4 padding

#define FLASH_SMEM_FLOATS (3 * FB_Q * QSTR + FB_Q * PSTR + 3 * FB_Q + FB_Q * 16)
#define FLASH_SMEM_BYTES  (FLASH_SMEM_FLOATS * 4)

__global__ __launch_bounds__(256)
void flash_kernel(const float* __restrict__ Q, const float* __restrict__ K,
                  const float* __restrict__ V, float* __restrict__ O)
{
    extern __shared__ float sm[];
    float* sQ    = sm;                       // 64 x 132
    float* sK    = sQ + FB_Q * QSTR;         // 64 x 132
    float* sV    = sK + FB_Q * QSTR;         // 64 x 132
    float* sP    = sV + FB_Q * QSTR;         // 64 x 68
    float* s_m   = sP + FB_Q * PSTR;         // 64
    float* s_l   = s_m + FB_Q;               // 64
    float* s_a   = s_l + FB_Q;               // 64
    float* s_red = s_a + FB_Q;               // 64 x 16

    const int tid = threadIdx.x;
    const int tx  = tid & 15;
    const int ty  = tid >> 4;

    const int qb = blockIdx.x;
    const int h  = blockIdx.y;
    const int b  = blockIdx.z;

    const float* Qb = Q + (((b * NHEADS + h) * S_LEN) + qb * FB_Q) * HDIM;
    const float* Kb = K + ((b * NHEADS + h) * S_LEN) * HDIM;
    const float* Vb = V + ((b * NHEADS + h) * S_LEN) * HDIM;

#pragma unroll
    for (int i = 0; i < 8; i++) {
        int idx = tid + i * 256;
        int row = idx >> 5;
        int c4  = (idx & 31) << 2;
        *(float4*)&sQ[row * QSTR + c4] = *(const float4*)&Qb[row * HDIM + c4];
    }
    if (tid < FB_Q) { s_m[tid] = -1e30f; s_l[tid] = 0.0f; }

    float acc[4][8];
#pragma unroll
    for (int i = 0; i < 4; i++)
#pragma unroll
        for (int j = 0; j < 8; j++) acc[i][j] = 0.0f;

    const float scale = 0.088388347648318447f;  // 1/sqrt(128)

    for (int kt = 0; kt <= qb; kt++) {
        __syncthreads();

        const float* Kt = Kb + kt * FB_K * HDIM;
        const float* Vt = Vb + kt * FB_K * HDIM;
#pragma unroll
        for (int i = 0; i < 8; i++) {
            int idx = tid + i * 256;
            int row = idx >> 5;
            int c4  = (idx & 31) << 2;
            *(float4*)&sK[row * QSTR + c4] = *(const float4*)&Kt[row * HDIM + c4];
            *(float4*)&sV[row * QSTR + c4] = *(const float4*)&Vt[row * HDIM + c4];
        }
        __syncthreads();

        float sc[4][4];
#pragma unroll
        for (int i = 0; i < 4; i++)
#pragma unroll
            for (int j = 0; j < 4; j++) sc[i][j] = 0.0f;

#pragma unroll 8
        for (int d4 = 0; d4 < HDIM; d4 += 4) {
            float4 qv[4], kv[4];
#pragma unroll
            for (int i = 0; i < 4; i++)
                qv[i] = *(float4*)&sQ[(ty * 4 + i) * QSTR + d4];
#pragma unroll
            for (int j = 0; j < 4; j++)
                kv[j] = *(float4*)&sK[(tx * 4 + j) * QSTR + d4];
#pragma unroll
            for (int i = 0; i < 4; i++)
#pragma unroll
                for (int j = 0; j < 4; j++)
                    sc[i][j] += qv[i].x * kv[j].x + qv[i].y * kv[j].y
                              + qv[i].z * kv[j].z + qv[i].w * kv[j].w;
        }

        float tmax[4];
#pragma unroll
        for (int i = 0; i < 4; i++) {
            tmax[i] = -1e30f;
#pragma unroll
            for (int j = 0; j < 4; j++) {
                sc[i][j] *= scale;
                if (kt == qb && (tx * 4 + j) > (ty * 4 + i)) sc[i][j] = -1e30f;
                tmax[i] = fmaxf(tmax[i], sc[i][j]);
            }
        }
#pragma unroll
        for (int i = 0; i < 4; i++) s_red[(ty * 4 + i) * 16 + tx] = tmax[i];
        __syncthreads();

        if (tid < FB_Q) {
            float mold = s_m[tid];
            float mnew = mold;
#pragma unroll
            for (int u = 0; u < 16; u++) mnew = fmaxf(mnew, s_red[tid * 16 + u]);
            s_a[tid] = __expf(mold - mnew);
            s_m[tid] = mnew;
        }
        __syncthreads();

        float psum[4];
#pragma unroll
        for (int i = 0; i < 4; i++) {
            float mnew = s_m[ty * 4 + i];
            psum[i] = 0.0f;
#pragma unroll
            for (int j = 0; j < 4; j++) {
                float p = __expf(sc[i][j] - mnew);
                sP[(ty * 4 + i) * PSTR + (tx * 4 + j)] = p;
                psum[i] += p;
            }
        }
#pragma unroll
        for (int i = 0; i < 4; i++) s_red[(ty * 4 + i) * 16 + tx] = psum[i];
        __syncthreads();

        if (tid < FB_Q) {
            float sum = 0.0f;
#pragma unroll
            for (int u = 0; u < 16; u++) sum += s_red[tid * 16 + u];
            s_l[tid] = s_l[tid] * s_a[tid] + sum;
        }

#pragma unroll
        for (int i = 0; i < 4; i++) {
            float a = s_a[ty * 4 + i];
#pragma unroll
            for (int j = 0; j < 8; j++) acc[i][j] *= a;
        }
#pragma unroll 4
        for (int kk = 0; kk < FB_K; kk++) {
            float pr[4];
#pragma unroll
            for (int i = 0; i < 4; i++) pr[i] = sP[(ty * 4 + i) * PSTR + kk];
            float4 v0 = *(float4*)&sV[kk * QSTR + tx * 8];
            float4 v1 = *(float4*)&sV[kk * QSTR + tx * 8 + 4];
#pragma unroll
            for (int i = 0; i < 4; i++) {
                acc[i][0] += pr[i] * v0.x;  acc[i][1] += pr[i] * v0.y;
                acc[i][2] += pr[i] * v0.z;  acc[i][3] += pr[i] * v0.w;
                acc[i][4] += pr[i] * v1.x;  acc[i][5] += pr[i] * v1.y;
                acc[i][6] += pr[i] * v1.z;  acc[i][7] += pr[i] * v1.w;
            }
        }
    }

    __syncthreads();

#pragma unroll
    for (int i = 0; i < 4; i++) {
        float invl = 1.0f / s_l[ty * 4 + i];
        int s_global = qb * FB_Q + ty * 4 + i;
        float* dst = O + ((b * S_LEN + s_global) * D_MODEL) + h * HDIM + tx * 8;
        *(float4*)dst = make_float4(acc[i][0] * invl, acc[i][1] * invl,
                                    acc[i][2] * invl, acc[i][3] * invl);
        *(float4*)(dst + 4) = make_float4(acc[i][4] * invl, acc[i][5] * invl,
                                          acc[i][6] * invl, acc[i][7] * invl);
    }
}

// ---------------------------------------------------------------------------
// Launch
// ---------------------------------------------------------------------------
extern "C" void kernel_launch(void* const* d_in, const int* in_sizes, int n_in,
                              void* d_out, int out_size)
{
    const float* x     = (const float*)d_in[0];
    const int*   pos32 = (const int*)d_in[1];   // int32 view; layout detected in-kernel
    const float* w_qkv = (const float*)d_in[2];
    const float* w_o   = (const float*)d_in[3];
    float* out         = (float*)d_out;

    float *q, *k, *v, *attn;
    cudaGetSymbolAddress((void**)&q,    g_q);
    cudaGetSymbolAddress((void**)&k,    g_k);
    cudaGetSymbolAddress((void**)&v,    g_v);
    cudaGetSymbolAddress((void**)&attn, g_attn);

    // 1) QKV projection (tf32 tensor cores) with scatter epilogue
    tf32_gemm<1><<<dim3(QKV_N / TBN, NTOK / TBM), 256>>>(
        x, w_qkv, nullptr, q, k, v, QKV_N, D_MODEL);

    // 2) RoPE on Q and K (in place)
    rope_kernel<<<BATCH * NHEADS * S_LEN, 64>>>(q, k, pos32);

    // 3) causal flash attention (fp32)
    cudaFuncSetAttribute(flash_kernel,
                         cudaFuncAttributeMaxDynamicSharedMemorySize,
                         FLASH_SMEM_BYTES);
    flash_kernel<<<dim3(S_LEN / FB_Q, NHEADS, BATCH), 256, FLASH_SMEM_BYTES>>>(
        q, k, v, attn);

    // 4) output projection (tf32 tensor cores)
    tf32_gemm<0><<<dim3(D_MODEL / TBN, NTOK / TBM), 256>>>(
        attn, w_o, out, nullptr, nullptr, nullptr, D_MODEL, D_MODEL);
}

// round 5
// speedup vs baseline: 3.4815x; 2.1569x over previous
#include <cuda_runtime.h>
#include <math.h>
#include <stdint.h>

// ---------------------------------------------------------------------------
// Problem constants
// ---------------------------------------------------------------------------
#define S_LEN   2048
#define D_MODEL 2048
#define NHEADS  16
#define HDIM    128
#define BATCH   2
#define NTOK    (BATCH * S_LEN)   // 4096
#define QKV_N   (3 * D_MODEL)     // 6144

// ---------------------------------------------------------------------------
// Scratch (device globals -- no allocation allowed in kernel_launch)
// ---------------------------------------------------------------------------
__device__ float g_q[BATCH * NHEADS * S_LEN * HDIM];     // 33.5 MB
__device__ float g_k[BATCH * NHEADS * S_LEN * HDIM];
__device__ float g_v[BATCH * NHEADS * S_LEN * HDIM];
__device__ float g_attn[NTOK * D_MODEL];                 // 33.5 MB

// ---------------------------------------------------------------------------
// tf32 helpers
// ---------------------------------------------------------------------------
__device__ __forceinline__ float f2tf(float x) {
    uint32_t u;
    asm("cvt.rna.tf32.f32 %0, %1;" : "=r"(u) : "f"(x));
    return __uint_as_float(u);
}
__device__ __forceinline__ float4 cvt4(float4 v) {
    v.x = f2tf(v.x); v.y = f2tf(v.y); v.z = f2tf(v.z); v.w = f2tf(v.w);
    return v;
}
__device__ __forceinline__ void mma_tf32(float c[4],
                                         uint32_t a0, uint32_t a1,
                                         uint32_t a2, uint32_t a3,
                                         uint32_t b0, uint32_t b1) {
    asm volatile(
        "mma.sync.aligned.m16n8k8.row.col.f32.tf32.tf32.f32 "
        "{%0,%1,%2,%3}, {%4,%5,%6,%7}, {%8,%9}, {%0,%1,%2,%3};"
        : "+f"(c[0]), "+f"(c[1]), "+f"(c[2]), "+f"(c[3])
        : "r"(a0), "r"(a1), "r"(a2), "r"(a3), "r"(b0), "r"(b1));
}
__device__ __forceinline__ void cp16(uint32_t dst, const void* src) {
    asm volatile("cp.async.cg.shared.global [%0], [%1], 16;"
                 :: "r"(dst), "l"(src));
}

// ---------------------------------------------------------------------------
// tf32 tensor-core GEMM (unchanged from round 4 -- passing).
// ---------------------------------------------------------------------------
#define TBM 128
#define TBN 128
#define TBK 16
#define ASTR 20
#define BSTR 136

template <int MODE>
__global__ __launch_bounds__(256)
void tf32_gemm(const float* __restrict__ A, const float* __restrict__ B,
               float* __restrict__ C,
               float* __restrict__ Cq, float* __restrict__ Ck,
               float* __restrict__ Cv,
               int N, int K)
{
    __shared__ float As[2][TBM][ASTR];
    __shared__ float Bs[2][TBK][BSTR];

    const int tid  = threadIdx.x;
    const int lane = tid & 31;
    const int wid  = tid >> 5;
    const int wm   = wid >> 1;
    const int wn   = wid & 1;
    const int g    = lane >> 2;
    const int q    = lane & 3;

    const int brow = blockIdx.y;
    const int bcol = blockIdx.x;

    const float* Ab = A + brow * TBM * K;
    const float* Bb = B + bcol * TBN;

    const int ar = tid >> 2;
    const int ac = (tid & 3) << 2;
    const int br = tid >> 5;
    const int bc = (tid & 31) << 2;

    float acc[2][8][4];
#pragma unroll
    for (int i = 0; i < 2; i++)
#pragma unroll
        for (int j = 0; j < 8; j++)
#pragma unroll
            for (int r = 0; r < 4; r++) acc[i][j][r] = 0.0f;

    {
        float4 a0v = cvt4(*(const float4*)(Ab + ar * K + ac));
        float4 a1v = cvt4(*(const float4*)(Ab + (ar + 64) * K + ac));
        float4 b0v = cvt4(*(const float4*)(Bb + br * N + bc));
        float4 b1v = cvt4(*(const float4*)(Bb + (br + 8) * N + bc));
        *(float4*)&As[0][ar][ac]      = a0v;
        *(float4*)&As[0][ar + 64][ac] = a1v;
        *(float4*)&Bs[0][br][bc]      = b0v;
        *(float4*)&Bs[0][br + 8][bc]  = b1v;
    }
    __syncthreads();

    const int T = K / TBK;
    float4 pa0, pa1, pb0, pb1;

    for (int t = 0; t < T; t++) {
        const int buf = t & 1;
        if (t + 1 < T) {
            const float* Ap = Ab + (t + 1) * TBK;
            const float* Bp = Bb + (t + 1) * TBK * N;
            pa0 = *(const float4*)(Ap + ar * K + ac);
            pa1 = *(const float4*)(Ap + (ar + 64) * K + ac);
            pb0 = *(const float4*)(Bp + br * N + bc);
            pb1 = *(const float4*)(Bp + (br + 8) * N + bc);
        }

#pragma unroll
        for (int k8 = 0; k8 < TBK; k8 += 8) {
            uint32_t af[2][4];
#pragma unroll
            for (int tm = 0; tm < 2; tm++) {
                const int rA = wm * 32 + tm * 16 + g;
                af[tm][0] = __float_as_uint(As[buf][rA]    [k8 + q]);
                af[tm][1] = __float_as_uint(As[buf][rA + 8][k8 + q]);
                af[tm][2] = __float_as_uint(As[buf][rA]    [k8 + q + 4]);
                af[tm][3] = __float_as_uint(As[buf][rA + 8][k8 + q + 4]);
            }
            uint32_t bf[8][2];
#pragma unroll
            for (int tn = 0; tn < 8; tn++) {
                const int nB = wn * 64 + tn * 8 + g;
                bf[tn][0] = __float_as_uint(Bs[buf][k8 + q][nB]);
                bf[tn][1] = __float_as_uint(Bs[buf][k8 + q + 4][nB]);
            }
#pragma unroll
            for (int tm = 0; tm < 2; tm++)
#pragma unroll
                for (int tn = 0; tn < 8; tn++)
                    mma_tf32(acc[tm][tn],
                             af[tm][0], af[tm][1], af[tm][2], af[tm][3],
                             bf[tn][0], bf[tn][1]);
        }

        if (t + 1 < T) {
            const int nb = 1 - buf;
            *(float4*)&As[nb][ar][ac]      = cvt4(pa0);
            *(float4*)&As[nb][ar + 64][ac] = cvt4(pa1);
            *(float4*)&Bs[nb][br][bc]      = cvt4(pb0);
            *(float4*)&Bs[nb][br + 8][bc]  = cvt4(pb1);
            __syncthreads();
        }
    }

    if (MODE == 0) {
#pragma unroll
        for (int tm = 0; tm < 2; tm++) {
            const int row = brow * TBM + wm * 32 + tm * 16 + g;
#pragma unroll
            for (int tn = 0; tn < 8; tn++) {
                const int col = bcol * TBN + wn * 64 + tn * 8 + 2 * q;
                *(float2*)&C[row * N + col] =
                    make_float2(acc[tm][tn][0], acc[tm][tn][1]);
                *(float2*)&C[(row + 8) * N + col] =
                    make_float2(acc[tm][tn][2], acc[tm][tn][3]);
            }
        }
    } else {
        const int col0  = bcol * TBN;
        const int which = col0 >> 11;
        const int h     = (col0 & 2047) >> 7;
        float* dst = (which == 0) ? Cq : ((which == 1) ? Ck : Cv);
#pragma unroll
        for (int tm = 0; tm < 2; tm++) {
            const int rowtok = brow * TBM + wm * 32 + tm * 16 + g;
            const int bb = rowtok >> 11;
            const int ss = rowtok & 2047;
            float* base0 = dst + (((bb * NHEADS + h) * S_LEN) + ss) * HDIM;
            const int rt8 = rowtok + 8;
            const int bb8 = rt8 >> 11;
            const int ss8 = rt8 & 2047;
            float* base8 = dst + (((bb8 * NHEADS + h) * S_LEN) + ss8) * HDIM;
#pragma unroll
            for (int tn = 0; tn < 8; tn++) {
                const int colh = wn * 64 + tn * 8 + 2 * q;
                *(float2*)&base0[colh] = make_float2(acc[tm][tn][0], acc[tm][tn][1]);
                *(float2*)&base8[colh] = make_float2(acc[tm][tn][2], acc[tm][tn][3]);
            }
        }
    }
}

// ---------------------------------------------------------------------------
// RoPE (interleaved pairs), in place on Q and K; also rounds Q,K,V to tf32
// (cvt.rna) so the flash tensor-core kernel sees unbiased operands (HMMA
// truncates raw f32 -> systematic logit shrink we must avoid).
// ---------------------------------------------------------------------------
__global__ void rope_kernel(float* __restrict__ Xq, float* __restrict__ Xk,
                            float* __restrict__ Xv,
                            const int* __restrict__ pos32)
{
    const int r = blockIdx.x;            // (b*H + h)*S + s
    const int s = r & (S_LEN - 1);
    const int j = threadIdx.x;           // 0..63

    const bool is64 = (pos32[1] == 0);   // high half of element 0 under int64
    const int  p    = is64 ? pos32[2 * s] : pos32[s];

    float inv = powf(10000.0f, -(float)(2 * j) * (1.0f / 128.0f));
    float ang = (float)p * inv;
    float sn, cs;
    sincosf(ang, &sn, &cs);

    float* qp = Xq + r * HDIM + 2 * j;
    float x1 = qp[0], x2 = qp[1];
    qp[0] = f2tf(x1 * cs - x2 * sn);
    qp[1] = f2tf(x1 * sn + x2 * cs);

    float* kp = Xk + r * HDIM + 2 * j;
    x1 = kp[0]; x2 = kp[1];
    kp[0] = f2tf(x1 * cs - x2 * sn);
    kp[1] = f2tf(x1 * sn + x2 * cs);

    float* vp = Xv + r * HDIM;
    vp[j]      = f2tf(vp[j]);
    vp[j + 64] = f2tf(vp[j + 64]);
}

// ---------------------------------------------------------------------------
// Flash attention, tf32 tensor cores, causal, online softmax in registers.
// Block: 128 q-rows, 8 warps x 16 rows. K/V tiles of 64 keys, cp.async
// double-buffered. QK: m16n8k8 M=16,N=64,K=128. PV: M=16,N=128,K=64.
// Row stats (max/sum) stay within a quad (2 shfl.xor), no smem reductions.
// ---------------------------------------------------------------------------
#define FQ   128
#define FKT  64
#define QS   132   // stride % 32 == 4 -> conflict-free A-frag loads
#define KS2  132   // same pattern for K (B-frag rows vary with g)
#define VS2  136   // stride % 32 == 8 -> conflict-free V B-frag loads
#define SMF_K0 (FQ * QS)
#define SMF_V0 (FQ * QS + 2 * FKT * KS2)
#define FLASH2_SMEM_BYTES ((FQ * QS + 2 * FKT * KS2 + 2 * FKT * VS2) * 4)  // 204800

__global__ __launch_bounds__(256, 1)
void flash_tc(const float* __restrict__ Q, const float* __restrict__ K,
              const float* __restrict__ V, float* __restrict__ O)
{
    extern __shared__ float sm[];
    const int tid  = threadIdx.x;
    const int lane = tid & 31;
    const int w    = tid >> 5;           // warp 0..7 -> q-rows [16w, 16w+16)
    const int g    = lane >> 2;          // 0..7
    const int q    = lane & 3;           // 0..3

    const int qb = blockIdx.x;
    const int h  = blockIdx.y;
    const int b  = blockIdx.z;

    const float* Qg = Q + (((size_t)(b * NHEADS + h)) * S_LEN + (size_t)qb * FQ) * HDIM;
    const float* Kg = K + ((size_t)(b * NHEADS + h)) * S_LEN * HDIM;
    const float* Vg = V + ((size_t)(b * NHEADS + h)) * S_LEN * HDIM;

    const uint32_t sb = (uint32_t)__cvta_generic_to_shared(sm);

    // Q tile: 128x128 f32 = 4096 16B chunks, 16 per thread
#pragma unroll
    for (int i = 0; i < 16; i++) {
        int id  = i * 256 + tid;
        int row = id >> 5, c = (id & 31) << 2;
        cp16(sb + (uint32_t)(row * QS + c) * 4u, Qg + row * HDIM + c);
    }
    // K/V tile 0 into buffer 0 (same commit group as Q)
#pragma unroll
    for (int i = 0; i < 8; i++) {
        int id  = i * 256 + tid;
        int row = id >> 5, c = (id & 31) << 2;
        cp16(sb + (uint32_t)(SMF_K0 + row * KS2 + c) * 4u, Kg + row * HDIM + c);
        cp16(sb + (uint32_t)(SMF_V0 + row * VS2 + c) * 4u, Vg + row * HDIM + c);
    }
    asm volatile("cp.async.commit_group;");

    float m0 = -1e30f, m1 = -1e30f, l0 = 0.0f, l1 = 0.0f;
    float acc[16][4];
#pragma unroll
    for (int nf = 0; nf < 16; nf++)
#pragma unroll
        for (int c = 0; c < 4; c++) acc[nf][c] = 0.0f;

    const float SC = 0.088388347648318447f;   // 1/sqrt(128)
    const int ntiles = 2 * qb + 2;
    const int r0 = qb * FQ + w * 16 + g;      // first-half global q-row
    const int r1 = r0 + 8;                    // second-half global q-row

    for (int kt = 0; kt < ntiles; kt++) {
        asm volatile("cp.async.wait_group 0;");
        __syncthreads();

        // prefetch next K/V tile into the other buffer (overlaps compute)
        if (kt + 1 < ntiles) {
            const int nbuf = (kt + 1) & 1;
            const float* Ks = Kg + (size_t)(kt + 1) * FKT * HDIM;
            const float* Vs = Vg + (size_t)(kt + 1) * FKT * HDIM;
#pragma unroll
            for (int i = 0; i < 8; i++) {
                int id  = i * 256 + tid;
                int row = id >> 5, c = (id & 31) << 2;
                cp16(sb + (uint32_t)(SMF_K0 + nbuf * FKT * KS2 + row * KS2 + c) * 4u,
                     Ks + row * HDIM + c);
                cp16(sb + (uint32_t)(SMF_V0 + nbuf * FKT * VS2 + row * VS2 + c) * 4u,
                     Vs + row * HDIM + c);
            }
            asm volatile("cp.async.commit_group;");
        }

        // warp-uniform skip of fully masked diagonal tiles
        if (kt * FKT <= qb * FQ + w * 16 + 15) {
            const float* sq = sm;
            const float* sk = sm + SMF_K0 + (kt & 1) * FKT * KS2;
            const float* sv = sm + SMF_V0 + (kt & 1) * FKT * VS2;

            // ---- S = Q K^T (per warp: 16 x 64 over d=128) ----
            float sc[8][4];
#pragma unroll
            for (int nf = 0; nf < 8; nf++)
#pragma unroll
                for (int c = 0; c < 4; c++) sc[nf][c] = 0.0f;

#pragma unroll
            for (int k8 = 0; k8 < 16; k8++) {
                const int kc = k8 * 8;
                uint32_t a0 = __float_as_uint(sq[(w * 16 + g)     * QS + kc + q]);
                uint32_t a1 = __float_as_uint(sq[(w * 16 + g + 8) * QS + kc + q]);
                uint32_t a2 = __float_as_uint(sq[(w * 16 + g)     * QS + kc + q + 4]);
                uint32_t a3 = __float_as_uint(sq[(w * 16 + g + 8) * QS + kc + q + 4]);
#pragma unroll
                for (int nf = 0; nf < 8; nf++) {
                    uint32_t b0 = __float_as_uint(sk[(nf * 8 + g) * KS2 + kc + q]);
                    uint32_t b1 = __float_as_uint(sk[(nf * 8 + g) * KS2 + kc + q + 4]);
                    mma_tf32(sc[nf], a0, a1, a2, a3, b0, b1);
                }
            }

            // ---- causal mask (only tiles touching the diagonal) ----
            if (kt * FKT + FKT - 1 > r0) {
#pragma unroll
                for (int nf = 0; nf < 8; nf++) {
#pragma unroll
                    for (int cb = 0; cb < 2; cb++) {
                        int kcol = kt * FKT + nf * 8 + 2 * q + cb;
                        if (kcol > r0) sc[nf][cb]     = -1e30f;
                        if (kcol > r1) sc[nf][2 + cb] = -1e30f;
                    }
                }
            }

            // ---- online softmax (quad-local) ----
            float mx0 = -1e30f, mx1 = -1e30f;
#pragma unroll
            for (int nf = 0; nf < 8; nf++) {
                mx0 = fmaxf(mx0, fmaxf(sc[nf][0], sc[nf][1]));
                mx1 = fmaxf(mx1, fmaxf(sc[nf][2], sc[nf][3]));
            }
            mx0 = fmaxf(mx0, __shfl_xor_sync(0xffffffffu, mx0, 1));
            mx0 = fmaxf(mx0, __shfl_xor_sync(0xffffffffu, mx0, 2));
            mx1 = fmaxf(mx1, __shfl_xor_sync(0xffffffffu, mx1, 1));
            mx1 = fmaxf(mx1, __shfl_xor_sync(0xffffffffu, mx1, 2));

            float mn0 = fmaxf(m0, mx0), mn1 = fmaxf(m1, mx1);
            float al0 = __expf(SC * (m0 - mn0));
            float al1 = __expf(SC * (m1 - mn1));
            m0 = mn0; m1 = mn1;

            float rs0 = 0.0f, rs1 = 0.0f;
#pragma unroll
            for (int nf = 0; nf < 8; nf++) {
                float p0 = f2tf(__expf(SC * (sc[nf][0] - m0)));
                float p1 = f2tf(__expf(SC * (sc[nf][1] - m0)));
                float p2 = f2tf(__expf(SC * (sc[nf][2] - m1)));
                float p3 = f2tf(__expf(SC * (sc[nf][3] - m1)));
                sc[nf][0] = p0; sc[nf][1] = p1; sc[nf][2] = p2; sc[nf][3] = p3;
                rs0 += p0 + p1;
                rs1 += p2 + p3;
            }
            rs0 += __shfl_xor_sync(0xffffffffu, rs0, 1);
            rs0 += __shfl_xor_sync(0xffffffffu, rs0, 2);
            rs1 += __shfl_xor_sync(0xffffffffu, rs1, 1);
            rs1 += __shfl_xor_sync(0xffffffffu, rs1, 2);
            l0 = l0 * al0 + rs0;
            l1 = l1 * al1 + rs1;

#pragma unroll
            for (int nf = 0; nf < 16; nf++) {
                acc[nf][0] *= al0; acc[nf][1] *= al0;
                acc[nf][2] *= al1; acc[nf][3] *= al1;
            }

            // ---- O += P V  (P C-layout -> A-layout via quad shuffles) ----
#pragma unroll
            for (int j = 0; j < 8; j++) {
                const int s0 = (q >> 1);
                const int s1 = 2 + (q >> 1);
                float v00 = __shfl_sync(0xffffffffu, sc[j][0], s0, 4);
                float v01 = __shfl_sync(0xffffffffu, sc[j][1], s0, 4);
                float v10 = __shfl_sync(0xffffffffu, sc[j][2], s0, 4);
                float v11 = __shfl_sync(0xffffffffu, sc[j][3], s0, 4);
                uint32_t a0 = __float_as_uint((q & 1) ? v01 : v00);
                uint32_t a1 = __float_as_uint((q & 1) ? v11 : v10);
                v00 = __shfl_sync(0xffffffffu, sc[j][0], s1, 4);
                v01 = __shfl_sync(0xffffffffu, sc[j][1], s1, 4);
                v10 = __shfl_sync(0xffffffffu, sc[j][2], s1, 4);
                v11 = __shfl_sync(0xffffffffu, sc[j][3], s1, 4);
                uint32_t a2 = __float_as_uint((q & 1) ? v01 : v00);
                uint32_t a3 = __float_as_uint((q & 1) ? v11 : v10);
#pragma unroll
                for (int nf = 0; nf < 16; nf++) {
                    uint32_t b0 = __float_as_uint(sv[(j * 8 + q)     * VS2 + nf * 8 + g]);
                    uint32_t b1 = __float_as_uint(sv[(j * 8 + q + 4) * VS2 + nf * 8 + g]);
                    mma_tf32(acc[nf], a0, a1, a2, a3, b0, b1);
                }
            }
        }
    }

    // ---- epilogue: normalize, store to [b][s][h*128+d] ----
    const float inv0 = 1.0f / l0;
    const float inv1 = 1.0f / l1;
    float* o0 = O + ((size_t)(b * S_LEN + r0)) * D_MODEL + h * HDIM;
    float* o1 = o0 + (size_t)8 * D_MODEL;
#pragma unroll
    for (int nf = 0; nf < 16; nf++) {
        const int col = nf * 8 + 2 * q;
        *(float2*)&o0[col] = make_float2(acc[nf][0] * inv0, acc[nf][1] * inv0);
        *(float2*)&o1[col] = make_float2(acc[nf][2] * inv1, acc[nf][3] * inv1);
    }
}

// ---------------------------------------------------------------------------
// Launch
// ---------------------------------------------------------------------------
extern "C" void kernel_launch(void* const* d_in, const int* in_sizes, int n_in,
                              void* d_out, int out_size)
{
    const float* x     = (const float*)d_in[0];
    const int*   pos32 = (const int*)d_in[1];   // int32 view; layout detected in-kernel
    const float* w_qkv = (const float*)d_in[2];
    const float* w_o   = (const float*)d_in[3];
    float* out         = (float*)d_out;

    float *q, *k, *v, *attn;
    cudaGetSymbolAddress((void**)&q,    g_q);
    cudaGetSymbolAddress((void**)&k,    g_k);
    cudaGetSymbolAddress((void**)&v,    g_v);
    cudaGetSymbolAddress((void**)&attn, g_attn);

    // 1) QKV projection (tf32 tensor cores) with scatter epilogue
    tf32_gemm<1><<<dim3(QKV_N / TBN, NTOK / TBM), 256>>>(
        x, w_qkv, nullptr, q, k, v, QKV_N, D_MODEL);

    // 2) RoPE on Q and K (in place) + tf32 rounding of Q,K,V
    rope_kernel<<<BATCH * NHEADS * S_LEN, 64>>>(q, k, v, pos32);

    // 3) causal flash attention (tf32 tensor cores)
    cudaFuncSetAttribute(flash_tc,
                         cudaFuncAttributeMaxDynamicSharedMemorySize,
                         FLASH2_SMEM_BYTES);
    flash_tc<<<dim3(S_LEN / FQ, NHEADS, BATCH), 256, FLASH2_SMEM_BYTES>>>(
        q, k, v, attn);

    // 4) output projection (tf32 tensor cores)
    tf32_gemm<0><<<dim3(D_MODEL / TBN, NTOK / TBM), 256>>>(
        attn, w_o, out, nullptr, nullptr, nullptr, D_MODEL, D_MODEL);
}

// round 7
// speedup vs baseline: 3.8546x; 1.1072x over previous
#include <cuda_runtime.h>
#include <math.h>
#include <stdint.h>

// ---------------------------------------------------------------------------
// Problem constants
// ---------------------------------------------------------------------------
#define S_LEN   2048
#define D_MODEL 2048
#define NHEADS  16
#define HDIM    128
#define BATCH   2
#define NTOK    (BATCH * S_LEN)   // 4096
#define QKV_N   (3 * D_MODEL)     // 6144

// ---------------------------------------------------------------------------
// Scratch (device globals -- no allocation allowed in kernel_launch)
// ---------------------------------------------------------------------------
__device__ float g_q[BATCH * NHEADS * S_LEN * HDIM];
__device__ float g_k[BATCH * NHEADS * S_LEN * HDIM];
__device__ float g_v[BATCH * NHEADS * S_LEN * HDIM];
__device__ float g_attn[NTOK * D_MODEL];
__device__ float g_xtf[NTOK * D_MODEL];          // tf32-rounded x
__device__ float g_wqkv[D_MODEL * QKV_N];        // tf32-rounded w_qkv
__device__ float g_wo[D_MODEL * D_MODEL];        // tf32-rounded w_o

// ---------------------------------------------------------------------------
// tf32 helpers
// ---------------------------------------------------------------------------
__device__ __forceinline__ float f2tf(float x) {
    uint32_t u;
    asm("cvt.rna.tf32.f32 %0, %1;" : "=r"(u) : "f"(x));
    return __uint_as_float(u);
}
__device__ __forceinline__ float4 cvt4(float4 v) {
    v.x = f2tf(v.x); v.y = f2tf(v.y); v.z = f2tf(v.z); v.w = f2tf(v.w);
    return v;
}
__device__ __forceinline__ void mma_tf32(float c[4],
                                         uint32_t a0, uint32_t a1,
                                         uint32_t a2, uint32_t a3,
                                         uint32_t b0, uint32_t b1) {
    asm volatile(
        "mma.sync.aligned.m16n8k8.row.col.f32.tf32.tf32.f32 "
        "{%0,%1,%2,%3}, {%4,%5,%6,%7}, {%8,%9}, {%0,%1,%2,%3};"
        : "+f"(c[0]), "+f"(c[1]), "+f"(c[2]), "+f"(c[3])
        : "r"(a0), "r"(a1), "r"(a2), "r"(a3), "r"(b0), "r"(b1));
}
__device__ __forceinline__ void cp16(uint32_t dst, const void* src) {
    asm volatile("cp.async.cg.shared.global [%0], [%1], 16;"
                 :: "r"(dst), "l"(src));
}

// ---------------------------------------------------------------------------
// Prep: elementwise tf32 (rna) rounding into scratch. float4 grid-stride-free.
// ---------------------------------------------------------------------------
__global__ void tf32_round_kernel(const float4* __restrict__ in,
                                  float4* __restrict__ out, int n4)
{
    int i = blockIdx.x * blockDim.x + threadIdx.x;
    if (i < n4) out[i] = cvt4(in[i]);
}

// ---------------------------------------------------------------------------
// tf32 HMMA GEMM, cp.async 4-stage pipeline.
// C[M,N] = A[M,K] @ B[K,N]; A,B already tf32-rounded in gmem.
// Block tile 128x128x16, 256 threads (8 warps 4x2), warp tile 32x64.
// MODE 0: plain store.  MODE 1: scatter into Q/K/V [B][H][S][hd].
// ---------------------------------------------------------------------------
#define TBM 128
#define TBN 128
#define TBK 16
#define ASTR 20          // As row stride (floats); 80B rows -> 16B aligned
#define BSTR 136         // Bs row stride (floats); 544B rows -> 16B aligned
#define STG  4
#define AS_FLOATS (TBM * ASTR)               // 2560
#define BS_FLOATS (TBK * BSTR)               // 2176
#define STAGE_FLOATS (AS_FLOATS + BS_FLOATS) // 4736
#define GEMM_SMEM (STG * STAGE_FLOATS * 4)   // 75776 B

template <int MODE>
__global__ __launch_bounds__(256, 2)
void tf32_gemm_pipe(const float* __restrict__ A, const float* __restrict__ B,
                    float* __restrict__ C,
                    float* __restrict__ Cq, float* __restrict__ Ck,
                    float* __restrict__ Cv,
                    int N, int K)
{
    extern __shared__ float smem[];
    const uint32_t sb = (uint32_t)__cvta_generic_to_shared(smem);

    const int tid  = threadIdx.x;
    const int lane = tid & 31;
    const int wid  = tid >> 5;
    const int wm   = wid >> 1;          // 0..3  (M)
    const int wn   = wid & 1;           // 0..1  (N)
    const int g    = lane >> 2;         // 0..7
    const int q    = lane & 3;          // 0..3

    const int brow = blockIdx.y;
    const int bcol = blockIdx.x;
    const float* Ab = A + (size_t)brow * TBM * K;
    const float* Bb = B + bcol * TBN;

    // cp.async mapping: 512 A-chunks + 512 B-chunks per tile, 2+2 per thread
    const int ac0 = tid,        ac1 = tid + 256;       // A chunk ids
    const int ar0 = ac0 >> 2,   af0 = (ac0 & 3) << 2;  // row, col(floats)
    const int ar1 = ac1 >> 2,   af1 = (ac1 & 3) << 2;
    const int br0 = tid >> 5,   bf0 = (tid & 31) << 2; // B rows 0..7
    const int br1 = br0 + 8,    bf1 = bf0;             // B rows 8..15

    const int T = K / TBK;

    // prefetch first STG-1 tiles
#pragma unroll
    for (int p = 0; p < STG - 1; p++) {
        const uint32_t sa  = sb + (uint32_t)(p * STAGE_FLOATS) * 4u;
        const uint32_t sbb = sa + (uint32_t)AS_FLOATS * 4u;
        const int kt = p * TBK;
        cp16(sa  + (uint32_t)(ar0 * ASTR + af0) * 4u, Ab + (size_t)ar0 * K + kt + af0);
        cp16(sa  + (uint32_t)(ar1 * ASTR + af1) * 4u, Ab + (size_t)ar1 * K + kt + af1);
        cp16(sbb + (uint32_t)(br0 * BSTR + bf0) * 4u, Bb + (size_t)(kt + br0) * N + bf0);
        cp16(sbb + (uint32_t)(br1 * BSTR + bf1) * 4u, Bb + (size_t)(kt + br1) * N + bf1);
        asm volatile("cp.async.commit_group;");
    }

    float acc[2][8][4];
#pragma unroll
    for (int i = 0; i < 2; i++)
#pragma unroll
        for (int j = 0; j < 8; j++)
#pragma unroll
            for (int r = 0; r < 4; r++) acc[i][j][r] = 0.0f;

    for (int t = 0; t < T; t++) {
        asm volatile("cp.async.wait_group %0;" :: "n"(STG - 2));
        __syncthreads();

        // issue loads for tile t+STG-1 into the stage freed at t-1
        {
            const int tn = t + STG - 1;
            if (tn < T) {
                const int st = tn & (STG - 1);
                const uint32_t sa  = sb + (uint32_t)(st * STAGE_FLOATS) * 4u;
                const uint32_t sbb = sa + (uint32_t)AS_FLOATS * 4u;
                const int kt = tn * TBK;
                cp16(sa  + (uint32_t)(ar0 * ASTR + af0) * 4u, Ab + (size_t)ar0 * K + kt + af0);
                cp16(sa  + (uint32_t)(ar1 * ASTR + af1) * 4u, Ab + (size_t)ar1 * K + kt + af1);
                cp16(sbb + (uint32_t)(br0 * BSTR + bf0) * 4u, Bb + (size_t)(kt + br0) * N + bf0);
                cp16(sbb + (uint32_t)(br1 * BSTR + bf1) * 4u, Bb + (size_t)(kt + br1) * N + bf1);
            }
            asm volatile("cp.async.commit_group;");
        }

        // compute tile t from stage t%4
        const float* as_p = smem + (t & (STG - 1)) * STAGE_FLOATS;
        const float* bs_p = as_p + AS_FLOATS;
#pragma unroll
        for (int k8 = 0; k8 < TBK; k8 += 8) {
            uint32_t af[2][4];
#pragma unroll
            for (int tm = 0; tm < 2; tm++) {
                const int rA = wm * 32 + tm * 16 + g;
                af[tm][0] = __float_as_uint(as_p[rA * ASTR + k8 + q]);
                af[tm][1] = __float_as_uint(as_p[(rA + 8) * ASTR + k8 + q]);
                af[tm][2] = __float_as_uint(as_p[rA * ASTR + k8 + q + 4]);
                af[tm][3] = __float_as_uint(as_p[(rA + 8) * ASTR + k8 + q + 4]);
            }
            uint32_t bf[8][2];
#pragma unroll
            for (int tn2 = 0; tn2 < 8; tn2++) {
                const int nB = wn * 64 + tn2 * 8 + g;
                bf[tn2][0] = __float_as_uint(bs_p[(k8 + q) * BSTR + nB]);
                bf[tn2][1] = __float_as_uint(bs_p[(k8 + q + 4) * BSTR + nB]);
            }
#pragma unroll
            for (int tm = 0; tm < 2; tm++)
#pragma unroll
                for (int tn2 = 0; tn2 < 8; tn2++)
                    mma_tf32(acc[tm][tn2],
                             af[tm][0], af[tm][1], af[tm][2], af[tm][3],
                             bf[tn2][0], bf[tn2][1]);
        }
    }

    // ---------------- epilogue ----------------
    if (MODE == 0) {
#pragma unroll
        for (int tm = 0; tm < 2; tm++) {
            const int row = brow * TBM + wm * 32 + tm * 16 + g;
#pragma unroll
            for (int tn2 = 0; tn2 < 8; tn2++) {
                const int col = bcol * TBN + wn * 64 + tn2 * 8 + 2 * q;
                *(float2*)&C[(size_t)row * N + col] =
                    make_float2(acc[tm][tn2][0], acc[tm][tn2][1]);
                *(float2*)&C[(size_t)(row + 8) * N + col] =
                    make_float2(acc[tm][tn2][2], acc[tm][tn2][3]);
            }
        }
    } else {
        const int col0  = bcol * TBN;
        const int which = col0 >> 11;          // 0=q,1=k,2=v
        const int h     = (col0 & 2047) >> 7;  // head
        float* dst = (which == 0) ? Cq : ((which == 1) ? Ck : Cv);
#pragma unroll
        for (int tm = 0; tm < 2; tm++) {
            const int rowtok = brow * TBM + wm * 32 + tm * 16 + g;
            const int bb = rowtok >> 11;
            const int ss = rowtok & 2047;
            float* base0 = dst + (((size_t)(bb * NHEADS + h) * S_LEN) + ss) * HDIM;
            const int rt8 = rowtok + 8;
            const int bb8 = rt8 >> 11;
            const int ss8 = rt8 & 2047;
            float* base8 = dst + (((size_t)(bb8 * NHEADS + h) * S_LEN) + ss8) * HDIM;
#pragma unroll
            for (int tn2 = 0; tn2 < 8; tn2++) {
                const int colh = wn * 64 + tn2 * 8 + 2 * q;
                *(float2*)&base0[colh] = make_float2(acc[tm][tn2][0], acc[tm][tn2][1]);
                *(float2*)&base8[colh] = make_float2(acc[tm][tn2][2], acc[tm][tn2][3]);
            }
        }
    }
}

// ---------------------------------------------------------------------------
// RoPE (interleaved pairs), in place on Q and K; rounds Q,K,V to tf32 (rna).
// token_positions may be int64 or (JAX x64-disabled) int32; detect layout.
// ---------------------------------------------------------------------------
__global__ void rope_kernel(float* __restrict__ Xq, float* __restrict__ Xk,
                            float* __restrict__ Xv,
                            const int* __restrict__ pos32)
{
    const int r = blockIdx.x;
    const int s = r & (S_LEN - 1);
    const int j = threadIdx.x;

    const bool is64 = (pos32[1] == 0);
    const int  p    = is64 ? pos32[2 * s] : pos32[s];

    float inv = powf(10000.0f, -(float)(2 * j) * (1.0f / 128.0f));
    float ang = (float)p * inv;
    float sn, cs;
    sincosf(ang, &sn, &cs);

    float* qp = Xq + r * HDIM + 2 * j;
    float x1 = qp[0], x2 = qp[1];
    qp[0] = f2tf(x1 * cs - x2 * sn);
    qp[1] = f2tf(x1 * sn + x2 * cs);

    float* kp = Xk + r * HDIM + 2 * j;
    x1 = kp[0]; x2 = kp[1];
    kp[0] = f2tf(x1 * cs - x2 * sn);
    kp[1] = f2tf(x1 * sn + x2 * cs);

    float* vp = Xv + r * HDIM;
    vp[j]      = f2tf(vp[j]);
    vp[j + 64] = f2tf(vp[j + 64]);
}

// ---------------------------------------------------------------------------
// Flash attention, tf32 HMMA (round-5 passing version; epilogue now rounds
// g_attn to tf32 so GEMM2 inputs are pre-rounded).
// ---------------------------------------------------------------------------
#define FQ   128
#define FKT  64
#define QS   132
#define KS2  132
#define VS2  136
#define SMF_K0 (FQ * QS)
#define SMF_V0 (FQ * QS + 2 * FKT * KS2)
#define FLASH2_SMEM_BYTES ((FQ * QS + 2 * FKT * KS2 + 2 * FKT * VS2) * 4)

__global__ __launch_bounds__(256, 1)
void flash_tc(const float* __restrict__ Q, const float* __restrict__ K,
              const float* __restrict__ V, float* __restrict__ O)
{
    extern __shared__ float sm[];
    const int tid  = threadIdx.x;
    const int lane = tid & 31;
    const int w    = tid >> 5;
    const int g    = lane >> 2;
    const int q    = lane & 3;

    const int qb = blockIdx.x;
    const int h  = blockIdx.y;
    const int b  = blockIdx.z;

    const float* Qg = Q + (((size_t)(b * NHEADS + h)) * S_LEN + (size_t)qb * FQ) * HDIM;
    const float* Kg = K + ((size_t)(b * NHEADS + h)) * S_LEN * HDIM;
    const float* Vg = V + ((size_t)(b * NHEADS + h)) * S_LEN * HDIM;

    const uint32_t sb = (uint32_t)__cvta_generic_to_shared(sm);

#pragma unroll
    for (int i = 0; i < 16; i++) {
        int id  = i * 256 + tid;
        int row = id >> 5, c = (id & 31) << 2;
        cp16(sb + (uint32_t)(row * QS + c) * 4u, Qg + row * HDIM + c);
    }
#pragma unroll
    for (int i = 0; i < 8; i++) {
        int id  = i * 256 + tid;
        int row = id >> 5, c = (id & 31) << 2;
        cp16(sb + (uint32_t)(SMF_K0 + row * KS2 + c) * 4u, Kg + row * HDIM + c);
        cp16(sb + (uint32_t)(SMF_V0 + row * VS2 + c) * 4u, Vg + row * HDIM + c);
    }
    asm volatile("cp.async.commit_group;");

    float m0 = -1e30f, m1 = -1e30f, l0 = 0.0f, l1 = 0.0f;
    float acc[16][4];
#pragma unroll
    for (int nf = 0; nf < 16; nf++)
#pragma unroll
        for (int c = 0; c < 4; c++) acc[nf][c] = 0.0f;

    const float SC = 0.088388347648318447f;
    const int ntiles = 2 * qb + 2;
    const int r0 = qb * FQ + w * 16 + g;
    const int r1 = r0 + 8;

    for (int kt = 0; kt < ntiles; kt++) {
        asm volatile("cp.async.wait_group 0;");
        __syncthreads();

        if (kt + 1 < ntiles) {
            const int nbuf = (kt + 1) & 1;
            const float* Ks = Kg + (size_t)(kt + 1) * FKT * HDIM;
            const float* Vs = Vg + (size_t)(kt + 1) * FKT * HDIM;
#pragma unroll
            for (int i = 0; i < 8; i++) {
                int id  = i * 256 + tid;
                int row = id >> 5, c = (id & 31) << 2;
                cp16(sb + (uint32_t)(SMF_K0 + nbuf * FKT * KS2 + row * KS2 + c) * 4u,
                     Ks + row * HDIM + c);
                cp16(sb + (uint32_t)(SMF_V0 + nbuf * FKT * VS2 + row * VS2 + c) * 4u,
                     Vs + row * HDIM + c);
            }
            asm volatile("cp.async.commit_group;");
        }

        if (kt * FKT <= qb * FQ + w * 16 + 15) {
            const float* sq = sm;
            const float* sk = sm + SMF_K0 + (kt & 1) * FKT * KS2;
            const float* sv = sm + SMF_V0 + (kt & 1) * FKT * VS2;

            float sc[8][4];
#pragma unroll
            for (int nf = 0; nf < 8; nf++)
#pragma unroll
                for (int c = 0; c < 4; c++) sc[nf][c] = 0.0f;

#pragma unroll
            for (int k8 = 0; k8 < 16; k8++) {
                const int kc = k8 * 8;
                uint32_t a0 = __float_as_uint(sq[(w * 16 + g)     * QS + kc + q]);
                uint32_t a1 = __float_as_uint(sq[(w * 16 + g + 8) * QS + kc + q]);
                uint32_t a2 = __float_as_uint(sq[(w * 16 + g)     * QS + kc + q + 4]);
                uint32_t a3 = __float_as_uint(sq[(w * 16 + g + 8) * QS + kc + q + 4]);
#pragma unroll
                for (int nf = 0; nf < 8; nf++) {
                    uint32_t b0 = __float_as_uint(sk[(nf * 8 + g) * KS2 + kc + q]);
                    uint32_t b1 = __float_as_uint(sk[(nf * 8 + g) * KS2 + kc + q + 4]);
                    mma_tf32(sc[nf], a0, a1, a2, a3, b0, b1);
                }
            }

            if (kt * FKT + FKT - 1 > r0) {
#pragma unroll
                for (int nf = 0; nf < 8; nf++) {
#pragma unroll
                    for (int cb = 0; cb < 2; cb++) {
                        int kcol = kt * FKT + nf * 8 + 2 * q + cb;
                        if (kcol > r0) sc[nf][cb]     = -1e30f;
                        if (kcol > r1) sc[nf][2 + cb] = -1e30f;
                    }
                }
            }

            float mx0 = -1e30f, mx1 = -1e30f;
#pragma unroll
            for (int nf = 0; nf < 8; nf++) {
                mx0 = fmaxf(mx0, fmaxf(sc[nf][0], sc[nf][1]));
                mx1 = fmaxf(mx1, fmaxf(sc[nf][2], sc[nf][3]));
            }
            mx0 = fmaxf(mx0, __shfl_xor_sync(0xffffffffu, mx0, 1));
            mx0 = fmaxf(mx0, __shfl_xor_sync(0xffffffffu, mx0, 2));
            mx1 = fmaxf(mx1, __shfl_xor_sync(0xffffffffu, mx1, 1));
            mx1 = fmaxf(mx1, __shfl_xor_sync(0xffffffffu, mx1, 2));

            float mn0 = fmaxf(m0, mx0), mn1 = fmaxf(m1, mx1);
            float al0 = __expf(SC * (m0 - mn0));
            float al1 = __expf(SC * (m1 - mn1));
            m0 = mn0; m1 = mn1;

            float rs0 = 0.0f, rs1 = 0.0f;
#pragma unroll
            for (int nf = 0; nf < 8; nf++) {
                float p0 = f2tf(__expf(SC * (sc[nf][0] - m0)));
                float p1 = f2tf(__expf(SC * (sc[nf][1] - m0)));
                float p2 = f2tf(__expf(SC * (sc[nf][2] - m1)));
                float p3 = f2tf(__expf(SC * (sc[nf][3] - m1)));
                sc[nf][0] = p0; sc[nf][1] = p1; sc[nf][2] = p2; sc[nf][3] = p3;
                rs0 += p0 + p1;
                rs1 += p2 + p3;
            }
            rs0 += __shfl_xor_sync(0xffffffffu, rs0, 1);
            rs0 += __shfl_xor_sync(0xffffffffu, rs0, 2);
            rs1 += __shfl_xor_sync(0xffffffffu, rs1, 1);
            rs1 += __shfl_xor_sync(0xffffffffu, rs1, 2);
            l0 = l0 * al0 + rs0;
            l1 = l1 * al1 + rs1;

#pragma unroll
            for (int nf = 0; nf < 16; nf++) {
                acc[nf][0] *= al0; acc[nf][1] *= al0;
                acc[nf][2] *= al1; acc[nf][3] *= al1;
            }

#pragma unroll
            for (int j = 0; j < 8; j++) {
                const int s0 = (q >> 1);
                const int s1 = 2 + (q >> 1);
                float v00 = __shfl_sync(0xffffffffu, sc[j][0], s0, 4);
                float v01 = __shfl_sync(0xffffffffu, sc[j][1], s0, 4);
                float v10 = __shfl_sync(0xffffffffu, sc[j][2], s0, 4);
                float v11 = __shfl_sync(0xffffffffu, sc[j][3], s0, 4);
                uint32_t a0 = __float_as_uint((q & 1) ? v01 : v00);
                uint32_t a1 = __float_as_uint((q & 1) ? v11 : v10);
                v00 = __shfl_sync(0xffffffffu, sc[j][0], s1, 4);
                v01 = __shfl_sync(0xffffffffu, sc[j][1], s1, 4);
                v10 = __shfl_sync(0xffffffffu, sc[j][2], s1, 4);
                v11 = __shfl_sync(0xffffffffu, sc[j][3], s1, 4);
                uint32_t a2 = __float_as_uint((q & 1) ? v01 : v00);
                uint32_t a3 = __float_as_uint((q & 1) ? v11 : v10);
#pragma unroll
                for (int nf = 0; nf < 16; nf++) {
                    uint32_t b0 = __float_as_uint(sv[(j * 8 + q)     * VS2 + nf * 8 + g]);
                    uint32_t b1 = __float_as_uint(sv[(j * 8 + q + 4) * VS2 + nf * 8 + g]);
                    mma_tf32(acc[nf], a0, a1, a2, a3, b0, b1);
                }
            }
        }
    }

    // epilogue: normalize + tf32-round (GEMM2 inputs pre-rounded)
    const float inv0 = 1.0f / l0;
    const float inv1 = 1.0f / l1;
    float* o0 = O + ((size_t)(b * S_LEN + r0)) * D_MODEL + h * HDIM;
    float* o1 = o0 + (size_t)8 * D_MODEL;
#pragma unroll
    for (int nf = 0; nf < 16; nf++) {
        const int col = nf * 8 + 2 * q;
        *(float2*)&o0[col] = make_float2(f2tf(acc[nf][0] * inv0), f2tf(acc[nf][1] * inv0));
        *(float2*)&o1[col] = make_float2(f2tf(acc[nf][2] * inv1), f2tf(acc[nf][3] * inv1));
    }
}

// ---------------------------------------------------------------------------
// Launch
// ---------------------------------------------------------------------------
extern "C" void kernel_launch(void* const* d_in, const int* in_sizes, int n_in,
                              void* d_out, int out_size)
{
    const float* x     = (const float*)d_in[0];
    const int*   pos32 = (const int*)d_in[1];
    const float* w_qkv = (const float*)d_in[2];
    const float* w_o   = (const float*)d_in[3];
    float* out         = (float*)d_out;

    float *q, *k, *v, *attn, *xtf, *wqkv, *wo;
    cudaGetSymbolAddress((void**)&q,    g_q);
    cudaGetSymbolAddress((void**)&k,    g_k);
    cudaGetSymbolAddress((void**)&v,    g_v);
    cudaGetSymbolAddress((void**)&attn, g_attn);
    cudaGetSymbolAddress((void**)&xtf,  g_xtf);
    cudaGetSymbolAddress((void**)&wqkv, g_wqkv);
    cudaGetSymbolAddress((void**)&wo,   g_wo);

    cudaFuncSetAttribute(tf32_gemm_pipe<1>,
                         cudaFuncAttributeMaxDynamicSharedMemorySize, GEMM_SMEM);
    cudaFuncSetAttribute(tf32_gemm_pipe<0>,
                         cudaFuncAttributeMaxDynamicSharedMemorySize, GEMM_SMEM);
    cudaFuncSetAttribute(flash_tc,
                         cudaFuncAttributeMaxDynamicSharedMemorySize,
                         FLASH2_SMEM_BYTES);

    // 0) pre-round inputs to tf32 (rna) -- unbiased, idempotent
    {
        const int nx = NTOK * D_MODEL / 4;
        const int nq = D_MODEL * QKV_N / 4;
        const int nw = D_MODEL * D_MODEL / 4;
        tf32_round_kernel<<<nx / 256, 256>>>((const float4*)x,     (float4*)xtf,  nx);
        tf32_round_kernel<<<nq / 256, 256>>>((const float4*)w_qkv, (float4*)wqkv, nq);
        tf32_round_kernel<<<nw / 256, 256>>>((const float4*)w_o,   (float4*)wo,   nw);
    }

    // 1) QKV projection (pipelined tf32 HMMA) with scatter epilogue
    tf32_gemm_pipe<1><<<dim3(QKV_N / TBN, NTOK / TBM), 256, GEMM_SMEM>>>(
        xtf, wqkv, nullptr, q, k, v, QKV_N, D_MODEL);

    // 2) RoPE on Q and K (in place) + tf32 rounding of Q,K,V
    rope_kernel<<<BATCH * NHEADS * S_LEN, 64>>>(q, k, v, pos32);

    // 3) causal flash attention (tf32 HMMA)
    flash_tc<<<dim3(S_LEN / FQ, NHEADS, BATCH), 256, FLASH2_SMEM_BYTES>>>(
        q, k, v, attn);

    // 4) output projection (pipelined tf32 HMMA)
    tf32_gemm_pipe<0><<<dim3(D_MODEL / TBN, NTOK / TBM), 256, GEMM_SMEM>>>(
        attn, wo, out, nullptr, nullptr, nullptr, D_MODEL, D_MODEL);
}

// round 8
// speedup vs baseline: 4.1420x; 1.0745x over previous
#include <cuda_runtime.h>
#include <math.h>
#include <stdint.h>

// ---------------------------------------------------------------------------
// Problem constants
// ---------------------------------------------------------------------------
#define S_LEN   2048
#define D_MODEL 2048
#define NHEADS  16
#define HDIM    128
#define BATCH   2
#define NTOK    (BATCH * S_LEN)   // 4096
#define QKV_N   (3 * D_MODEL)     // 6144

// ---------------------------------------------------------------------------
// Scratch (device globals -- no allocation allowed in kernel_launch)
// ---------------------------------------------------------------------------
__device__ float g_q[BATCH * NHEADS * S_LEN * HDIM];
__device__ float g_k[BATCH * NHEADS * S_LEN * HDIM];
__device__ float g_v[BATCH * NHEADS * S_LEN * HDIM];
__device__ float g_attn[NTOK * D_MODEL];
__device__ float g_xtf[NTOK * D_MODEL];          // tf32-rounded x
__device__ float g_wqkv[D_MODEL * QKV_N];        // tf32-rounded w_qkv
__device__ float g_wo[D_MODEL * D_MODEL];        // tf32-rounded w_o

// ---------------------------------------------------------------------------
// tf32 helpers
// ---------------------------------------------------------------------------
__device__ __forceinline__ float f2tf(float x) {
    uint32_t u;
    asm("cvt.rna.tf32.f32 %0, %1;" : "=r"(u) : "f"(x));
    return __uint_as_float(u);
}
__device__ __forceinline__ float4 cvt4(float4 v) {
    v.x = f2tf(v.x); v.y = f2tf(v.y); v.z = f2tf(v.z); v.w = f2tf(v.w);
    return v;
}
__device__ __forceinline__ void mma_tf32(float c[4],
                                         uint32_t a0, uint32_t a1,
                                         uint32_t a2, uint32_t a3,
                                         uint32_t b0, uint32_t b1) {
    asm volatile(
        "mma.sync.aligned.m16n8k8.row.col.f32.tf32.tf32.f32 "
        "{%0,%1,%2,%3}, {%4,%5,%6,%7}, {%8,%9}, {%0,%1,%2,%3};"
        : "+f"(c[0]), "+f"(c[1]), "+f"(c[2]), "+f"(c[3])
        : "r"(a0), "r"(a1), "r"(a2), "r"(a3), "r"(b0), "r"(b1));
}
__device__ __forceinline__ void cp16(uint32_t dst, const void* src) {
    asm volatile("cp.async.cg.shared.global [%0], [%1], 16;"
                 :: "r"(dst), "l"(src));
}

// ---------------------------------------------------------------------------
// Prep: elementwise tf32 (rna) rounding into scratch.
// ---------------------------------------------------------------------------
__global__ void tf32_round_kernel(const float4* __restrict__ in,
                                  float4* __restrict__ out, int n4)
{
    int i = blockIdx.x * blockDim.x + threadIdx.x;
    if (i < n4) out[i] = cvt4(in[i]);
}

// ---------------------------------------------------------------------------
// tf32 HMMA GEMM, cp.async 3-stage pipeline, BK=32 (one barrier per 64 HMMA).
// C[M,N] = A[M,K] @ B[K,N]; A,B already tf32-rounded in gmem.
// Block tile 128x128x32, 256 threads (8 warps 4x2), warp tile 32x64.
// MODE 0: plain store.  MODE 1: scatter into Q/K/V [B][H][S][hd].
// ---------------------------------------------------------------------------
#define TBM 128
#define TBN 128
#define TBK 32
#define ASTR 36          // A row stride: banks (4g+q) distinct for frag loads
#define BSTR 136         // B row stride: banks (8q+8tn+g) distinct
#define STG  3
#define AS_FLOATS (TBM * ASTR)               // 4608
#define BS_FLOATS (TBK * BSTR)               // 4352
#define STAGE_FLOATS (AS_FLOATS + BS_FLOATS) // 8960
#define GEMM_SMEM (STG * STAGE_FLOATS * 4)   // 107520 B

template <int MODE>
__global__ __launch_bounds__(256, 2)
void tf32_gemm_pipe(const float* __restrict__ A, const float* __restrict__ B,
                    float* __restrict__ C,
                    float* __restrict__ Cq, float* __restrict__ Ck,
                    float* __restrict__ Cv,
                    int N, int K)
{
    extern __shared__ float smem[];
    const uint32_t sb = (uint32_t)__cvta_generic_to_shared(smem);

    const int tid  = threadIdx.x;
    const int lane = tid & 31;
    const int wid  = tid >> 5;
    const int wm   = wid >> 1;          // 0..3  (M)
    const int wn   = wid & 1;           // 0..1  (N)
    const int g    = lane >> 2;         // 0..7
    const int q    = lane & 3;          // 0..3

    const int brow = blockIdx.y;
    const int bcol = blockIdx.x;
    const float* Ab = A + (size_t)brow * TBM * K;
    const float* Bb = B + bcol * TBN;

    // cp.async mapping: per tile 1024 A-chunks + 1024 B-chunks, 4+4 per thread
    // A chunk c: row = c>>3, colf = (c&7)*4.  B chunk c: row = c>>5, colf=(c&31)*4
    const int T = K / TBK;

    // prefetch first STG-1 tiles
#pragma unroll
    for (int p = 0; p < STG - 1; p++) {
        const uint32_t sa  = sb + (uint32_t)(p * STAGE_FLOATS) * 4u;
        const uint32_t sbb = sa + (uint32_t)AS_FLOATS * 4u;
        const int kt = p * TBK;
#pragma unroll
        for (int i = 0; i < 4; i++) {
            const int c  = tid + i * 256;
            const int arr = c >> 3, acf = (c & 7) << 2;
            const int brr = c >> 5, bcf = (c & 31) << 2;
            cp16(sa  + (uint32_t)(arr * ASTR + acf) * 4u, Ab + (size_t)arr * K + kt + acf);
            cp16(sbb + (uint32_t)(brr * BSTR + bcf) * 4u, Bb + (size_t)(kt + brr) * N + bcf);
        }
        asm volatile("cp.async.commit_group;");
    }

    float acc[2][8][4];
#pragma unroll
    for (int i = 0; i < 2; i++)
#pragma unroll
        for (int j = 0; j < 8; j++)
#pragma unroll
            for (int r = 0; r < 4; r++) acc[i][j][r] = 0.0f;

    int stage = 0;
    for (int t = 0; t < T; t++) {
        asm volatile("cp.async.wait_group %0;" :: "n"(STG - 2));
        __syncthreads();

        // issue loads for tile t+STG-1 into the stage freed at t-1 (safe after sync)
        {
            const int tn = t + STG - 1;
            if (tn < T) {
                int st = stage + (STG - 1);
                if (st >= STG) st -= STG;
                const uint32_t sa  = sb + (uint32_t)(st * STAGE_FLOATS) * 4u;
                const uint32_t sbb = sa + (uint32_t)AS_FLOATS * 4u;
                const int kt = tn * TBK;
#pragma unroll
                for (int i = 0; i < 4; i++) {
                    const int c  = tid + i * 256;
                    const int arr = c >> 3, acf = (c & 7) << 2;
                    const int brr = c >> 5, bcf = (c & 31) << 2;
                    cp16(sa  + (uint32_t)(arr * ASTR + acf) * 4u,
                         Ab + (size_t)arr * K + kt + acf);
                    cp16(sbb + (uint32_t)(brr * BSTR + bcf) * 4u,
                         Bb + (size_t)(kt + brr) * N + bcf);
                }
            }
            asm volatile("cp.async.commit_group;");
        }

        // compute tile t: 4 unrolled k8 steps (96 LDS + 64 HMMA, no barriers)
        const float* as_p = smem + stage * STAGE_FLOATS;
        const float* bs_p = as_p + AS_FLOATS;
#pragma unroll
        for (int k8 = 0; k8 < TBK; k8 += 8) {
            uint32_t af[2][4];
#pragma unroll
            for (int tm = 0; tm < 2; tm++) {
                const int rA = wm * 32 + tm * 16 + g;
                af[tm][0] = __float_as_uint(as_p[rA * ASTR + k8 + q]);
                af[tm][1] = __float_as_uint(as_p[(rA + 8) * ASTR + k8 + q]);
                af[tm][2] = __float_as_uint(as_p[rA * ASTR + k8 + q + 4]);
                af[tm][3] = __float_as_uint(as_p[(rA + 8) * ASTR + k8 + q + 4]);
            }
            uint32_t bf[8][2];
#pragma unroll
            for (int tn2 = 0; tn2 < 8; tn2++) {
                const int nB = wn * 64 + tn2 * 8 + g;
                bf[tn2][0] = __float_as_uint(bs_p[(k8 + q) * BSTR + nB]);
                bf[tn2][1] = __float_as_uint(bs_p[(k8 + q + 4) * BSTR + nB]);
            }
#pragma unroll
            for (int tm = 0; tm < 2; tm++)
#pragma unroll
                for (int tn2 = 0; tn2 < 8; tn2++)
                    mma_tf32(acc[tm][tn2],
                             af[tm][0], af[tm][1], af[tm][2], af[tm][3],
                             bf[tn2][0], bf[tn2][1]);
        }
        if (++stage == STG) stage = 0;
    }

    // ---------------- epilogue ----------------
    if (MODE == 0) {
#pragma unroll
        for (int tm = 0; tm < 2; tm++) {
            const int row = brow * TBM + wm * 32 + tm * 16 + g;
#pragma unroll
            for (int tn2 = 0; tn2 < 8; tn2++) {
                const int col = bcol * TBN + wn * 64 + tn2 * 8 + 2 * q;
                *(float2*)&C[(size_t)row * N + col] =
                    make_float2(acc[tm][tn2][0], acc[tm][tn2][1]);
                *(float2*)&C[(size_t)(row + 8) * N + col] =
                    make_float2(acc[tm][tn2][2], acc[tm][tn2][3]);
            }
        }
    } else {
        const int col0  = bcol * TBN;
        const int which = col0 >> 11;          // 0=q,1=k,2=v
        const int h     = (col0 & 2047) >> 7;  // head
        float* dst = (which == 0) ? Cq : ((which == 1) ? Ck : Cv);
#pragma unroll
        for (int tm = 0; tm < 2; tm++) {
            const int rowtok = brow * TBM + wm * 32 + tm * 16 + g;
            const int bb = rowtok >> 11;
            const int ss = rowtok & 2047;
            float* base0 = dst + (((size_t)(bb * NHEADS + h) * S_LEN) + ss) * HDIM;
            const int rt8 = rowtok + 8;
            const int bb8 = rt8 >> 11;
            const int ss8 = rt8 & 2047;
            float* base8 = dst + (((size_t)(bb8 * NHEADS + h) * S_LEN) + ss8) * HDIM;
#pragma unroll
            for (int tn2 = 0; tn2 < 8; tn2++) {
                const int colh = wn * 64 + tn2 * 8 + 2 * q;
                *(float2*)&base0[colh] = make_float2(acc[tm][tn2][0], acc[tm][tn2][1]);
                *(float2*)&base8[colh] = make_float2(acc[tm][tn2][2], acc[tm][tn2][3]);
            }
        }
    }
}

// ---------------------------------------------------------------------------
// RoPE (interleaved pairs), in place on Q and K; rounds Q,K,V to tf32 (rna).
// token_positions may be int64 or (JAX x64-disabled) int32; detect layout.
// ---------------------------------------------------------------------------
__global__ void rope_kernel(float* __restrict__ Xq, float* __restrict__ Xk,
                            float* __restrict__ Xv,
                            const int* __restrict__ pos32)
{
    const int r = blockIdx.x;
    const int s = r & (S_LEN - 1);
    const int j = threadIdx.x;

    const bool is64 = (pos32[1] == 0);
    const int  p    = is64 ? pos32[2 * s] : pos32[s];

    float inv = powf(10000.0f, -(float)(2 * j) * (1.0f / 128.0f));
    float ang = (float)p * inv;
    float sn, cs;
    sincosf(ang, &sn, &cs);

    float* qp = Xq + r * HDIM + 2 * j;
    float x1 = qp[0], x2 = qp[1];
    qp[0] = f2tf(x1 * cs - x2 * sn);
    qp[1] = f2tf(x1 * sn + x2 * cs);

    float* kp = Xk + r * HDIM + 2 * j;
    x1 = kp[0]; x2 = kp[1];
    kp[0] = f2tf(x1 * cs - x2 * sn);
    kp[1] = f2tf(x1 * sn + x2 * cs);

    float* vp = Xv + r * HDIM;
    vp[j]      = f2tf(vp[j]);
    vp[j + 64] = f2tf(vp[j + 64]);
}

// ---------------------------------------------------------------------------
// Flash attention, tf32 HMMA (passing version; epilogue rounds g_attn to tf32).
// ---------------------------------------------------------------------------
#define FQ   128
#define FKT  64
#define QS   132
#define KS2  132
#define VS2  136
#define SMF_K0 (FQ * QS)
#define SMF_V0 (FQ * QS + 2 * FKT * KS2)
#define FLASH2_SMEM_BYTES ((FQ * QS + 2 * FKT * KS2 + 2 * FKT * VS2) * 4)

__global__ __launch_bounds__(256, 1)
void flash_tc(const float* __restrict__ Q, const float* __restrict__ K,
              const float* __restrict__ V, float* __restrict__ O)
{
    extern __shared__ float sm[];
    const int tid  = threadIdx.x;
    const int lane = tid & 31;
    const int w    = tid >> 5;
    const int g    = lane >> 2;
    const int q    = lane & 3;

    const int qb = blockIdx.x;
    const int h  = blockIdx.y;
    const int b  = blockIdx.z;

    const float* Qg = Q + (((size_t)(b * NHEADS + h)) * S_LEN + (size_t)qb * FQ) * HDIM;
    const float* Kg = K + ((size_t)(b * NHEADS + h)) * S_LEN * HDIM;
    const float* Vg = V + ((size_t)(b * NHEADS + h)) * S_LEN * HDIM;

    const uint32_t sb = (uint32_t)__cvta_generic_to_shared(sm);

#pragma unroll
    for (int i = 0; i < 16; i++) {
        int id  = i * 256 + tid;
        int row = id >> 5, c = (id & 31) << 2;
        cp16(sb + (uint32_t)(row * QS + c) * 4u, Qg + row * HDIM + c);
    }
#pragma unroll
    for (int i = 0; i < 8; i++) {
        int id  = i * 256 + tid;
        int row = id >> 5, c = (id & 31) << 2;
        cp16(sb + (uint32_t)(SMF_K0 + row * KS2 + c) * 4u, Kg + row * HDIM + c);
        cp16(sb + (uint32_t)(SMF_V0 + row * VS2 + c) * 4u, Vg + row * HDIM + c);
    }
    asm volatile("cp.async.commit_group;");

    float m0 = -1e30f, m1 = -1e30f, l0 = 0.0f, l1 = 0.0f;
    float acc[16][4];
#pragma unroll
    for (int nf = 0; nf < 16; nf++)
#pragma unroll
        for (int c = 0; c < 4; c++) acc[nf][c] = 0.0f;

    const float SC = 0.088388347648318447f;
    const int ntiles = 2 * qb + 2;
    const int r0 = qb * FQ + w * 16 + g;
    const int r1 = r0 + 8;

    for (int kt = 0; kt < ntiles; kt++) {
        asm volatile("cp.async.wait_group 0;");
        __syncthreads();

        if (kt + 1 < ntiles) {
            const int nbuf = (kt + 1) & 1;
            const float* Ks = Kg + (size_t)(kt + 1) * FKT * HDIM;
            const float* Vs = Vg + (size_t)(kt + 1) * FKT * HDIM;
#pragma unroll
            for (int i = 0; i < 8; i++) {
                int id  = i * 256 + tid;
                int row = id >> 5, c = (id & 31) << 2;
                cp16(sb + (uint32_t)(SMF_K0 + nbuf * FKT * KS2 + row * KS2 + c) * 4u,
                     Ks + row * HDIM + c);
                cp16(sb + (uint32_t)(SMF_V0 + nbuf * FKT * VS2 + row * VS2 + c) * 4u,
                     Vs + row * HDIM + c);
            }
            asm volatile("cp.async.commit_group;");
        }

        if (kt * FKT <= qb * FQ + w * 16 + 15) {
            const float* sq = sm;
            const float* sk = sm + SMF_K0 + (kt & 1) * FKT * KS2;
            const float* sv = sm + SMF_V0 + (kt & 1) * FKT * VS2;

            float sc[8][4];
#pragma unroll
            for (int nf = 0; nf < 8; nf++)
#pragma unroll
                for (int c = 0; c < 4; c++) sc[nf][c] = 0.0f;

#pragma unroll
            for (int k8 = 0; k8 < 16; k8++) {
                const int kc = k8 * 8;
                uint32_t a0 = __float_as_uint(sq[(w * 16 + g)     * QS + kc + q]);
                uint32_t a1 = __float_as_uint(sq[(w * 16 + g + 8) * QS + kc + q]);
                uint32_t a2 = __float_as_uint(sq[(w * 16 + g)     * QS + kc + q + 4]);
                uint32_t a3 = __float_as_uint(sq[(w * 16 + g + 8) * QS + kc + q + 4]);
#pragma unroll
                for (int nf = 0; nf < 8; nf++) {
                    uint32_t b0 = __float_as_uint(sk[(nf * 8 + g) * KS2 + kc + q]);
                    uint32_t b1 = __float_as_uint(sk[(nf * 8 + g) * KS2 + kc + q + 4]);
                    mma_tf32(sc[nf], a0, a1, a2, a3, b0, b1);
                }
            }

            if (kt * FKT + FKT - 1 > r0) {
#pragma unroll
                for (int nf = 0; nf < 8; nf++) {
#pragma unroll
                    for (int cb = 0; cb < 2; cb++) {
                        int kcol = kt * FKT + nf * 8 + 2 * q + cb;
                        if (kcol > r0) sc[nf][cb]     = -1e30f;
                        if (kcol > r1) sc[nf][2 + cb] = -1e30f;
                    }
                }
            }

            float mx0 = -1e30f, mx1 = -1e30f;
#pragma unroll
            for (int nf = 0; nf < 8; nf++) {
                mx0 = fmaxf(mx0, fmaxf(sc[nf][0], sc[nf][1]));
                mx1 = fmaxf(mx1, fmaxf(sc[nf][2], sc[nf][3]));
            }
            mx0 = fmaxf(mx0, __shfl_xor_sync(0xffffffffu, mx0, 1));
            mx0 = fmaxf(mx0, __shfl_xor_sync(0xffffffffu, mx0, 2));
            mx1 = fmaxf(mx1, __shfl_xor_sync(0xffffffffu, mx1, 1));
            mx1 = fmaxf(mx1, __shfl_xor_sync(0xffffffffu, mx1, 2));

            float mn0 = fmaxf(m0, mx0), mn1 = fmaxf(m1, mx1);
            float al0 = __expf(SC * (m0 - mn0));
            float al1 = __expf(SC * (m1 - mn1));
            m0 = mn0; m1 = mn1;

            float rs0 = 0.0f, rs1 = 0.0f;
#pragma unroll
            for (int nf = 0; nf < 8; nf++) {
                float p0 = f2tf(__expf(SC * (sc[nf][0] - m0)));
                float p1 = f2tf(__expf(SC * (sc[nf][1] - m0)));
                float p2 = f2tf(__expf(SC * (sc[nf][2] - m1)));
                float p3 = f2tf(__expf(SC * (sc[nf][3] - m1)));
                sc[nf][0] = p0; sc[nf][1] = p1; sc[nf][2] = p2; sc[nf][3] = p3;
                rs0 += p0 + p1;
                rs1 += p2 + p3;
            }
            rs0 += __shfl_xor_sync(0xffffffffu, rs0, 1);
            rs0 += __shfl_xor_sync(0xffffffffu, rs0, 2);
            rs1 += __shfl_xor_sync(0xffffffffu, rs1, 1);
            rs1 += __shfl_xor_sync(0xffffffffu, rs1, 2);
            l0 = l0 * al0 + rs0;
            l1 = l1 * al1 + rs1;

#pragma unroll
            for (int nf = 0; nf < 16; nf++) {
                acc[nf][0] *= al0; acc[nf][1] *= al0;
                acc[nf][2] *= al1; acc[nf][3] *= al1;
            }

#pragma unroll
            for (int j = 0; j < 8; j++) {
                const int s0 = (q >> 1);
                const int s1 = 2 + (q >> 1);
                float v00 = __shfl_sync(0xffffffffu, sc[j][0], s0, 4);
                float v01 = __shfl_sync(0xffffffffu, sc[j][1], s0, 4);
                float v10 = __shfl_sync(0xffffffffu, sc[j][2], s0, 4);
                float v11 = __shfl_sync(0xffffffffu, sc[j][3], s0, 4);
                uint32_t a0 = __float_as_uint((q & 1) ? v01 : v00);
                uint32_t a1 = __float_as_uint((q & 1) ? v11 : v10);
                v00 = __shfl_sync(0xffffffffu, sc[j][0], s1, 4);
                v01 = __shfl_sync(0xffffffffu, sc[j][1], s1, 4);
                v10 = __shfl_sync(0xffffffffu, sc[j][2], s1, 4);
                v11 = __shfl_sync(0xffffffffu, sc[j][3], s1, 4);
                uint32_t a2 = __float_as_uint((q & 1) ? v01 : v00);
                uint32_t a3 = __float_as_uint((q & 1) ? v11 : v10);
#pragma unroll
                for (int nf = 0; nf < 16; nf++) {
                    uint32_t b0 = __float_as_uint(sv[(j * 8 + q)     * VS2 + nf * 8 + g]);
                    uint32_t b1 = __float_as_uint(sv[(j * 8 + q + 4) * VS2 + nf * 8 + g]);
                    mma_tf32(acc[nf], a0, a1, a2, a3, b0, b1);
                }
            }
        }
    }

    // epilogue: normalize + tf32-round (GEMM2 inputs pre-rounded)
    const float inv0 = 1.0f / l0;
    const float inv1 = 1.0f / l1;
    float* o0 = O + ((size_t)(b * S_LEN + r0)) * D_MODEL + h * HDIM;
    float* o1 = o0 + (size_t)8 * D_MODEL;
#pragma unroll
    for (int nf = 0; nf < 16; nf++) {
        const int col = nf * 8 + 2 * q;
        *(float2*)&o0[col] = make_float2(f2tf(acc[nf][0] * inv0), f2tf(acc[nf][1] * inv0));
        *(float2*)&o1[col] = make_float2(f2tf(acc[nf][2] * inv1), f2tf(acc[nf][3] * inv1));
    }
}

// ---------------------------------------------------------------------------
// Launch
// ---------------------------------------------------------------------------
extern "C" void kernel_launch(void* const* d_in, const int* in_sizes, int n_in,
                              void* d_out, int out_size)
{
    const float* x     = (const float*)d_in[0];
    const int*   pos32 = (const int*)d_in[1];
    const float* w_qkv = (const float*)d_in[2];
    const float* w_o   = (const float*)d_in[3];
    float* out         = (float*)d_out;

    float *q, *k, *v, *attn, *xtf, *wqkv, *wo;
    cudaGetSymbolAddress((void**)&q,    g_q);
    cudaGetSymbolAddress((void**)&k,    g_k);
    cudaGetSymbolAddress((void**)&v,    g_v);
    cudaGetSymbolAddress((void**)&attn, g_attn);
    cudaGetSymbolAddress((void**)&xtf,  g_xtf);
    cudaGetSymbolAddress((void**)&wqkv, g_wqkv);
    cudaGetSymbolAddress((void**)&wo,   g_wo);

    cudaFuncSetAttribute(tf32_gemm_pipe<1>,
                         cudaFuncAttributeMaxDynamicSharedMemorySize, GEMM_SMEM);
    cudaFuncSetAttribute(tf32_gemm_pipe<0>,
                         cudaFuncAttributeMaxDynamicSharedMemorySize, GEMM_SMEM);
    cudaFuncSetAttribute(flash_tc,
                         cudaFuncAttributeMaxDynamicSharedMemorySize,
                         FLASH2_SMEM_BYTES);

    // 0) pre-round inputs to tf32 (rna) -- unbiased, idempotent
    {
        const int nx = NTOK * D_MODEL / 4;
        const int nq = D_MODEL * QKV_N / 4;
        const int nw = D_MODEL * D_MODEL / 4;
        tf32_round_kernel<<<nx / 256, 256>>>((const float4*)x,     (float4*)xtf,  nx);
        tf32_round_kernel<<<nq / 256, 256>>>((const float4*)w_qkv, (float4*)wqkv, nq);
        tf32_round_kernel<<<nw / 256, 256>>>((const float4*)w_o,   (float4*)wo,   nw);
    }

    // 1) QKV projection (pipelined tf32 HMMA, BK=32) with scatter epilogue
    tf32_gemm_pipe<1><<<dim3(QKV_N / TBN, NTOK / TBM), 256, GEMM_SMEM>>>(
        xtf, wqkv, nullptr, q, k, v, QKV_N, D_MODEL);

    // 2) RoPE on Q and K (in place) + tf32 rounding of Q,K,V
    rope_kernel<<<BATCH * NHEADS * S_LEN, 64>>>(q, k, v, pos32);

    // 3) causal flash attention (tf32 HMMA)
    flash_tc<<<dim3(S_LEN / FQ, NHEADS, BATCH), 256, FLASH2_SMEM_BYTES>>>(
        q, k, v, attn);

    // 4) output projection (pipelined tf32 HMMA, BK=32)
    tf32_gemm_pipe<0><<<dim3(D_MODEL / TBN, NTOK / TBM), 256, GEMM_SMEM>>>(
        attn, wo, out, nullptr, nullptr, nullptr, D_MODEL, D_MODEL);
}

// round 9
// speedup vs baseline: 4.2263x; 1.0204x over previous
#include <cuda_runtime.h>
#include <math.h>
#include <stdint.h>

// ---------------------------------------------------------------------------
// Problem constants
// ---------------------------------------------------------------------------
#define S_LEN   2048
#define D_MODEL 2048
#define NHEADS  16
#define HDIM    128
#define BATCH   2
#define NTOK    (BATCH * S_LEN)   // 4096
#define QKV_N   (3 * D_MODEL)     // 6144

// ---------------------------------------------------------------------------
// Scratch (device globals -- no allocation allowed in kernel_launch)
// ---------------------------------------------------------------------------
__device__ float g_q[BATCH * NHEADS * S_LEN * HDIM];
__device__ float g_k[BATCH * NHEADS * S_LEN * HDIM];
__device__ float g_v[BATCH * NHEADS * S_LEN * HDIM];
__device__ float g_attn[NTOK * D_MODEL];
__device__ float g_xtf[NTOK * D_MODEL];          // tf32-rounded x
__device__ float g_wqkv[D_MODEL * QKV_N];        // tf32-rounded w_qkv
__device__ float g_wo[D_MODEL * D_MODEL];        // tf32-rounded w_o

// ---------------------------------------------------------------------------
// tf32 helpers
// ---------------------------------------------------------------------------
__device__ __forceinline__ float f2tf(float x) {
    uint32_t u;
    asm("cvt.rna.tf32.f32 %0, %1;" : "=r"(u) : "f"(x));
    return __uint_as_float(u);
}
__device__ __forceinline__ float4 cvt4(float4 v) {
    v.x = f2tf(v.x); v.y = f2tf(v.y); v.z = f2tf(v.z); v.w = f2tf(v.w);
    return v;
}
__device__ __forceinline__ void mma_tf32(float c[4],
                                         uint32_t a0, uint32_t a1,
                                         uint32_t a2, uint32_t a3,
                                         uint32_t b0, uint32_t b1) {
    asm volatile(
        "mma.sync.aligned.m16n8k8.row.col.f32.tf32.tf32.f32 "
        "{%0,%1,%2,%3}, {%4,%5,%6,%7}, {%8,%9}, {%0,%1,%2,%3};"
        : "+f"(c[0]), "+f"(c[1]), "+f"(c[2]), "+f"(c[3])
        : "r"(a0), "r"(a1), "r"(a2), "r"(a3), "r"(b0), "r"(b1));
}
__device__ __forceinline__ void cp16(uint32_t dst, const void* src) {
    asm volatile("cp.async.cg.shared.global [%0], [%1], 16;"
                 :: "r"(dst), "l"(src));
}

// ---------------------------------------------------------------------------
// Prep: elementwise tf32 (rna) rounding into scratch.
// ---------------------------------------------------------------------------
__global__ void tf32_round_kernel(const float4* __restrict__ in,
                                  float4* __restrict__ out, int n4)
{
    int i = blockIdx.x * blockDim.x + threadIdx.x;
    if (i < n4) out[i] = cvt4(in[i]);
}

// ---------------------------------------------------------------------------
// tf32 HMMA GEMM, cp.async 3-stage pipeline, BK=32.
// CUTLASS-style: 128 threads, 4 warps (2x2) of 64x64; 255-reg budget lets
// ptxas double-buffer fragments across k8 steps (the round-8 stall).
// C[M,N] = A[M,K] @ B[K,N]; A,B already tf32-rounded in gmem.
// MODE 0: plain store.  MODE 1: scatter into Q/K/V [B][H][S][hd].
// ---------------------------------------------------------------------------
#define TBM 128
#define TBN 128
#define TBK 32
#define ASTR 36          // A row stride: frag banks (4g+q) distinct
#define BSTR 136         // B row stride: frag banks (8q+g) distinct
#define STG  3
#define AS_FLOATS (TBM * ASTR)               // 4608
#define BS_FLOATS (TBK * BSTR)               // 4352
#define STAGE_FLOATS (AS_FLOATS + BS_FLOATS) // 8960
#define GEMM_SMEM (STG * STAGE_FLOATS * 4)   // 107520 B

template <int MODE>
__global__ __launch_bounds__(128, 2)
void tf32_gemm_pipe(const float* __restrict__ A, const float* __restrict__ B,
                    float* __restrict__ C,
                    float* __restrict__ Cq, float* __restrict__ Ck,
                    float* __restrict__ Cv,
                    int N, int K)
{
    extern __shared__ float smem[];
    const uint32_t sb = (uint32_t)__cvta_generic_to_shared(smem);

    const int tid  = threadIdx.x;
    const int lane = tid & 31;
    const int wid  = tid >> 5;          // 0..3
    const int wm   = wid >> 1;          // 0..1  (M)
    const int wn   = wid & 1;           // 0..1  (N)
    const int g    = lane >> 2;         // 0..7
    const int q    = lane & 3;          // 0..3

    const int brow = blockIdx.y;
    const int bcol = blockIdx.x;
    const float* Ab = A + (size_t)brow * TBM * K;
    const float* Bb = B + bcol * TBN;

    const int T = K / TBK;

    // prefetch first STG-1 tiles: 1024 A-chunks + 1024 B-chunks, 8+8 per thread
#pragma unroll
    for (int p = 0; p < STG - 1; p++) {
        const uint32_t sa  = sb + (uint32_t)(p * STAGE_FLOATS) * 4u;
        const uint32_t sbb = sa + (uint32_t)AS_FLOATS * 4u;
        const int kt = p * TBK;
#pragma unroll
        for (int i = 0; i < 8; i++) {
            const int c  = tid + i * 128;
            const int arr = c >> 3, acf = (c & 7) << 2;
            const int brr = c >> 5, bcf = (c & 31) << 2;
            cp16(sa  + (uint32_t)(arr * ASTR + acf) * 4u, Ab + (size_t)arr * K + kt + acf);
            cp16(sbb + (uint32_t)(brr * BSTR + bcf) * 4u, Bb + (size_t)(kt + brr) * N + bcf);
        }
        asm volatile("cp.async.commit_group;");
    }

    float acc[4][8][4];
#pragma unroll
    for (int i = 0; i < 4; i++)
#pragma unroll
        for (int j = 0; j < 8; j++)
#pragma unroll
            for (int r = 0; r < 4; r++) acc[i][j][r] = 0.0f;

    int stage = 0;
    for (int t = 0; t < T; t++) {
        asm volatile("cp.async.wait_group %0;" :: "n"(STG - 2));
        __syncthreads();

        // issue loads for tile t+STG-1 into the stage freed at t-1
        {
            const int tn = t + STG - 1;
            if (tn < T) {
                int st = stage + (STG - 1);
                if (st >= STG) st -= STG;
                const uint32_t sa  = sb + (uint32_t)(st * STAGE_FLOATS) * 4u;
                const uint32_t sbb = sa + (uint32_t)AS_FLOATS * 4u;
                const int kt = tn * TBK;
#pragma unroll
                for (int i = 0; i < 8; i++) {
                    const int c  = tid + i * 128;
                    const int arr = c >> 3, acf = (c & 7) << 2;
                    const int brr = c >> 5, bcf = (c & 31) << 2;
                    cp16(sa  + (uint32_t)(arr * ASTR + acf) * 4u,
                         Ab + (size_t)arr * K + kt + acf);
                    cp16(sbb + (uint32_t)(brr * BSTR + bcf) * 4u,
                         Bb + (size_t)(kt + brr) * N + bcf);
                }
            }
            asm volatile("cp.async.commit_group;");
        }

        // compute tile t: 4 unrolled k8 steps, 32 LDS + 32 HMMA each (no barriers)
        const float* as_p = smem + stage * STAGE_FLOATS;
        const float* bs_p = as_p + AS_FLOATS;
#pragma unroll
        for (int k8 = 0; k8 < TBK; k8 += 8) {
            uint32_t af[4][4];
#pragma unroll
            for (int tm = 0; tm < 4; tm++) {
                const int rA = wm * 64 + tm * 16 + g;
                af[tm][0] = __float_as_uint(as_p[rA * ASTR + k8 + q]);
                af[tm][1] = __float_as_uint(as_p[(rA + 8) * ASTR + k8 + q]);
                af[tm][2] = __float_as_uint(as_p[rA * ASTR + k8 + q + 4]);
                af[tm][3] = __float_as_uint(as_p[(rA + 8) * ASTR + k8 + q + 4]);
            }
            uint32_t bf[8][2];
#pragma unroll
            for (int tn2 = 0; tn2 < 8; tn2++) {
                const int nB = wn * 64 + tn2 * 8 + g;
                bf[tn2][0] = __float_as_uint(bs_p[(k8 + q) * BSTR + nB]);
                bf[tn2][1] = __float_as_uint(bs_p[(k8 + q + 4) * BSTR + nB]);
            }
#pragma unroll
            for (int tm = 0; tm < 4; tm++)
#pragma unroll
                for (int tn2 = 0; tn2 < 8; tn2++)
                    mma_tf32(acc[tm][tn2],
                             af[tm][0], af[tm][1], af[tm][2], af[tm][3],
                             bf[tn2][0], bf[tn2][1]);
        }
        if (++stage == STG) stage = 0;
    }

    // ---------------- epilogue ----------------
    if (MODE == 0) {
#pragma unroll
        for (int tm = 0; tm < 4; tm++) {
            const int row = brow * TBM + wm * 64 + tm * 16 + g;
#pragma unroll
            for (int tn2 = 0; tn2 < 8; tn2++) {
                const int col = bcol * TBN + wn * 64 + tn2 * 8 + 2 * q;
                *(float2*)&C[(size_t)row * N + col] =
                    make_float2(acc[tm][tn2][0], acc[tm][tn2][1]);
                *(float2*)&C[(size_t)(row + 8) * N + col] =
                    make_float2(acc[tm][tn2][2], acc[tm][tn2][3]);
            }
        }
    } else {
        const int col0  = bcol * TBN;
        const int which = col0 >> 11;          // 0=q,1=k,2=v
        const int h     = (col0 & 2047) >> 7;  // head
        float* dst = (which == 0) ? Cq : ((which == 1) ? Ck : Cv);
#pragma unroll
        for (int tm = 0; tm < 4; tm++) {
            const int rowtok = brow * TBM + wm * 64 + tm * 16 + g;
            const int bb = rowtok >> 11;
            const int ss = rowtok & 2047;
            float* base0 = dst + (((size_t)(bb * NHEADS + h) * S_LEN) + ss) * HDIM;
            const int rt8 = rowtok + 8;
            const int bb8 = rt8 >> 11;
            const int ss8 = rt8 & 2047;
            float* base8 = dst + (((size_t)(bb8 * NHEADS + h) * S_LEN) + ss8) * HDIM;
#pragma unroll
            for (int tn2 = 0; tn2 < 8; tn2++) {
                const int colh = wn * 64 + tn2 * 8 + 2 * q;
                *(float2*)&base0[colh] = make_float2(acc[tm][tn2][0], acc[tm][tn2][1]);
                *(float2*)&base8[colh] = make_float2(acc[tm][tn2][2], acc[tm][tn2][3]);
            }
        }
    }
}

// ---------------------------------------------------------------------------
// RoPE (interleaved pairs), in place on Q and K; rounds Q,K,V to tf32 (rna).
// token_positions may be int64 or (JAX x64-disabled) int32; detect layout.
// ---------------------------------------------------------------------------
__global__ void rope_kernel(float* __restrict__ Xq, float* __restrict__ Xk,
                            float* __restrict__ Xv,
                            const int* __restrict__ pos32)
{
    const int r = blockIdx.x;
    const int s = r & (S_LEN - 1);
    const int j = threadIdx.x;

    const bool is64 = (pos32[1] == 0);
    const int  p    = is64 ? pos32[2 * s] : pos32[s];

    float inv = powf(10000.0f, -(float)(2 * j) * (1.0f / 128.0f));
    float ang = (float)p * inv;
    float sn, cs;
    sincosf(ang, &sn, &cs);

    float* qp = Xq + r * HDIM + 2 * j;
    float x1 = qp[0], x2 = qp[1];
    qp[0] = f2tf(x1 * cs - x2 * sn);
    qp[1] = f2tf(x1 * sn + x2 * cs);

    float* kp = Xk + r * HDIM + 2 * j;
    x1 = kp[0]; x2 = kp[1];
    kp[0] = f2tf(x1 * cs - x2 * sn);
    kp[1] = f2tf(x1 * sn + x2 * cs);

    float* vp = Xv + r * HDIM;
    vp[j]      = f2tf(vp[j]);
    vp[j + 64] = f2tf(vp[j + 64]);
}

// ---------------------------------------------------------------------------
// Flash attention, tf32 HMMA (passing version; epilogue rounds g_attn to tf32).
// ---------------------------------------------------------------------------
#define FQ   128
#define FKT  64
#define QS   132
#define KS2  132
#define VS2  136
#define SMF_K0 (FQ * QS)
#define SMF_V0 (FQ * QS + 2 * FKT * KS2)
#define FLASH2_SMEM_BYTES ((FQ * QS + 2 * FKT * KS2 + 2 * FKT * VS2) * 4)

__global__ __launch_bounds__(256, 1)
void flash_tc(const float* __restrict__ Q, const float* __restrict__ K,
              const float* __restrict__ V, float* __restrict__ O)
{
    extern __shared__ float sm[];
    const int tid  = threadIdx.x;
    const int lane = tid & 31;
    const int w    = tid >> 5;
    const int g    = lane >> 2;
    const int q    = lane & 3;

    const int qb = blockIdx.x;
    const int h  = blockIdx.y;
    const int b  = blockIdx.z;

    const float* Qg = Q + (((size_t)(b * NHEADS + h)) * S_LEN + (size_t)qb * FQ) * HDIM;
    const float* Kg = K + ((size_t)(b * NHEADS + h)) * S_LEN * HDIM;
    const float* Vg = V + ((size_t)(b * NHEADS + h)) * S_LEN * HDIM;

    const uint32_t sb = (uint32_t)__cvta_generic_to_shared(sm);

#pragma unroll
    for (int i = 0; i < 16; i++) {
        int id  = i * 256 + tid;
        int row = id >> 5, c = (id & 31) << 2;
        cp16(sb + (uint32_t)(row * QS + c) * 4u, Qg + row * HDIM + c);
    }
#pragma unroll
    for (int i = 0; i < 8; i++) {
        int id  = i * 256 + tid;
        int row = id >> 5, c = (id & 31) << 2;
        cp16(sb + (uint32_t)(SMF_K0 + row * KS2 + c) * 4u, Kg + row * HDIM + c);
        cp16(sb + (uint32_t)(SMF_V0 + row * VS2 + c) * 4u, Vg + row * HDIM + c);
    }
    asm volatile("cp.async.commit_group;");

    float m0 = -1e30f, m1 = -1e30f, l0 = 0.0f, l1 = 0.0f;
    float acc[16][4];
#pragma unroll
    for (int nf = 0; nf < 16; nf++)
#pragma unroll
        for (int c = 0; c < 4; c++) acc[nf][c] = 0.0f;

    const float SC = 0.088388347648318447f;
    const int ntiles = 2 * qb + 2;
    const int r0 = qb * FQ + w * 16 + g;
    const int r1 = r0 + 8;

    for (int kt = 0; kt < ntiles; kt++) {
        asm volatile("cp.async.wait_group 0;");
        __syncthreads();

        if (kt + 1 < ntiles) {
            const int nbuf = (kt + 1) & 1;
            const float* Ks = Kg + (size_t)(kt + 1) * FKT * HDIM;
            const float* Vs = Vg + (size_t)(kt + 1) * FKT * HDIM;
#pragma unroll
            for (int i = 0; i < 8; i++) {
                int id  = i * 256 + tid;
                int row = id >> 5, c = (id & 31) << 2;
                cp16(sb + (uint32_t)(SMF_K0 + nbuf * FKT * KS2 + row * KS2 + c) * 4u,
                     Ks + row * HDIM + c);
                cp16(sb + (uint32_t)(SMF_V0 + nbuf * FKT * VS2 + row * VS2 + c) * 4u,
                     Vs + row * HDIM + c);
            }
            asm volatile("cp.async.commit_group;");
        }

        if (kt * FKT <= qb * FQ + w * 16 + 15) {
            const float* sq = sm;
            const float* sk = sm + SMF_K0 + (kt & 1) * FKT * KS2;
            const float* sv = sm + SMF_V0 + (kt & 1) * FKT * VS2;

            float sc[8][4];
#pragma unroll
            for (int nf = 0; nf < 8; nf++)
#pragma unroll
                for (int c = 0; c < 4; c++) sc[nf][c] = 0.0f;

#pragma unroll
            for (int k8 = 0; k8 < 16; k8++) {
                const int kc = k8 * 8;
                uint32_t a0 = __float_as_uint(sq[(w * 16 + g)     * QS + kc + q]);
                uint32_t a1 = __float_as_uint(sq[(w * 16 + g + 8) * QS + kc + q]);
                uint32_t a2 = __float_as_uint(sq[(w * 16 + g)     * QS + kc + q + 4]);
                uint32_t a3 = __float_as_uint(sq[(w * 16 + g + 8) * QS + kc + q + 4]);
#pragma unroll
                for (int nf = 0; nf < 8; nf++) {
                    uint32_t b0 = __float_as_uint(sk[(nf * 8 + g) * KS2 + kc + q]);
                    uint32_t b1 = __float_as_uint(sk[(nf * 8 + g) * KS2 + kc + q + 4]);
                    mma_tf32(sc[nf], a0, a1, a2, a3, b0, b1);
                }
            }

            if (kt * FKT + FKT - 1 > r0) {
#pragma unroll
                for (int nf = 0; nf < 8; nf++) {
#pragma unroll
                    for (int cb = 0; cb < 2; cb++) {
                        int kcol = kt * FKT + nf * 8 + 2 * q + cb;
                        if (kcol > r0) sc[nf][cb]     = -1e30f;
                        if (kcol > r1) sc[nf][2 + cb] = -1e30f;
                    }
                }
            }

            float mx0 = -1e30f, mx1 = -1e30f;
#pragma unroll
            for (int nf = 0; nf < 8; nf++) {
                mx0 = fmaxf(mx0, fmaxf(sc[nf][0], sc[nf][1]));
                mx1 = fmaxf(mx1, fmaxf(sc[nf][2], sc[nf][3]));
            }
            mx0 = fmaxf(mx0, __shfl_xor_sync(0xffffffffu, mx0, 1));
            mx0 = fmaxf(mx0, __shfl_xor_sync(0xffffffffu, mx0, 2));
            mx1 = fmaxf(mx1, __shfl_xor_sync(0xffffffffu, mx1, 1));
            mx1 = fmaxf(mx1, __shfl_xor_sync(0xffffffffu, mx1, 2));

            float mn0 = fmaxf(m0, mx0), mn1 = fmaxf(m1, mx1);
            float al0 = __expf(SC * (m0 - mn0));
            float al1 = __expf(SC * (m1 - mn1));
            m0 = mn0; m1 = mn1;

            float rs0 = 0.0f, rs1 = 0.0f;
#pragma unroll
            for (int nf = 0; nf < 8; nf++) {
                float p0 = f2tf(__expf(SC * (sc[nf][0] - m0)));
                float p1 = f2tf(__expf(SC * (sc[nf][1] - m0)));
                float p2 = f2tf(__expf(SC * (sc[nf][2] - m1)));
                float p3 = f2tf(__expf(SC * (sc[nf][3] - m1)));
                sc[nf][0] = p0; sc[nf][1] = p1; sc[nf][2] = p2; sc[nf][3] = p3;
                rs0 += p0 + p1;
                rs1 += p2 + p3;
            }
            rs0 += __shfl_xor_sync(0xffffffffu, rs0, 1);
            rs0 += __shfl_xor_sync(0xffffffffu, rs0, 2);
            rs1 += __shfl_xor_sync(0xffffffffu, rs1, 1);
            rs1 += __shfl_xor_sync(0xffffffffu, rs1, 2);
            l0 = l0 * al0 + rs0;
            l1 = l1 * al1 + rs1;

#pragma unroll
            for (int nf = 0; nf < 16; nf++) {
                acc[nf][0] *= al0; acc[nf][1] *= al0;
                acc[nf][2] *= al1; acc[nf][3] *= al1;
            }

#pragma unroll
            for (int j = 0; j < 8; j++) {
                const int s0 = (q >> 1);
                const int s1 = 2 + (q >> 1);
                float v00 = __shfl_sync(0xffffffffu, sc[j][0], s0, 4);
                float v01 = __shfl_sync(0xffffffffu, sc[j][1], s0, 4);
                float v10 = __shfl_sync(0xffffffffu, sc[j][2], s0, 4);
                float v11 = __shfl_sync(0xffffffffu, sc[j][3], s0, 4);
                uint32_t a0 = __float_as_uint((q & 1) ? v01 : v00);
                uint32_t a1 = __float_as_uint((q & 1) ? v11 : v10);
                v00 = __shfl_sync(0xffffffffu, sc[j][0], s1, 4);
                v01 = __shfl_sync(0xffffffffu, sc[j][1], s1, 4);
                v10 = __shfl_sync(0xffffffffu, sc[j][2], s1, 4);
                v11 = __shfl_sync(0xffffffffu, sc[j][3], s1, 4);
                uint32_t a2 = __float_as_uint((q & 1) ? v01 : v00);
                uint32_t a3 = __float_as_uint((q & 1) ? v11 : v10);
#pragma unroll
                for (int nf = 0; nf < 16; nf++) {
                    uint32_t b0 = __float_as_uint(sv[(j * 8 + q)     * VS2 + nf * 8 + g]);
                    uint32_t b1 = __float_as_uint(sv[(j * 8 + q + 4) * VS2 + nf * 8 + g]);
                    mma_tf32(acc[nf], a0, a1, a2, a3, b0, b1);
                }
            }
        }
    }

    // epilogue: normalize + tf32-round (GEMM2 inputs pre-rounded)
    const float inv0 = 1.0f / l0;
    const float inv1 = 1.0f / l1;
    float* o0 = O + ((size_t)(b * S_LEN + r0)) * D_MODEL + h * HDIM;
    float* o1 = o0 + (size_t)8 * D_MODEL;
#pragma unroll
    for (int nf = 0; nf < 16; nf++) {
        const int col = nf * 8 + 2 * q;
        *(float2*)&o0[col] = make_float2(f2tf(acc[nf][0] * inv0), f2tf(acc[nf][1] * inv0));
        *(float2*)&o1[col] = make_float2(f2tf(acc[nf][2] * inv1), f2tf(acc[nf][3] * inv1));
    }
}

// ---------------------------------------------------------------------------
// Launch
// ---------------------------------------------------------------------------
extern "C" void kernel_launch(void* const* d_in, const int* in_sizes, int n_in,
                              void* d_out, int out_size)
{
    const float* x     = (const float*)d_in[0];
    const int*   pos32 = (const int*)d_in[1];
    const float* w_qkv = (const float*)d_in[2];
    const float* w_o   = (const float*)d_in[3];
    float* out         = (float*)d_out;

    float *q, *k, *v, *attn, *xtf, *wqkv, *wo;
    cudaGetSymbolAddress((void**)&q,    g_q);
    cudaGetSymbolAddress((void**)&k,    g_k);
    cudaGetSymbolAddress((void**)&v,    g_v);
    cudaGetSymbolAddress((void**)&attn, g_attn);
    cudaGetSymbolAddress((void**)&xtf,  g_xtf);
    cudaGetSymbolAddress((void**)&wqkv, g_wqkv);
    cudaGetSymbolAddress((void**)&wo,   g_wo);

    cudaFuncSetAttribute(tf32_gemm_pipe<1>,
                         cudaFuncAttributeMaxDynamicSharedMemorySize, GEMM_SMEM);
    cudaFuncSetAttribute(tf32_gemm_pipe<0>,
                         cudaFuncAttributeMaxDynamicSharedMemorySize, GEMM_SMEM);
    cudaFuncSetAttribute(flash_tc,
                         cudaFuncAttributeMaxDynamicSharedMemorySize,
                         FLASH2_SMEM_BYTES);

    // 0) pre-round inputs to tf32 (rna) -- unbiased, idempotent
    {
        const int nx = NTOK * D_MODEL / 4;
        const int nq = D_MODEL * QKV_N / 4;
        const int nw = D_MODEL * D_MODEL / 4;
        tf32_round_kernel<<<nx / 256, 256>>>((const float4*)x,     (float4*)xtf,  nx);
        tf32_round_kernel<<<nq / 256, 256>>>((const float4*)w_qkv, (float4*)wqkv, nq);
        tf32_round_kernel<<<nw / 256, 256>>>((const float4*)w_o,   (float4*)wo,   nw);
    }

    // 1) QKV projection (tf32 HMMA, 64x64 warp tile) with scatter epilogue
    tf32_gemm_pipe<1><<<dim3(QKV_N / TBN, NTOK / TBM), 128, GEMM_SMEM>>>(
        xtf, wqkv, nullptr, q, k, v, QKV_N, D_MODEL);

    // 2) RoPE on Q and K (in place) + tf32 rounding of Q,K,V
    rope_kernel<<<BATCH * NHEADS * S_LEN, 64>>>(q, k, v, pos32);

    // 3) causal flash attention (tf32 HMMA)
    flash_tc<<<dim3(S_LEN / FQ, NHEADS, BATCH), 256, FLASH2_SMEM_BYTES>>>(
        q, k, v, attn);

    // 4) output projection (tf32 HMMA, 64x64 warp tile)
    tf32_gemm_pipe<0><<<dim3(D_MODEL / TBN, NTOK / TBM), 128, GEMM_SMEM>>>(
        attn, wo, out, nullptr, nullptr, nullptr, D_MODEL, D_MODEL);
}

// round 11
// speedup vs baseline: 4.2297x; 1.0008x over previous
#include <cuda_runtime.h>
#include <math.h>
#include <stdint.h>

// ---------------------------------------------------------------------------
// Problem constants
// ---------------------------------------------------------------------------
#define S_LEN   2048
#define D_MODEL 2048
#define NHEADS  16
#define HDIM    128
#define BATCH   2
#define NTOK    (BATCH * S_LEN)   // 4096
#define QKV_N   (3 * D_MODEL)     // 6144

// ---------------------------------------------------------------------------
// Scratch (device globals -- no allocation allowed in kernel_launch)
// ---------------------------------------------------------------------------
__device__ float g_q[BATCH * NHEADS * S_LEN * HDIM];
__device__ float g_k[BATCH * NHEADS * S_LEN * HDIM];
__device__ float g_v[BATCH * NHEADS * S_LEN * HDIM];
__device__ float g_attn[NTOK * D_MODEL];
__device__ float g_xtf[NTOK * D_MODEL];          // tf32-rounded x
__device__ float g_wqkv[D_MODEL * QKV_N];        // tf32-rounded w_qkv
__device__ float g_wo[D_MODEL * D_MODEL];        // tf32-rounded w_o

// ---------------------------------------------------------------------------
// tf32 helpers
// ---------------------------------------------------------------------------
__device__ __forceinline__ float f2tf(float x) {
    uint32_t u;
    asm("cvt.rna.tf32.f32 %0, %1;" : "=r"(u) : "f"(x));
    return __uint_as_float(u);
}
__device__ __forceinline__ float4 cvt4(float4 v) {
    v.x = f2tf(v.x); v.y = f2tf(v.y); v.z = f2tf(v.z); v.w = f2tf(v.w);
    return v;
}
__device__ __forceinline__ void mma_tf32(float c[4],
                                         uint32_t a0, uint32_t a1,
                                         uint32_t a2, uint32_t a3,
                                         uint32_t b0, uint32_t b1) {
    asm volatile(
        "mma.sync.aligned.m16n8k8.row.col.f32.tf32.tf32.f32 "
        "{%0,%1,%2,%3}, {%4,%5,%6,%7}, {%8,%9}, {%0,%1,%2,%3};"
        : "+f"(c[0]), "+f"(c[1]), "+f"(c[2]), "+f"(c[3])
        : "r"(a0), "r"(a1), "r"(a2), "r"(a3), "r"(b0), "r"(b1));
}
__device__ __forceinline__ void cp16(uint32_t dst, const void* src) {
    asm volatile("cp.async.cg.shared.global [%0], [%1], 16;"
                 :: "r"(dst), "l"(src));
}

// ---------------------------------------------------------------------------
// Prep: elementwise tf32 (rna) rounding into scratch.
// ---------------------------------------------------------------------------
__global__ void tf32_round_kernel(const float4* __restrict__ in,
                                  float4* __restrict__ out, int n4)
{
    int i = blockIdx.x * blockDim.x + threadIdx.x;
    if (i < n4) out[i] = cvt4(in[i]);
}

// ---------------------------------------------------------------------------
// tf32 HMMA GEMM, cp.async 3-stage pipeline, BK=32, MANUAL fragment
// double-buffering: step k8+1's LDS issue before step k8's HMMAs so shared
// latency hides under tensor work (ptxas does not do this on its own --
// rounds 8/9 evidence).
// 128 threads, 4 warps (2x2) of 64x64.  A,B already tf32-rounded in gmem.
// MODE 0: plain store.  MODE 1: scatter into Q/K/V [B][H][S][hd].
// ---------------------------------------------------------------------------
#define TBM 128
#define TBN 128
#define TBK 32
#define ASTR 36          // A row stride: frag banks (4g+q) distinct
#define BSTR 136         // B row stride: frag banks (8q+g) distinct
#define STG  3
#define AS_FLOATS (TBM * ASTR)               // 4608
#define BS_FLOATS (TBK * BSTR)               // 4352
#define STAGE_FLOATS (AS_FLOATS + BS_FLOATS) // 8960
#define GEMM_SMEM (STG * STAGE_FLOATS * 4)   // 107520 B

__device__ __forceinline__ void frag_ld(uint32_t af[4][4], uint32_t bf[8][2],
                                        const float* __restrict__ as_p,
                                        const float* __restrict__ bs_p,
                                        int k8, int wm, int wn, int g, int q)
{
#pragma unroll
    for (int tm = 0; tm < 4; tm++) {
        const int rA = wm * 64 + tm * 16 + g;
        af[tm][0] = __float_as_uint(as_p[rA * ASTR + k8 + q]);
        af[tm][1] = __float_as_uint(as_p[(rA + 8) * ASTR + k8 + q]);
        af[tm][2] = __float_as_uint(as_p[rA * ASTR + k8 + q + 4]);
        af[tm][3] = __float_as_uint(as_p[(rA + 8) * ASTR + k8 + q + 4]);
    }
#pragma unroll
    for (int tn2 = 0; tn2 < 8; tn2++) {
        const int nB = wn * 64 + tn2 * 8 + g;
        bf[tn2][0] = __float_as_uint(bs_p[(k8 + q) * BSTR + nB]);
        bf[tn2][1] = __float_as_uint(bs_p[(k8 + q + 4) * BSTR + nB]);
    }
}

template <int MODE>
__global__ __launch_bounds__(128, 2)
void tf32_gemm_pipe(const float* __restrict__ A, const float* __restrict__ B,
                    float* __restrict__ C,
                    float* __restrict__ Cq, float* __restrict__ Ck,
                    float* __restrict__ Cv,
                    int N, int K)
{
    extern __shared__ float smem[];
    const uint32_t sb = (uint32_t)__cvta_generic_to_shared(smem);

    const int tid  = threadIdx.x;
    const int lane = tid & 31;
    const int wid  = tid >> 5;          // 0..3
    const int wm   = wid >> 1;          // 0..1  (M)
    const int wn   = wid & 1;           // 0..1  (N)
    const int g    = lane >> 2;         // 0..7
    const int q    = lane & 3;          // 0..3

    const int brow = blockIdx.y;
    const int bcol = blockIdx.x;
    const float* Ab = A + (size_t)brow * TBM * K;
    const float* Bb = B + bcol * TBN;

    const int T = K / TBK;

    // prefetch first STG-1 tiles: 1024 A-chunks + 1024 B-chunks, 8+8 per thread
#pragma unroll
    for (int p = 0; p < STG - 1; p++) {
        const uint32_t sa  = sb + (uint32_t)(p * STAGE_FLOATS) * 4u;
        const uint32_t sbb = sa + (uint32_t)AS_FLOATS * 4u;
        const int kt = p * TBK;
#pragma unroll
        for (int i = 0; i < 8; i++) {
            const int c  = tid + i * 128;
            const int arr = c >> 3, acf = (c & 7) << 2;
            const int brr = c >> 5, bcf = (c & 31) << 2;
            cp16(sa  + (uint32_t)(arr * ASTR + acf) * 4u, Ab + (size_t)arr * K + kt + acf);
            cp16(sbb + (uint32_t)(brr * BSTR + bcf) * 4u, Bb + (size_t)(kt + brr) * N + bcf);
        }
        asm volatile("cp.async.commit_group;");
    }

    float acc[4][8][4];
#pragma unroll
    for (int i = 0; i < 4; i++)
#pragma unroll
        for (int j = 0; j < 8; j++)
#pragma unroll
            for (int r = 0; r < 4; r++) acc[i][j][r] = 0.0f;

    uint32_t af[2][4][4], bf[2][8][2];   // double-buffered fragments

    int stage = 0;
    for (int t = 0; t < T; t++) {
        asm volatile("cp.async.wait_group %0;" :: "n"(STG - 2));
        __syncthreads();

        // issue loads for tile t+STG-1 into the stage freed at t-1
        {
            const int tn = t + STG - 1;
            if (tn < T) {
                int st = stage + (STG - 1);
                if (st >= STG) st -= STG;
                const uint32_t sa  = sb + (uint32_t)(st * STAGE_FLOATS) * 4u;
                const uint32_t sbb = sa + (uint32_t)AS_FLOATS * 4u;
                const int kt = tn * TBK;
#pragma unroll
                for (int i = 0; i < 8; i++) {
                    const int c  = tid + i * 128;
                    const int arr = c >> 3, acf = (c & 7) << 2;
                    const int brr = c >> 5, bcf = (c & 31) << 2;
                    cp16(sa  + (uint32_t)(arr * ASTR + acf) * 4u,
                         Ab + (size_t)arr * K + kt + acf);
                    cp16(sbb + (uint32_t)(brr * BSTR + bcf) * 4u,
                         Bb + (size_t)(kt + brr) * N + bcf);
                }
            }
            asm volatile("cp.async.commit_group;");
        }

        // compute tile t with manual fragment pipelining:
        // frag loads for step k8+1 are issued BEFORE the HMMAs of step k8.
        const float* as_p = smem + stage * STAGE_FLOATS;
        const float* bs_p = as_p + AS_FLOATS;

        frag_ld(af[0], bf[0], as_p, bs_p, 0, wm, wn, g, q);
#pragma unroll
        for (int k8i = 0; k8i < TBK / 8; k8i++) {
            const int cur = k8i & 1;
            const int nxt = cur ^ 1;
            if (k8i + 1 < TBK / 8)
                frag_ld(af[nxt], bf[nxt], as_p, bs_p, (k8i + 1) * 8, wm, wn, g, q);
#pragma unroll
            for (int tm = 0; tm < 4; tm++)
#pragma unroll
                for (int tn2 = 0; tn2 < 8; tn2++)
                    mma_tf32(acc[tm][tn2],
                             af[cur][tm][0], af[cur][tm][1],
                             af[cur][tm][2], af[cur][tm][3],
                             bf[cur][tn2][0], bf[cur][tn2][1]);
        }
        if (++stage == STG) stage = 0;
    }

    // ---------------- epilogue ----------------
    if (MODE == 0) {
#pragma unroll
        for (int tm = 0; tm < 4; tm++) {
            const int row = brow * TBM + wm * 64 + tm * 16 + g;
#pragma unroll
            for (int tn2 = 0; tn2 < 8; tn2++) {
                const int col = bcol * TBN + wn * 64 + tn2 * 8 + 2 * q;
                *(float2*)&C[(size_t)row * N + col] =
                    make_float2(acc[tm][tn2][0], acc[tm][tn2][1]);
                *(float2*)&C[(size_t)(row + 8) * N + col] =
                    make_float2(acc[tm][tn2][2], acc[tm][tn2][3]);
            }
        }
    } else {
        const int col0  = bcol * TBN;
        const int which = col0 >> 11;          // 0=q,1=k,2=v
        const int h     = (col0 & 2047) >> 7;  // head
        float* dst = (which == 0) ? Cq : ((which == 1) ? Ck : Cv);
#pragma unroll
        for (int tm = 0; tm < 4; tm++) {
            const int rowtok = brow * TBM + wm * 64 + tm * 16 + g;
            const int bb = rowtok >> 11;
            const int ss = rowtok & 2047;
            float* base0 = dst + (((size_t)(bb * NHEADS + h) * S_LEN) + ss) * HDIM;
            const int rt8 = rowtok + 8;
            const int bb8 = rt8 >> 11;
            const int ss8 = rt8 & 2047;
            float* base8 = dst + (((size_t)(bb8 * NHEADS + h) * S_LEN) + ss8) * HDIM;
#pragma unroll
            for (int tn2 = 0; tn2 < 8; tn2++) {
                const int colh = wn * 64 + tn2 * 8 + 2 * q;
                *(float2*)&base0[colh] = make_float2(acc[tm][tn2][0], acc[tm][tn2][1]);
                *(float2*)&base8[colh] = make_float2(acc[tm][tn2][2], acc[tm][tn2][3]);
            }
        }
    }
}

// ---------------------------------------------------------------------------
// RoPE (interleaved pairs), in place on Q and K; rounds Q,K,V to tf32 (rna).
// token_positions may be int64 or (JAX x64-disabled) int32; detect layout.
// ---------------------------------------------------------------------------
__global__ void rope_kernel(float* __restrict__ Xq, float* __restrict__ Xk,
                            float* __restrict__ Xv,
                            const int* __restrict__ pos32)
{
    const int r = blockIdx.x;
    const int s = r & (S_LEN - 1);
    const int j = threadIdx.x;

    const bool is64 = (pos32[1] == 0);
    const int  p    = is64 ? pos32[2 * s] : pos32[s];

    float inv = powf(10000.0f, -(float)(2 * j) * (1.0f / 128.0f));
    float ang = (float)p * inv;
    float sn, cs;
    sincosf(ang, &sn, &cs);

    float* qp = Xq + r * HDIM + 2 * j;
    float x1 = qp[0], x2 = qp[1];
    qp[0] = f2tf(x1 * cs - x2 * sn);
    qp[1] = f2tf(x1 * sn + x2 * cs);

    float* kp = Xk + r * HDIM + 2 * j;
    x1 = kp[0]; x2 = kp[1];
    kp[0] = f2tf(x1 * cs - x2 * sn);
    kp[1] = f2tf(x1 * sn + x2 * cs);

    float* vp = Xv + r * HDIM;
    vp[j]      = f2tf(vp[j]);
    vp[j + 64] = f2tf(vp[j + 64]);
}

// ---------------------------------------------------------------------------
// Flash attention, tf32 HMMA (passing version; epilogue rounds g_attn to tf32).
// ---------------------------------------------------------------------------
#define FQ   128
#define FKT  64
#define QS   132
#define KS2  132
#define VS2  136
#define SMF_K0 (FQ * QS)
#define SMF_V0 (FQ * QS + 2 * FKT * KS2)
#define FLASH2_SMEM_BYTES ((FQ * QS + 2 * FKT * KS2 + 2 * FKT * VS2) * 4)

__global__ __launch_bounds__(256, 1)
void flash_tc(const float* __restrict__ Q, const float* __restrict__ K,
              const float* __restrict__ V, float* __restrict__ O)
{
    extern __shared__ float sm[];
    const int tid  = threadIdx.x;
    const int lane = tid & 31;
    const int w    = tid >> 5;
    const int g    = lane >> 2;
    const int q    = lane & 3;

    const int qb = blockIdx.x;
    const int h  = blockIdx.y;
    const int b  = blockIdx.z;

    const float* Qg = Q + (((size_t)(b * NHEADS + h)) * S_LEN + (size_t)qb * FQ) * HDIM;
    const float* Kg = K + ((size_t)(b * NHEADS + h)) * S_LEN * HDIM;
    const float* Vg = V + ((size_t)(b * NHEADS + h)) * S_LEN * HDIM;

    const uint32_t sb = (uint32_t)__cvta_generic_to_shared(sm);

#pragma unroll
    for (int i = 0; i < 16; i++) {
        int id  = i * 256 + tid;
        int row = id >> 5, c = (id & 31) << 2;
        cp16(sb + (uint32_t)(row * QS + c) * 4u, Qg + row * HDIM + c);
    }
#pragma unroll
    for (int i = 0; i < 8; i++) {
        int id  = i * 256 + tid;
        int row = id >> 5, c = (id & 31) << 2;
        cp16(sb + (uint32_t)(SMF_K0 + row * KS2 + c) * 4u, Kg + row * HDIM + c);
        cp16(sb + (uint32_t)(SMF_V0 + row * VS2 + c) * 4u, Vg + row * HDIM + c);
    }
    asm volatile("cp.async.commit_group;");

    float m0 = -1e30f, m1 = -1e30f, l0 = 0.0f, l1 = 0.0f;
    float acc[16][4];
#pragma unroll
    for (int nf = 0; nf < 16; nf++)
#pragma unroll
        for (int c = 0; c < 4; c++) acc[nf][c] = 0.0f;

    const float SC = 0.088388347648318447f;
    const int ntiles = 2 * qb + 2;
    const int r0 = qb * FQ + w * 16 + g;
    const int r1 = r0 + 8;

    for (int kt = 0; kt < ntiles; kt++) {
        asm volatile("cp.async.wait_group 0;");
        __syncthreads();

        if (kt + 1 < ntiles) {
            const int nbuf = (kt + 1) & 1;
            const float* Ks = Kg + (size_t)(kt + 1) * FKT * HDIM;
            const float* Vs = Vg + (size_t)(kt + 1) * FKT * HDIM;
#pragma unroll
            for (int i = 0; i < 8; i++) {
                int id  = i * 256 + tid;
                int row = id >> 5, c = (id & 31) << 2;
                cp16(sb + (uint32_t)(SMF_K0 + nbuf * FKT * KS2 + row * KS2 + c) * 4u,
                     Ks + row * HDIM + c);
                cp16(sb + (uint32_t)(SMF_V0 + nbuf * FKT * VS2 + row * VS2 + c) * 4u,
                     Vs + row * HDIM + c);
            }
            asm volatile("cp.async.commit_group;");
        }

        if (kt * FKT <= qb * FQ + w * 16 + 15) {
            const float* sq = sm;
            const float* sk = sm + SMF_K0 + (kt & 1) * FKT * KS2;
            const float* sv = sm + SMF_V0 + (kt & 1) * FKT * VS2;

            float sc[8][4];
#pragma unroll
            for (int nf = 0; nf < 8; nf++)
#pragma unroll
                for (int c = 0; c < 4; c++) sc[nf][c] = 0.0f;

#pragma unroll
            for (int k8 = 0; k8 < 16; k8++) {
                const int kc = k8 * 8;
                uint32_t a0 = __float_as_uint(sq[(w * 16 + g)     * QS + kc + q]);
                uint32_t a1 = __float_as_uint(sq[(w * 16 + g + 8) * QS + kc + q]);
                uint32_t a2 = __float_as_uint(sq[(w * 16 + g)     * QS + kc + q + 4]);
                uint32_t a3 = __float_as_uint(sq[(w * 16 + g + 8) * QS + kc + q + 4]);
#pragma unroll
                for (int nf = 0; nf < 8; nf++) {
                    uint32_t b0 = __float_as_uint(sk[(nf * 8 + g) * KS2 + kc + q]);
                    uint32_t b1 = __float_as_uint(sk[(nf * 8 + g) * KS2 + kc + q + 4]);
                    mma_tf32(sc[nf], a0, a1, a2, a3, b0, b1);
                }
            }

            if (kt * FKT + FKT - 1 > r0) {
#pragma unroll
                for (int nf = 0; nf < 8; nf++) {
#pragma unroll
                    for (int cb = 0; cb < 2; cb++) {
                        int kcol = kt * FKT + nf * 8 + 2 * q + cb;
                        if (kcol > r0) sc[nf][cb]     = -1e30f;
                        if (kcol > r1) sc[nf][2 + cb] = -1e30f;
                    }
                }
            }

            float mx0 = -1e30f, mx1 = -1e30f;
#pragma unroll
            for (int nf = 0; nf < 8; nf++) {
                mx0 = fmaxf(mx0, fmaxf(sc[nf][0], sc[nf][1]));
                mx1 = fmaxf(mx1, fmaxf(sc[nf][2], sc[nf][3]));
            }
            mx0 = fmaxf(mx0, __shfl_xor_sync(0xffffffffu, mx0, 1));
            mx0 = fmaxf(mx0, __shfl_xor_sync(0xffffffffu, mx0, 2));
            mx1 = fmaxf(mx1, __shfl_xor_sync(0xffffffffu, mx1, 1));
            mx1 = fmaxf(mx1, __shfl_xor_sync(0xffffffffu, mx1, 2));

            float mn0 = fmaxf(m0, mx0), mn1 = fmaxf(m1, mx1);
            float al0 = __expf(SC * (m0 - mn0));
            float al1 = __expf(SC * (m1 - mn1));
            m0 = mn0; m1 = mn1;

            float rs0 = 0.0f, rs1 = 0.0f;
#pragma unroll
            for (int nf = 0; nf < 8; nf++) {
                float p0 = f2tf(__expf(SC * (sc[nf][0] - m0)));
                float p1 = f2tf(__expf(SC * (sc[nf][1] - m0)));
                float p2 = f2tf(__expf(SC * (sc[nf][2] - m1)));
                float p3 = f2tf(__expf(SC * (sc[nf][3] - m1)));
                sc[nf][0] = p0; sc[nf][1] = p1; sc[nf][2] = p2; sc[nf][3] = p3;
                rs0 += p0 + p1;
                rs1 += p2 + p3;
            }
            rs0 += __shfl_xor_sync(0xffffffffu, rs0, 1);
            rs0 += __shfl_xor_sync(0xffffffffu, rs0, 2);
            rs1 += __shfl_xor_sync(0xffffffffu, rs1, 1);
            rs1 += __shfl_xor_sync(0xffffffffu, rs1, 2);
            l0 = l0 * al0 + rs0;
            l1 = l1 * al1 + rs1;

#pragma unroll
            for (int nf = 0; nf < 16; nf++) {
                acc[nf][0] *= al0; acc[nf][1] *= al0;
                acc[nf][2] *= al1; acc[nf][3] *= al1;
            }

#pragma unroll
            for (int j = 0; j < 8; j++) {
                const int s0 = (q >> 1);
                const int s1 = 2 + (q >> 1);
                float v00 = __shfl_sync(0xffffffffu, sc[j][0], s0, 4);
                float v01 = __shfl_sync(0xffffffffu, sc[j][1], s0, 4);
                float v10 = __shfl_sync(0xffffffffu, sc[j][2], s0, 4);
                float v11 = __shfl_sync(0xffffffffu, sc[j][3], s0, 4);
                uint32_t a0 = __float_as_uint((q & 1) ? v01 : v00);
                uint32_t a1 = __float_as_uint((q & 1) ? v11 : v10);
                v00 = __shfl_sync(0xffffffffu, sc[j][0], s1, 4);
                v01 = __shfl_sync(0xffffffffu, sc[j][1], s1, 4);
                v10 = __shfl_sync(0xffffffffu, sc[j][2], s1, 4);
                v11 = __shfl_sync(0xffffffffu, sc[j][3], s1, 4);
                uint32_t a2 = __float_as_uint((q & 1) ? v01 : v00);
                uint32_t a3 = __float_as_uint((q & 1) ? v11 : v10);
#pragma unroll
                for (int nf = 0; nf < 16; nf++) {
                    uint32_t b0 = __float_as_uint(sv[(j * 8 + q)     * VS2 + nf * 8 + g]);
                    uint32_t b1 = __float_as_uint(sv[(j * 8 + q + 4) * VS2 + nf * 8 + g]);
                    mma_tf32(acc[nf], a0, a1, a2, a3, b0, b1);
                }
            }
        }
    }

    // epilogue: normalize + tf32-round (GEMM2 inputs pre-rounded)
    const float inv0 = 1.0f / l0;
    const float inv1 = 1.0f / l1;
    float* o0 = O + ((size_t)(b * S_LEN + r0)) * D_MODEL + h * HDIM;
    float* o1 = o0 + (size_t)8 * D_MODEL;
#pragma unroll
    for (int nf = 0; nf < 16; nf++) {
        const int col = nf * 8 + 2 * q;
        *(float2*)&o0[col] = make_float2(f2tf(acc[nf][0] * inv0), f2tf(acc[nf][1] * inv0));
        *(float2*)&o1[col] = make_float2(f2tf(acc[nf][2] * inv1), f2tf(acc[nf][3] * inv1));
    }
}

// ---------------------------------------------------------------------------
// Launch
// ---------------------------------------------------------------------------
extern "C" void kernel_launch(void* const* d_in, const int* in_sizes, int n_in,
                              void* d_out, int out_size)
{
    const float* x     = (const float*)d_in[0];
    const int*   pos32 = (const int*)d_in[1];
    const float* w_qkv = (const float*)d_in[2];
    const float* w_o   = (const float*)d_in[3];
    float* out         = (float*)d_out;

    float *q, *k, *v, *attn, *xtf, *wqkv, *wo;
    cudaGetSymbolAddress((void**)&q,    g_q);
    cudaGetSymbolAddress((void**)&k,    g_k);
    cudaGetSymbolAddress((void**)&v,    g_v);
    cudaGetSymbolAddress((void**)&attn, g_attn);
    cudaGetSymbolAddress((void**)&xtf,  g_xtf);
    cudaGetSymbolAddress((void**)&wqkv, g_wqkv);
    cudaGetSymbolAddress((void**)&wo,   g_wo);

    cudaFuncSetAttribute(tf32_gemm_pipe<1>,
                         cudaFuncAttributeMaxDynamicSharedMemorySize, GEMM_SMEM);
    cudaFuncSetAttribute(tf32_gemm_pipe<0>,
                         cudaFuncAttributeMaxDynamicSharedMemorySize, GEMM_SMEM);
    cudaFuncSetAttribute(flash_tc,
                         cudaFuncAttributeMaxDynamicSharedMemorySize,
                         FLASH2_SMEM_BYTES);

    // 0) pre-round inputs to tf32 (rna) -- unbiased, idempotent
    {
        const int nx = NTOK * D_MODEL / 4;
        const int nq = D_MODEL * QKV_N / 4;
        const int nw = D_MODEL * D_MODEL / 4;
        tf32_round_kernel<<<nx / 256, 256>>>((const float4*)x,     (float4*)xtf,  nx);
        tf32_round_kernel<<<nq / 256, 256>>>((const float4*)w_qkv, (float4*)wqkv, nq);
        tf32_round_kernel<<<nw / 256, 256>>>((const float4*)w_o,   (float4*)wo,   nw);
    }

    // 1) QKV projection (tf32 HMMA, manual fragment pipelining)
    tf32_gemm_pipe<1><<<dim3(QKV_N / TBN, NTOK / TBM), 128, GEMM_SMEM>>>(
        xtf, wqkv, nullptr, q, k, v, QKV_N, D_MODEL);

    // 2) RoPE on Q and K (in place) + tf32 rounding of Q,K,V
    rope_kernel<<<BATCH * NHEADS * S_LEN, 64>>>(q, k, v, pos32);

    // 3) causal flash attention (tf32 HMMA)
    flash_tc<<<dim3(S_LEN / FQ, NHEADS, BATCH), 256, FLASH2_SMEM_BYTES>>>(
        q, k, v, attn);

    // 4) output projection (tf32 HMMA, manual fragment pipelining)
    tf32_gemm_pipe<0><<<dim3(D_MODEL / TBN, NTOK / TBM), 128, GEMM_SMEM>>>(
        attn, wo, out, nullptr, nullptr, nullptr, D_MODEL, D_MODEL);
}

// round 12
// speedup vs baseline: 7.7137x; 1.8237x over previous
#include <cuda_runtime.h>
#include <cuda_fp16.h>
#include <math.h>
#include <stdint.h>

// ---------------------------------------------------------------------------
// Problem constants
// ---------------------------------------------------------------------------
#define S_LEN   2048
#define D_MODEL 2048
#define NHEADS  16
#define HDIM    128
#define BATCH   2
#define NTOK    (BATCH * S_LEN)   // 4096
#define QKV_N   (3 * D_MODEL)     // 6144
#define BH      (BATCH * NHEADS)  // 32

// ---------------------------------------------------------------------------
// Scratch (device globals -- no allocation allowed in kernel_launch)
// ---------------------------------------------------------------------------
__device__ float    g_q[BH * S_LEN * HDIM];          // f32 QKV-out / rope-in
__device__ float    g_k[BH * S_LEN * HDIM];
__device__ float    g_v[BH * S_LEN * HDIM];
__device__ uint32_t g_xh[NTOK * D_MODEL / 2];        // x as fp16 pairs
__device__ uint32_t g_wqkvh[(D_MODEL / 2) * QKV_N];  // w_qkv packed [K/2][N]
__device__ uint32_t g_woh[(D_MODEL / 2) * D_MODEL];  // w_o packed [K/2][N]
__device__ uint32_t g_qh[BH * S_LEN * HDIM / 2];     // Q fp16 [row][64] words
__device__ uint32_t g_kh[BH * S_LEN * HDIM / 2];     // K fp16 [row][64] words
__device__ uint32_t g_vh[BH * (S_LEN / 2) * HDIM];   // V packed [s/2][128] words
__device__ uint32_t g_attnh[NTOK * D_MODEL / 2];     // attn out fp16 pairs

// ---------------------------------------------------------------------------
// helpers
// ---------------------------------------------------------------------------
__device__ __forceinline__ void mma_f16(float c[4],
                                        uint32_t a0, uint32_t a1,
                                        uint32_t a2, uint32_t a3,
                                        uint32_t b0, uint32_t b1) {
    asm volatile(
        "mma.sync.aligned.m16n8k16.row.col.f32.f16.f16.f32 "
        "{%0,%1,%2,%3}, {%4,%5,%6,%7}, {%8,%9}, {%0,%1,%2,%3};"
        : "+f"(c[0]), "+f"(c[1]), "+f"(c[2]), "+f"(c[3])
        : "r"(a0), "r"(a1), "r"(a2), "r"(a3), "r"(b0), "r"(b1));
}
__device__ __forceinline__ void cp16(uint32_t dst, const void* src) {
    asm volatile("cp.async.cg.shared.global [%0], [%1], 16;"
                 :: "r"(dst), "l"(src));
}
__device__ __forceinline__ uint32_t packh2(float a, float b) {
    __half2 h = __floats2half2_rn(a, b);
    return *(uint32_t*)&h;
}

// ---------------------------------------------------------------------------
// Prep: x -> fp16 pairs (natural row-major)
// ---------------------------------------------------------------------------
__global__ void f32_to_h16(const float4* __restrict__ in,
                           uint32_t* __restrict__ out, int n4)
{
    int i = blockIdx.x * blockDim.x + threadIdx.x;
    if (i < n4) {
        float4 v = in[i];
        out[2 * i + 0] = packh2(v.x, v.y);
        out[2 * i + 1] = packh2(v.z, v.w);
    }
}

// Prep: weight [K][N] f32 -> packed fp16 pairs [K/2][N]
__global__ void pack_w16(const float* __restrict__ in,
                         uint32_t* __restrict__ out, int N)
{
    const int n  = blockIdx.x * blockDim.x + threadIdx.x;
    const int kk = blockIdx.y;
    out[(size_t)kk * N + n] =
        packh2(in[(size_t)(2 * kk) * N + n], in[(size_t)(2 * kk + 1) * N + n]);
}

// ---------------------------------------------------------------------------
// fp16 HMMA GEMM (m16n8k16), cp.async 3-stage, BK=64.
// A: fp16 pairs row-major [M][K/2] words.  B: packed [K/2][N] words.
// 128 threads, 4 warps (2x2) of 64x64, manual fragment double-buffer.
// MODE 0: plain f32 store.  MODE 1: scatter f32 into Q/K/V [B][H][S][hd].
// ---------------------------------------------------------------------------
#define TBM 128
#define TBN 128
#define TBKW 32          // 64 k-elements = 32 pair-words
#define ASTR 36          // A row stride (words): frag banks (4g+q) distinct
#define BSTR 136         // B row stride (words): frag banks (8q+g) distinct
#define STG  3
#define AS_W (TBM * ASTR)            // 4608
#define BS_W (TBKW * BSTR)           // 4352
#define STAGE_W (AS_W + BS_W)        // 8960
#define GEMM_SMEM (STG * STAGE_W * 4)  // 107520 B

__device__ __forceinline__ void frag_ld_h(uint32_t af[4][4], uint32_t bf[8][2],
                                          const uint32_t* __restrict__ as_p,
                                          const uint32_t* __restrict__ bs_p,
                                          int kw, int wm, int wn, int g, int q)
{
#pragma unroll
    for (int tm = 0; tm < 4; tm++) {
        const int rA = wm * 64 + tm * 16 + g;
        af[tm][0] = as_p[rA * ASTR + kw + q];
        af[tm][1] = as_p[(rA + 8) * ASTR + kw + q];
        af[tm][2] = as_p[rA * ASTR + kw + q + 4];
        af[tm][3] = as_p[(rA + 8) * ASTR + kw + q + 4];
    }
#pragma unroll
    for (int tn = 0; tn < 8; tn++) {
        const int nB = wn * 64 + tn * 8 + g;
        bf[tn][0] = bs_p[(kw + q) * BSTR + nB];
        bf[tn][1] = bs_p[(kw + q + 4) * BSTR + nB];
    }
}

template <int MODE>
__global__ __launch_bounds__(128, 2)
void h16_gemm(const uint32_t* __restrict__ A, const uint32_t* __restrict__ B,
              float* __restrict__ C,
              float* __restrict__ Cq, float* __restrict__ Ck,
              float* __restrict__ Cv,
              int N, int K)
{
    extern __shared__ uint32_t smw[];
    const uint32_t sb = (uint32_t)__cvta_generic_to_shared(smw);

    const int tid  = threadIdx.x;
    const int lane = tid & 31;
    const int wid  = tid >> 5;
    const int wm   = wid >> 1;
    const int wn   = wid & 1;
    const int g    = lane >> 2;
    const int q    = lane & 3;

    const int brow = blockIdx.y;
    const int bcol = blockIdx.x;
    const int Kw   = K >> 1;
    const uint32_t* Ab = A + (size_t)brow * TBM * Kw;
    const uint32_t* Bb = B + bcol * TBN;

    const int T = K / 64;

    // prefetch first STG-1 tiles: 1024 A-chunks + 1024 B-chunks, 8+8/thread
#pragma unroll
    for (int p = 0; p < STG - 1; p++) {
        const uint32_t sa  = sb + (uint32_t)(p * STAGE_W) * 4u;
        const uint32_t sbb = sa + (uint32_t)AS_W * 4u;
        const int ktw = p * TBKW;
#pragma unroll
        for (int i = 0; i < 8; i++) {
            const int c   = tid + i * 128;
            const int arr = c >> 3, acw = (c & 7) << 2;
            const int brr = c >> 5, bcw = (c & 31) << 2;
            cp16(sa  + (uint32_t)(arr * ASTR + acw) * 4u,
                 Ab + (size_t)arr * Kw + ktw + acw);
            cp16(sbb + (uint32_t)(brr * BSTR + bcw) * 4u,
                 Bb + (size_t)(ktw + brr) * N + bcw);
        }
        asm volatile("cp.async.commit_group;");
    }

    float acc[4][8][4];
#pragma unroll
    for (int i = 0; i < 4; i++)
#pragma unroll
        for (int j = 0; j < 8; j++)
#pragma unroll
            for (int r = 0; r < 4; r++) acc[i][j][r] = 0.0f;

    uint32_t af[2][4][4], bf[2][8][2];

    int stage = 0;
    for (int t = 0; t < T; t++) {
        asm volatile("cp.async.wait_group %0;" :: "n"(STG - 2));
        __syncthreads();

        {
            const int tn = t + STG - 1;
            if (tn < T) {
                int st = stage + (STG - 1);
                if (st >= STG) st -= STG;
                const uint32_t sa  = sb + (uint32_t)(st * STAGE_W) * 4u;
                const uint32_t sbb = sa + (uint32_t)AS_W * 4u;
                const int ktw = tn * TBKW;
#pragma unroll
                for (int i = 0; i < 8; i++) {
                    const int c   = tid + i * 128;
                    const int arr = c >> 3, acw = (c & 7) << 2;
                    const int brr = c >> 5, bcw = (c & 31) << 2;
                    cp16(sa  + (uint32_t)(arr * ASTR + acw) * 4u,
                         Ab + (size_t)arr * Kw + ktw + acw);
                    cp16(sbb + (uint32_t)(brr * BSTR + bcw) * 4u,
                         Bb + (size_t)(ktw + brr) * N + bcw);
                }
            }
            asm volatile("cp.async.commit_group;");
        }

        const uint32_t* as_p = smw + stage * STAGE_W;
        const uint32_t* bs_p = as_p + AS_W;

        frag_ld_h(af[0], bf[0], as_p, bs_p, 0, wm, wn, g, q);
#pragma unroll
        for (int s = 0; s < 4; s++) {             // 4 k16 steps (kw = 8s)
            const int cur = s & 1;
            const int nxt = cur ^ 1;
            if (s + 1 < 4)
                frag_ld_h(af[nxt], bf[nxt], as_p, bs_p, (s + 1) * 8, wm, wn, g, q);
#pragma unroll
            for (int tm = 0; tm < 4; tm++)
#pragma unroll
                for (int tn2 = 0; tn2 < 8; tn2++)
                    mma_f16(acc[tm][tn2],
                            af[cur][tm][0], af[cur][tm][1],
                            af[cur][tm][2], af[cur][tm][3],
                            bf[cur][tn2][0], bf[cur][tn2][1]);
        }
        if (++stage == STG) stage = 0;
    }

    // ---------------- epilogue (f32) ----------------
    if (MODE == 0) {
#pragma unroll
        for (int tm = 0; tm < 4; tm++) {
            const int row = brow * TBM + wm * 64 + tm * 16 + g;
#pragma unroll
            for (int tn2 = 0; tn2 < 8; tn2++) {
                const int col = bcol * TBN + wn * 64 + tn2 * 8 + 2 * q;
                *(float2*)&C[(size_t)row * N + col] =
                    make_float2(acc[tm][tn2][0], acc[tm][tn2][1]);
                *(float2*)&C[(size_t)(row + 8) * N + col] =
                    make_float2(acc[tm][tn2][2], acc[tm][tn2][3]);
            }
        }
    } else {
        const int col0  = bcol * TBN;
        const int which = col0 >> 11;
        const int h     = (col0 & 2047) >> 7;
        float* dst = (which == 0) ? Cq : ((which == 1) ? Ck : Cv);
#pragma unroll
        for (int tm = 0; tm < 4; tm++) {
            const int rowtok = brow * TBM + wm * 64 + tm * 16 + g;
            const int bb = rowtok >> 11;
            const int ss = rowtok & 2047;
            float* base0 = dst + (((size_t)(bb * NHEADS + h) * S_LEN) + ss) * HDIM;
            const int rt8 = rowtok + 8;
            const int bb8 = rt8 >> 11;
            const int ss8 = rt8 & 2047;
            float* base8 = dst + (((size_t)(bb8 * NHEADS + h) * S_LEN) + ss8) * HDIM;
#pragma unroll
            for (int tn2 = 0; tn2 < 8; tn2++) {
                const int colh = wn * 64 + tn2 * 8 + 2 * q;
                *(float2*)&base0[colh] = make_float2(acc[tm][tn2][0], acc[tm][tn2][1]);
                *(float2*)&base8[colh] = make_float2(acc[tm][tn2][2], acc[tm][tn2][3]);
            }
        }
    }
}

// ---------------------------------------------------------------------------
// RoPE + fp16 conversion.  One block per PAIR of rows (s0=2*s2, s1=s0+1),
// 128 threads.  Writes Q,K natural fp16 pair-words and V packed kv-pair words.
// token_positions may be int64 or int32 (JAX x64-off); detect layout.
// ---------------------------------------------------------------------------
__global__ void rope_pack_kernel(const float* __restrict__ Q,
                                 const float* __restrict__ Kk,
                                 const float* __restrict__ V,
                                 uint32_t* __restrict__ Qh,
                                 uint32_t* __restrict__ Kh,
                                 uint32_t* __restrict__ Vp,
                                 const int* __restrict__ pos32)
{
    const int r2  = blockIdx.x;                 // bh*(S/2) + s2
    const int bh  = r2 / (S_LEN / 2);
    const int s2  = r2 - bh * (S_LEN / 2);
    const int t   = threadIdx.x;

    const bool is64 = (pos32[1] == 0);

    // rope: threads 0..63 -> row s0, 64..127 -> row s1; j = pair index
    {
        const int rr  = 2 * s2 + (t >> 6);
        const int j   = t & 63;
        const int p   = is64 ? pos32[2 * rr] : pos32[rr];
        const int row = bh * S_LEN + rr;

        float inv = powf(10000.0f, -(float)(2 * j) * (1.0f / 128.0f));
        float ang = (float)p * inv;
        float sn, cs;
        sincosf(ang, &sn, &cs);

        const float* qp = Q + (size_t)row * HDIM + 2 * j;
        float x1 = qp[0], x2 = qp[1];
        Qh[(size_t)row * 64 + j] = packh2(x1 * cs - x2 * sn, x1 * sn + x2 * cs);

        const float* kp = Kk + (size_t)row * HDIM + 2 * j;
        x1 = kp[0]; x2 = kp[1];
        Kh[(size_t)row * 64 + j] = packh2(x1 * cs - x2 * sn, x1 * sn + x2 * cs);
    }

    // V pack: word(s2, d) = half2(V[2s2, d], V[2s2+1, d]), d = t (0..127)
    {
        const size_t base = (size_t)(bh * S_LEN + 2 * s2) * HDIM;
        Vp[((size_t)bh * (S_LEN / 2) + s2) * HDIM + t] =
            packh2(V[base + t], V[base + HDIM + t]);
    }
}

// ---------------------------------------------------------------------------
// Flash attention, fp16 HMMA (m16n8k16), causal, online softmax.
// Block: 128 q-rows, 8 warps x 16 rows, 256 threads.  K/V tiles of 64 keys,
// cp.async double-buffered.  P C-frag == A-frag for fp16 -> NO shuffles.
// Output: fp16 pair-words (GEMM2 A input).
// ---------------------------------------------------------------------------
#define FQ   128
#define FKT  64
#define QSH  68     // Q/K row stride (words): banks 4g+q conflict-free
#define VSH  136    // V row stride (words): banks 8q+g conflict-free
#define SW_K0 (FQ * QSH)                 // 8704
#define SW_V0 (SW_K0 + 2 * FKT * QSH)    // 8704 + 8704
#define FLASH_H_SMEM ((SW_V0 + 2 * (FKT / 2) * VSH) * 4)   // 104448 B

__global__ __launch_bounds__(256, 1)
void flash_h16(const uint32_t* __restrict__ Qh, const uint32_t* __restrict__ Kh,
               const uint32_t* __restrict__ Vp, uint32_t* __restrict__ Oh)
{
    extern __shared__ uint32_t smw[];
    const int tid  = threadIdx.x;
    const int lane = tid & 31;
    const int w    = tid >> 5;
    const int g    = lane >> 2;
    const int q    = lane & 3;

    const int qb = blockIdx.x;
    const int h  = blockIdx.y;
    const int b  = blockIdx.z;
    const int bh = b * NHEADS + h;

    const uint32_t* Qg = Qh + ((size_t)bh * S_LEN + (size_t)qb * FQ) * 64;
    const uint32_t* Kg = Kh + (size_t)bh * S_LEN * 64;
    const uint32_t* Vg = Vp + (size_t)bh * (S_LEN / 2) * HDIM;

    const uint32_t sb = (uint32_t)__cvta_generic_to_shared(smw);

    // Q tile: 128 rows x 64 words -> 2048 chunks, 8/thread
#pragma unroll
    for (int i = 0; i < 8; i++) {
        int c   = i * 256 + tid;
        int row = c >> 4, cw = (c & 15) << 2;
        cp16(sb + (uint32_t)(row * QSH + cw) * 4u, Qg + (size_t)row * 64 + cw);
    }
    // K tile 0: 64 x 64 words -> 1024 chunks, 4/thread.  V tile 0: 32 x 128.
#pragma unroll
    for (int i = 0; i < 4; i++) {
        int c = i * 256 + tid;
        {
            int row = c >> 4, cw = (c & 15) << 2;
            cp16(sb + (uint32_t)(SW_K0 + row * QSH + cw) * 4u,
                 Kg + (size_t)row * 64 + cw);
        }
        {
            int row = c >> 5, cw = (c & 31) << 2;
            cp16(sb + (uint32_t)(SW_V0 + row * VSH + cw) * 4u,
                 Vg + (size_t)row * HDIM + cw);
        }
    }
    asm volatile("cp.async.commit_group;");

    float m0 = -1e30f, m1 = -1e30f, l0 = 0.0f, l1 = 0.0f;
    float acc[16][4];
#pragma unroll
    for (int nf = 0; nf < 16; nf++)
#pragma unroll
        for (int c = 0; c < 4; c++) acc[nf][c] = 0.0f;

    const float SC = 0.088388347648318447f;   // 1/sqrt(128)
    const int ntiles = 2 * qb + 2;
    const int r0 = qb * FQ + w * 16 + g;
    const int r1 = r0 + 8;

    for (int kt = 0; kt < ntiles; kt++) {
        asm volatile("cp.async.wait_group 0;");
        __syncthreads();

        if (kt + 1 < ntiles) {
            const int nb = (kt + 1) & 1;
            const uint32_t* Ks = Kg + (size_t)(kt + 1) * FKT * 64;
            const uint32_t* Vs = Vg + (size_t)(kt + 1) * (FKT / 2) * HDIM;
#pragma unroll
            for (int i = 0; i < 4; i++) {
                int c = i * 256 + tid;
                {
                    int row = c >> 4, cw = (c & 15) << 2;
                    cp16(sb + (uint32_t)(SW_K0 + nb * FKT * QSH + row * QSH + cw) * 4u,
                         Ks + (size_t)row * 64 + cw);
                }
                {
                    int row = c >> 5, cw = (c & 31) << 2;
                    cp16(sb + (uint32_t)(SW_V0 + nb * (FKT / 2) * VSH + row * VSH + cw) * 4u,
                         Vs + (size_t)row * HDIM + cw);
                }
            }
            asm volatile("cp.async.commit_group;");
        }

        if (kt * FKT <= qb * FQ + w * 16 + 15) {
            const uint32_t* sq = smw;
            const uint32_t* sk = smw + SW_K0 + (kt & 1) * FKT * QSH;
            const uint32_t* sv = smw + SW_V0 + (kt & 1) * (FKT / 2) * VSH;

            // ---- S = Q K^T : 8 d-steps (k16) x 8 n-frags ----
            float sc[8][4];
#pragma unroll
            for (int nf = 0; nf < 8; nf++)
#pragma unroll
                for (int c = 0; c < 4; c++) sc[nf][c] = 0.0f;

#pragma unroll
            for (int ds = 0; ds < 8; ds++) {
                const int kw = ds * 8;
                uint32_t a0 = sq[(w * 16 + g) * QSH + kw + q];
                uint32_t a1 = sq[(w * 16 + g + 8) * QSH + kw + q];
                uint32_t a2 = sq[(w * 16 + g) * QSH + kw + q + 4];
                uint32_t a3 = sq[(w * 16 + g + 8) * QSH + kw + q + 4];
#pragma unroll
                for (int nf = 0; nf < 8; nf++) {
                    uint32_t b0 = sk[(nf * 8 + g) * QSH + kw + q];
                    uint32_t b1 = sk[(nf * 8 + g) * QSH + kw + q + 4];
                    mma_f16(sc[nf], a0, a1, a2, a3, b0, b1);
                }
            }

            // ---- causal mask ----
            if (kt * FKT + FKT - 1 > r0) {
#pragma unroll
                for (int nf = 0; nf < 8; nf++) {
#pragma unroll
                    for (int cb = 0; cb < 2; cb++) {
                        int kcol = kt * FKT + nf * 8 + 2 * q + cb;
                        if (kcol > r0) sc[nf][cb]     = -1e30f;
                        if (kcol > r1) sc[nf][2 + cb] = -1e30f;
                    }
                }
            }

            // ---- online softmax (quad-local) ----
            float mx0 = -1e30f, mx1 = -1e30f;
#pragma unroll
            for (int nf = 0; nf < 8; nf++) {
                mx0 = fmaxf(mx0, fmaxf(sc[nf][0], sc[nf][1]));
                mx1 = fmaxf(mx1, fmaxf(sc[nf][2], sc[nf][3]));
            }
            mx0 = fmaxf(mx0, __shfl_xor_sync(0xffffffffu, mx0, 1));
            mx0 = fmaxf(mx0, __shfl_xor_sync(0xffffffffu, mx0, 2));
            mx1 = fmaxf(mx1, __shfl_xor_sync(0xffffffffu, mx1, 1));
            mx1 = fmaxf(mx1, __shfl_xor_sync(0xffffffffu, mx1, 2));

            float mn0 = fmaxf(m0, mx0), mn1 = fmaxf(m1, mx1);
            float al0 = __expf(SC * (m0 - mn0));
            float al1 = __expf(SC * (m1 - mn1));
            m0 = mn0; m1 = mn1;

            float rs0 = 0.0f, rs1 = 0.0f;
#pragma unroll
            for (int nf = 0; nf < 8; nf++) {
                float p0 = __half2float(__float2half_rn(__expf(SC * (sc[nf][0] - m0))));
                float p1 = __half2float(__float2half_rn(__expf(SC * (sc[nf][1] - m0))));
                float p2 = __half2float(__float2half_rn(__expf(SC * (sc[nf][2] - m1))));
                float p3 = __half2float(__float2half_rn(__expf(SC * (sc[nf][3] - m1))));
                sc[nf][0] = p0; sc[nf][1] = p1; sc[nf][2] = p2; sc[nf][3] = p3;
                rs0 += p0 + p1;
                rs1 += p2 + p3;
            }
            rs0 += __shfl_xor_sync(0xffffffffu, rs0, 1);
            rs0 += __shfl_xor_sync(0xffffffffu, rs0, 2);
            rs1 += __shfl_xor_sync(0xffffffffu, rs1, 1);
            rs1 += __shfl_xor_sync(0xffffffffu, rs1, 2);
            l0 = l0 * al0 + rs0;
            l1 = l1 * al1 + rs1;

#pragma unroll
            for (int nf = 0; nf < 16; nf++) {
                acc[nf][0] *= al0; acc[nf][1] *= al0;
                acc[nf][2] *= al1; acc[nf][3] *= al1;
            }

            // ---- O += P V : P C-frag == fp16 A-frag (no shuffles) ----
#pragma unroll
            for (int j = 0; j < 4; j++) {          // kv16 steps
                uint32_t pa0 = packh2(sc[2 * j][0],     sc[2 * j][1]);
                uint32_t pa1 = packh2(sc[2 * j][2],     sc[2 * j][3]);
                uint32_t pa2 = packh2(sc[2 * j + 1][0], sc[2 * j + 1][1]);
                uint32_t pa3 = packh2(sc[2 * j + 1][2], sc[2 * j + 1][3]);
#pragma unroll
                for (int nf2 = 0; nf2 < 16; nf2++) {
                    uint32_t b0 = sv[(j * 8 + q) * VSH + nf2 * 8 + g];
                    uint32_t b1 = sv[(j * 8 + q + 4) * VSH + nf2 * 8 + g];
                    mma_f16(acc[nf2], pa0, pa1, pa2, pa3, b0, b1);
                }
            }
        }
    }

    // ---- epilogue: normalize, emit fp16 pair-words into [tok][2048] ----
    const float inv0 = 1.0f / l0;
    const float inv1 = 1.0f / l1;
    uint32_t* o0 = Oh + (size_t)(b * S_LEN + r0) * (D_MODEL / 2) + h * 64;
    uint32_t* o1 = o0 + (size_t)8 * (D_MODEL / 2);
#pragma unroll
    for (int nf = 0; nf < 16; nf++) {
        const int wc = nf * 4 + q;      // word index of cols (nf*8+2q, +1)
        o0[wc] = packh2(acc[nf][0] * inv0, acc[nf][1] * inv0);
        o1[wc] = packh2(acc[nf][2] * inv1, acc[nf][3] * inv1);
    }
}

// ---------------------------------------------------------------------------
// Launch
// ---------------------------------------------------------------------------
extern "C" void kernel_launch(void* const* d_in, const int* in_sizes, int n_in,
                              void* d_out, int out_size)
{
    const float* x     = (const float*)d_in[0];
    const int*   pos32 = (const int*)d_in[1];
    const float* w_qkv = (const float*)d_in[2];
    const float* w_o   = (const float*)d_in[3];
    float* out         = (float*)d_out;

    float *q, *k, *v;
    uint32_t *xh, *wqkvh, *woh, *qh, *kh, *vh, *attnh;
    cudaGetSymbolAddress((void**)&q,     g_q);
    cudaGetSymbolAddress((void**)&k,     g_k);
    cudaGetSymbolAddress((void**)&v,     g_v);
    cudaGetSymbolAddress((void**)&xh,    g_xh);
    cudaGetSymbolAddress((void**)&wqkvh, g_wqkvh);
    cudaGetSymbolAddress((void**)&woh,   g_woh);
    cudaGetSymbolAddress((void**)&qh,    g_qh);
    cudaGetSymbolAddress((void**)&kh,    g_kh);
    cudaGetSymbolAddress((void**)&vh,    g_vh);
    cudaGetSymbolAddress((void**)&attnh, g_attnh);

    cudaFuncSetAttribute(h16_gemm<1>,
                         cudaFuncAttributeMaxDynamicSharedMemorySize, GEMM_SMEM);
    cudaFuncSetAttribute(h16_gemm<0>,
                         cudaFuncAttributeMaxDynamicSharedMemorySize, GEMM_SMEM);
    cudaFuncSetAttribute(flash_h16,
                         cudaFuncAttributeMaxDynamicSharedMemorySize, FLASH_H_SMEM);

    // 0) prep: x -> fp16; weights -> packed fp16 pairs
    {
        const int nx4 = NTOK * D_MODEL / 4;
        f32_to_h16<<<nx4 / 256, 256>>>((const float4*)x, xh, nx4);
        pack_w16<<<dim3(QKV_N / 256, D_MODEL / 2), 256>>>(w_qkv, wqkvh, QKV_N);
        pack_w16<<<dim3(D_MODEL / 256, D_MODEL / 2), 256>>>(w_o, woh, D_MODEL);
    }

    // 1) QKV projection (fp16 HMMA) with f32 scatter epilogue
    h16_gemm<1><<<dim3(QKV_N / TBN, NTOK / TBM), 128, GEMM_SMEM>>>(
        xh, wqkvh, nullptr, q, k, v, QKV_N, D_MODEL);

    // 2) RoPE + fp16 conversion of Q,K + V pair-packing
    rope_pack_kernel<<<BH * (S_LEN / 2), 128>>>(q, k, v, qh, kh, vh, pos32);

    // 3) causal flash attention (fp16 HMMA), emits fp16 directly
    flash_h16<<<dim3(S_LEN / FQ, NHEADS, BATCH), 256, FLASH_H_SMEM>>>(
        qh, kh, vh, attnh);

    // 4) output projection (fp16 HMMA) -> f32 out
    h16_gemm<0><<<dim3(D_MODEL / TBN, NTOK / TBM), 128, GEMM_SMEM>>>(
        attnh, woh, out, nullptr, nullptr, nullptr, D_MODEL, D_MODEL);
}

// round 13
// speedup vs baseline: 7.8567x; 1.0185x over previous
#include <cuda_runtime.h>
#include <cuda_fp16.h>
#include <math.h>
#include <stdint.h>

// ---------------------------------------------------------------------------
// Problem constants
// ---------------------------------------------------------------------------
#define S_LEN   2048
#define D_MODEL 2048
#define NHEADS  16
#define HDIM    128
#define BATCH   2
#define NTOK    (BATCH * S_LEN)   // 4096
#define QKV_N   (3 * D_MODEL)     // 6144
#define BH      (BATCH * NHEADS)  // 32

// ---------------------------------------------------------------------------
// Scratch (device globals -- no allocation allowed in kernel_launch)
// ---------------------------------------------------------------------------
__device__ uint32_t g_xh[NTOK * D_MODEL / 2];        // x as fp16 pairs
__device__ uint32_t g_wqkvh[(D_MODEL / 2) * QKV_N];  // w_qkv packed [K/2][N]
__device__ uint32_t g_woh[(D_MODEL / 2) * D_MODEL];  // w_o packed [K/2][N]
__device__ uint32_t g_qh[BH * S_LEN * HDIM / 2];     // Q fp16 [row][64] words (roped)
__device__ uint32_t g_kh[BH * S_LEN * HDIM / 2];     // K fp16 [row][64] words (roped)
__device__ uint32_t g_vn[BH * S_LEN * HDIM / 2];     // V fp16 natural [row][64] words
__device__ uint32_t g_vh[BH * (S_LEN / 2) * HDIM];   // V packed [s/2][128] words
__device__ uint32_t g_attnh[NTOK * D_MODEL / 2];     // attn out fp16 pairs
__device__ float2   g_ctab[S_LEN * 64];              // (cos,sin) per (s, j)

// ---------------------------------------------------------------------------
// helpers
// ---------------------------------------------------------------------------
__device__ __forceinline__ void mma_f16(float c[4],
                                        uint32_t a0, uint32_t a1,
                                        uint32_t a2, uint32_t a3,
                                        uint32_t b0, uint32_t b1) {
    asm volatile(
        "mma.sync.aligned.m16n8k16.row.col.f32.f16.f16.f32 "
        "{%0,%1,%2,%3}, {%4,%5,%6,%7}, {%8,%9}, {%0,%1,%2,%3};"
        : "+f"(c[0]), "+f"(c[1]), "+f"(c[2]), "+f"(c[3])
        : "r"(a0), "r"(a1), "r"(a2), "r"(a3), "r"(b0), "r"(b1));
}
__device__ __forceinline__ void cp16(uint32_t dst, const void* src) {
    asm volatile("cp.async.cg.shared.global [%0], [%1], 16;"
                 :: "r"(dst), "l"(src));
}
__device__ __forceinline__ uint32_t packh2(float a, float b) {
    __half2 h = __floats2half2_rn(a, b);
    return *(uint32_t*)&h;
}

// ---------------------------------------------------------------------------
// Prep kernels
// ---------------------------------------------------------------------------
__global__ void f32_to_h16(const float4* __restrict__ in,
                           uint32_t* __restrict__ out, int n4)
{
    int i = blockIdx.x * blockDim.x + threadIdx.x;
    if (i < n4) {
        float4 v = in[i];
        out[2 * i + 0] = packh2(v.x, v.y);
        out[2 * i + 1] = packh2(v.z, v.w);
    }
}

__global__ void pack_w16(const float* __restrict__ in,
                         uint32_t* __restrict__ out, int N)
{
    const int n  = blockIdx.x * blockDim.x + threadIdx.x;
    const int kk = blockIdx.y;
    out[(size_t)kk * N + n] =
        packh2(in[(size_t)(2 * kk) * N + n], in[(size_t)(2 * kk + 1) * N + n]);
}

// cos/sin table: ctab[s][j] = (cos, sin) of pos[s] * theta^(-2j/128).
// token_positions may be int64 or (JAX x64-off) int32; detect layout.
__global__ void build_ctab(float2* __restrict__ ctab,
                           const int* __restrict__ pos32)
{
    const int s = blockIdx.x;
    const int j = threadIdx.x;          // 0..63
    const bool is64 = (pos32[1] == 0);
    const int  p    = is64 ? pos32[2 * s] : pos32[s];
    float inv = powf(10000.0f, -(float)(2 * j) * (1.0f / 128.0f));
    float sn, cs;
    sincosf((float)p * inv, &sn, &cs);
    ctab[s * 64 + j] = make_float2(cs, sn);
}

// V pair-pack: Vp word(s2, d) = half2(V[2s2][d], V[2s2+1][d]).  No re-rounding.
__global__ void vpack_kernel(const __half* __restrict__ Vn,
                             uint32_t* __restrict__ Vp)
{
    const int i  = blockIdx.x * 256 + threadIdx.x;   // over BH*(S/2)*HDIM
    const int d  = i & (HDIM - 1);
    const int r  = i >> 7;
    const int s2 = r & (S_LEN / 2 - 1);
    const int bh = r >> 10;
    const __half* base = Vn + ((size_t)(bh * S_LEN + 2 * s2)) * HDIM + d;
    __half2 h = __halves2half2(base[0], base[HDIM]);
    Vp[i] = *(uint32_t*)&h;
}

// ---------------------------------------------------------------------------
// fp16 HMMA GEMM (m16n8k16), cp.async 3-stage, BK=64.
// 128 threads, 4 warps (2x2) of 64x64, manual fragment double-buffer.
// MODE 0: plain f32 store to C.
// MODE 1: fused RoPE epilogue -> fp16 Q/K (roped) + fp16 V natural.
// ---------------------------------------------------------------------------
#define TBM 128
#define TBN 128
#define TBKW 32          // 64 k-elements = 32 pair-words
#define ASTR 36
#define BSTR 136
#define STG  3
#define AS_W (TBM * ASTR)            // 4608
#define BS_W (TBKW * BSTR)           // 4352
#define STAGE_W (AS_W + BS_W)        // 8960
#define GEMM_SMEM (STG * STAGE_W * 4)  // 107520 B

__device__ __forceinline__ void frag_ld_h(uint32_t af[4][4], uint32_t bf[8][2],
                                          const uint32_t* __restrict__ as_p,
                                          const uint32_t* __restrict__ bs_p,
                                          int kw, int wm, int wn, int g, int q)
{
#pragma unroll
    for (int tm = 0; tm < 4; tm++) {
        const int rA = wm * 64 + tm * 16 + g;
        af[tm][0] = as_p[rA * ASTR + kw + q];
        af[tm][1] = as_p[(rA + 8) * ASTR + kw + q];
        af[tm][2] = as_p[rA * ASTR + kw + q + 4];
        af[tm][3] = as_p[(rA + 8) * ASTR + kw + q + 4];
    }
#pragma unroll
    for (int tn = 0; tn < 8; tn++) {
        const int nB = wn * 64 + tn * 8 + g;
        bf[tn][0] = bs_p[(kw + q) * BSTR + nB];
        bf[tn][1] = bs_p[(kw + q + 4) * BSTR + nB];
    }
}

template <int MODE>
__global__ __launch_bounds__(128, 2)
void h16_gemm(const uint32_t* __restrict__ A, const uint32_t* __restrict__ B,
              float* __restrict__ C,
              uint32_t* __restrict__ Qh, uint32_t* __restrict__ Kh,
              uint32_t* __restrict__ Vn,
              const float2* __restrict__ ctab,
              int N, int K)
{
    extern __shared__ uint32_t smw[];
    const uint32_t sb = (uint32_t)__cvta_generic_to_shared(smw);

    const int tid  = threadIdx.x;
    const int lane = tid & 31;
    const int wid  = tid >> 5;
    const int wm   = wid >> 1;
    const int wn   = wid & 1;
    const int g    = lane >> 2;
    const int q    = lane & 3;

    const int brow = blockIdx.y;
    const int bcol = blockIdx.x;
    const int Kw   = K >> 1;
    const uint32_t* Ab = A + (size_t)brow * TBM * Kw;
    const uint32_t* Bb = B + bcol * TBN;

    const int T = K / 64;

#pragma unroll
    for (int p = 0; p < STG - 1; p++) {
        const uint32_t sa  = sb + (uint32_t)(p * STAGE_W) * 4u;
        const uint32_t sbb = sa + (uint32_t)AS_W * 4u;
        const int ktw = p * TBKW;
#pragma unroll
        for (int i = 0; i < 8; i++) {
            const int c   = tid + i * 128;
            const int arr = c >> 3, acw = (c & 7) << 2;
            const int brr = c >> 5, bcw = (c & 31) << 2;
            cp16(sa  + (uint32_t)(arr * ASTR + acw) * 4u,
                 Ab + (size_t)arr * Kw + ktw + acw);
            cp16(sbb + (uint32_t)(brr * BSTR + bcw) * 4u,
                 Bb + (size_t)(ktw + brr) * N + bcw);
        }
        asm volatile("cp.async.commit_group;");
    }

    float acc[4][8][4];
#pragma unroll
    for (int i = 0; i < 4; i++)
#pragma unroll
        for (int j = 0; j < 8; j++)
#pragma unroll
            for (int r = 0; r < 4; r++) acc[i][j][r] = 0.0f;

    uint32_t af[2][4][4], bf[2][8][2];

    int stage = 0;
    for (int t = 0; t < T; t++) {
        asm volatile("cp.async.wait_group %0;" :: "n"(STG - 2));
        __syncthreads();

        {
            const int tn = t + STG - 1;
            if (tn < T) {
                int st = stage + (STG - 1);
                if (st >= STG) st -= STG;
                const uint32_t sa  = sb + (uint32_t)(st * STAGE_W) * 4u;
                const uint32_t sbb = sa + (uint32_t)AS_W * 4u;
                const int ktw = tn * TBKW;
#pragma unroll
                for (int i = 0; i < 8; i++) {
                    const int c   = tid + i * 128;
                    const int arr = c >> 3, acw = (c & 7) << 2;
                    const int brr = c >> 5, bcw = (c & 31) << 2;
                    cp16(sa  + (uint32_t)(arr * ASTR + acw) * 4u,
                         Ab + (size_t)arr * Kw + ktw + acw);
                    cp16(sbb + (uint32_t)(brr * BSTR + bcw) * 4u,
                         Bb + (size_t)(ktw + brr) * N + bcw);
                }
            }
            asm volatile("cp.async.commit_group;");
        }

        const uint32_t* as_p = smw + stage * STAGE_W;
        const uint32_t* bs_p = as_p + AS_W;

        frag_ld_h(af[0], bf[0], as_p, bs_p, 0, wm, wn, g, q);
#pragma unroll
        for (int s = 0; s < 4; s++) {
            const int cur = s & 1;
            const int nxt = cur ^ 1;
            if (s + 1 < 4)
                frag_ld_h(af[nxt], bf[nxt], as_p, bs_p, (s + 1) * 8, wm, wn, g, q);
#pragma unroll
            for (int tm = 0; tm < 4; tm++)
#pragma unroll
                for (int tn2 = 0; tn2 < 8; tn2++)
                    mma_f16(acc[tm][tn2],
                            af[cur][tm][0], af[cur][tm][1],
                            af[cur][tm][2], af[cur][tm][3],
                            bf[cur][tn2][0], bf[cur][tn2][1]);
        }
        if (++stage == STG) stage = 0;
    }

    // ---------------- epilogue ----------------
    if (MODE == 0) {
#pragma unroll
        for (int tm = 0; tm < 4; tm++) {
            const int row = brow * TBM + wm * 64 + tm * 16 + g;
#pragma unroll
            for (int tn2 = 0; tn2 < 8; tn2++) {
                const int col = bcol * TBN + wn * 64 + tn2 * 8 + 2 * q;
                *(float2*)&C[(size_t)row * N + col] =
                    make_float2(acc[tm][tn2][0], acc[tm][tn2][1]);
                *(float2*)&C[(size_t)(row + 8) * N + col] =
                    make_float2(acc[tm][tn2][2], acc[tm][tn2][3]);
            }
        }
    } else {
        // Fused RoPE + fp16 epilogue.
        // Head-local col pair (2q, 2q+1) of each accumulator == rope pair j.
        const int col0  = bcol * TBN;
        const int which = col0 >> 11;          // 0=q,1=k,2=v
        const int h     = (col0 & 2047) >> 7;  // head
        uint32_t* dst = (which == 0) ? Qh : ((which == 1) ? Kh : Vn);
#pragma unroll
        for (int tm = 0; tm < 4; tm++) {
            const int rowtok = brow * TBM + wm * 64 + tm * 16 + g;
            const int bb  = rowtok >> 11;
            const int ss  = rowtok & 2047;
            const int rt8 = rowtok + 8;
            const int bb8 = rt8 >> 11;
            const int ss8 = rt8 & 2047;
            uint32_t* b0 = dst + ((size_t)(bb  * NHEADS + h) * S_LEN + ss)  * 64;
            uint32_t* b8 = dst + ((size_t)(bb8 * NHEADS + h) * S_LEN + ss8) * 64;
#pragma unroll
            for (int tn2 = 0; tn2 < 8; tn2++) {
                const int jl = wn * 32 + tn2 * 4 + q;   // word index in head
                if (which < 2) {
                    const float2 c0 = ctab[ss  * 64 + jl];
                    const float2 c8 = ctab[ss8 * 64 + jl];
                    float x1 = acc[tm][tn2][0], x2 = acc[tm][tn2][1];
                    b0[jl] = packh2(x1 * c0.x - x2 * c0.y, x1 * c0.y + x2 * c0.x);
                    x1 = acc[tm][tn2][2]; x2 = acc[tm][tn2][3];
                    b8[jl] = packh2(x1 * c8.x - x2 * c8.y, x1 * c8.y + x2 * c8.x);
                } else {
                    b0[jl] = packh2(acc[tm][tn2][0], acc[tm][tn2][1]);
                    b8[jl] = packh2(acc[tm][tn2][2], acc[tm][tn2][3]);
                }
            }
        }
    }
}

// ---------------------------------------------------------------------------
// Flash attention, fp16 HMMA (m16n8k16), causal, online softmax.
// Block: 128 q-rows, 8 warps x 16 rows, 256 threads.  K/V tiles of 64 keys,
// cp.async double-buffered.  P C-frag == A-frag for fp16 -> NO shuffles.
// Output: fp16 pair-words (GEMM2 A input).
// ---------------------------------------------------------------------------
#define FQ   128
#define FKT  64
#define QSH  68
#define VSH  136
#define SW_K0 (FQ * QSH)
#define SW_V0 (SW_K0 + 2 * FKT * QSH)
#define FLASH_H_SMEM ((SW_V0 + 2 * (FKT / 2) * VSH) * 4)   // 104448 B

__global__ __launch_bounds__(256, 1)
void flash_h16(const uint32_t* __restrict__ Qh, const uint32_t* __restrict__ Kh,
               const uint32_t* __restrict__ Vp, uint32_t* __restrict__ Oh)
{
    extern __shared__ uint32_t smw[];
    const int tid  = threadIdx.x;
    const int lane = tid & 31;
    const int w    = tid >> 5;
    const int g    = lane >> 2;
    const int q    = lane & 3;

    const int qb = blockIdx.x;
    const int h  = blockIdx.y;
    const int b  = blockIdx.z;
    const int bh = b * NHEADS + h;

    const uint32_t* Qg = Qh + ((size_t)bh * S_LEN + (size_t)qb * FQ) * 64;
    const uint32_t* Kg = Kh + (size_t)bh * S_LEN * 64;
    const uint32_t* Vg = Vp + (size_t)bh * (S_LEN / 2) * HDIM;

    const uint32_t sb = (uint32_t)__cvta_generic_to_shared(smw);

#pragma unroll
    for (int i = 0; i < 8; i++) {
        int c   = i * 256 + tid;
        int row = c >> 4, cw = (c & 15) << 2;
        cp16(sb + (uint32_t)(row * QSH + cw) * 4u, Qg + (size_t)row * 64 + cw);
    }
#pragma unroll
    for (int i = 0; i < 4; i++) {
        int c = i * 256 + tid;
        {
            int row = c >> 4, cw = (c & 15) << 2;
            cp16(sb + (uint32_t)(SW_K0 + row * QSH + cw) * 4u,
                 Kg + (size_t)row * 64 + cw);
        }
        {
            int row = c >> 5, cw = (c & 31) << 2;
            cp16(sb + (uint32_t)(SW_V0 + row * VSH + cw) * 4u,
                 Vg + (size_t)row * HDIM + cw);
        }
    }
    asm volatile("cp.async.commit_group;");

    float m0 = -1e30f, m1 = -1e30f, l0 = 0.0f, l1 = 0.0f;
    float acc[16][4];
#pragma unroll
    for (int nf = 0; nf < 16; nf++)
#pragma unroll
        for (int c = 0; c < 4; c++) acc[nf][c] = 0.0f;

    const float SC = 0.088388347648318447f;
    const int ntiles = 2 * qb + 2;
    const int r0 = qb * FQ + w * 16 + g;
    const int r1 = r0 + 8;

    for (int kt = 0; kt < ntiles; kt++) {
        asm volatile("cp.async.wait_group 0;");
        __syncthreads();

        if (kt + 1 < ntiles) {
            const int nb = (kt + 1) & 1;
            const uint32_t* Ks = Kg + (size_t)(kt + 1) * FKT * 64;
            const uint32_t* Vs = Vg + (size_t)(kt + 1) * (FKT / 2) * HDIM;
#pragma unroll
            for (int i = 0; i < 4; i++) {
                int c = i * 256 + tid;
                {
                    int row = c >> 4, cw = (c & 15) << 2;
                    cp16(sb + (uint32_t)(SW_K0 + nb * FKT * QSH + row * QSH + cw) * 4u,
                         Ks + (size_t)row * 64 + cw);
                }
                {
                    int row = c >> 5, cw = (c & 31) << 2;
                    cp16(sb + (uint32_t)(SW_V0 + nb * (FKT / 2) * VSH + row * VSH + cw) * 4u,
                         Vs + (size_t)row * HDIM + cw);
                }
            }
            asm volatile("cp.async.commit_group;");
        }

        if (kt * FKT <= qb * FQ + w * 16 + 15) {
            const uint32_t* sq = smw;
            const uint32_t* sk = smw + SW_K0 + (kt & 1) * FKT * QSH;
            const uint32_t* sv = smw + SW_V0 + (kt & 1) * (FKT / 2) * VSH;

            float sc[8][4];
#pragma unroll
            for (int nf = 0; nf < 8; nf++)
#pragma unroll
                for (int c = 0; c < 4; c++) sc[nf][c] = 0.0f;

#pragma unroll
            for (int ds = 0; ds < 8; ds++) {
                const int kw = ds * 8;
                uint32_t a0 = sq[(w * 16 + g) * QSH + kw + q];
                uint32_t a1 = sq[(w * 16 + g + 8) * QSH + kw + q];
                uint32_t a2 = sq[(w * 16 + g) * QSH + kw + q + 4];
                uint32_t a3 = sq[(w * 16 + g + 8) * QSH + kw + q + 4];
#pragma unroll
                for (int nf = 0; nf < 8; nf++) {
                    uint32_t b0 = sk[(nf * 8 + g) * QSH + kw + q];
                    uint32_t b1 = sk[(nf * 8 + g) * QSH + kw + q + 4];
                    mma_f16(sc[nf], a0, a1, a2, a3, b0, b1);
                }
            }

            if (kt * FKT + FKT - 1 > r0) {
#pragma unroll
                for (int nf = 0; nf < 8; nf++) {
#pragma unroll
                    for (int cb = 0; cb < 2; cb++) {
                        int kcol = kt * FKT + nf * 8 + 2 * q + cb;
                        if (kcol > r0) sc[nf][cb]     = -1e30f;
                        if (kcol > r1) sc[nf][2 + cb] = -1e30f;
                    }
                }
            }

            float mx0 = -1e30f, mx1 = -1e30f;
#pragma unroll
            for (int nf = 0; nf < 8; nf++) {
                mx0 = fmaxf(mx0, fmaxf(sc[nf][0], sc[nf][1]));
                mx1 = fmaxf(mx1, fmaxf(sc[nf][2], sc[nf][3]));
            }
            mx0 = fmaxf(mx0, __shfl_xor_sync(0xffffffffu, mx0, 1));
            mx0 = fmaxf(mx0, __shfl_xor_sync(0xffffffffu, mx0, 2));
            mx1 = fmaxf(mx1, __shfl_xor_sync(0xffffffffu, mx1, 1));
            mx1 = fmaxf(mx1, __shfl_xor_sync(0xffffffffu, mx1, 2));

            float mn0 = fmaxf(m0, mx0), mn1 = fmaxf(m1, mx1);
            float al0 = __expf(SC * (m0 - mn0));
            float al1 = __expf(SC * (m1 - mn1));
            m0 = mn0; m1 = mn1;

            float rs0 = 0.0f, rs1 = 0.0f;
#pragma unroll
            for (int nf = 0; nf < 8; nf++) {
                float p0 = __half2float(__float2half_rn(__expf(SC * (sc[nf][0] - m0))));
                float p1 = __half2float(__float2half_rn(__expf(SC * (sc[nf][1] - m0))));
                float p2 = __half2float(__float2half_rn(__expf(SC * (sc[nf][2] - m1))));
                float p3 = __half2float(__float2half_rn(__expf(SC * (sc[nf][3] - m1))));
                sc[nf][0] = p0; sc[nf][1] = p1; sc[nf][2] = p2; sc[nf][3] = p3;
                rs0 += p0 + p1;
                rs1 += p2 + p3;
            }
            rs0 += __shfl_xor_sync(0xffffffffu, rs0, 1);
            rs0 += __shfl_xor_sync(0xffffffffu, rs0, 2);
            rs1 += __shfl_xor_sync(0xffffffffu, rs1, 1);
            rs1 += __shfl_xor_sync(0xffffffffu, rs1, 2);
            l0 = l0 * al0 + rs0;
            l1 = l1 * al1 + rs1;

#pragma unroll
            for (int nf = 0; nf < 16; nf++) {
                acc[nf][0] *= al0; acc[nf][1] *= al0;
                acc[nf][2] *= al1; acc[nf][3] *= al1;
            }

#pragma unroll
            for (int j = 0; j < 4; j++) {
                uint32_t pa0 = packh2(sc[2 * j][0],     sc[2 * j][1]);
                uint32_t pa1 = packh2(sc[2 * j][2],     sc[2 * j][3]);
                uint32_t pa2 = packh2(sc[2 * j + 1][0], sc[2 * j + 1][1]);
                uint32_t pa3 = packh2(sc[2 * j + 1][2], sc[2 * j + 1][3]);
#pragma unroll
                for (int nf2 = 0; nf2 < 16; nf2++) {
                    uint32_t b0 = sv[(j * 8 + q) * VSH + nf2 * 8 + g];
                    uint32_t b1 = sv[(j * 8 + q + 4) * VSH + nf2 * 8 + g];
                    mma_f16(acc[nf2], pa0, pa1, pa2, pa3, b0, b1);
                }
            }
        }
    }

    const float inv0 = 1.0f / l0;
    const float inv1 = 1.0f / l1;
    uint32_t* o0 = Oh + (size_t)(b * S_LEN + r0) * (D_MODEL / 2) + h * 64;
    uint32_t* o1 = o0 + (size_t)8 * (D_MODEL / 2);
#pragma unroll
    for (int nf = 0; nf < 16; nf++) {
        const int wc = nf * 4 + q;
        o0[wc] = packh2(acc[nf][0] * inv0, acc[nf][1] * inv0);
        o1[wc] = packh2(acc[nf][2] * inv1, acc[nf][3] * inv1);
    }
}

// ---------------------------------------------------------------------------
// Launch
// ---------------------------------------------------------------------------
extern "C" void kernel_launch(void* const* d_in, const int* in_sizes, int n_in,
                              void* d_out, int out_size)
{
    const float* x     = (const float*)d_in[0];
    const int*   pos32 = (const int*)d_in[1];
    const float* w_qkv = (const float*)d_in[2];
    const float* w_o   = (const float*)d_in[3];
    float* out         = (float*)d_out;

    uint32_t *xh, *wqkvh, *woh, *qh, *kh, *vn, *vh, *attnh;
    float2* ctab;
    cudaGetSymbolAddress((void**)&xh,    g_xh);
    cudaGetSymbolAddress((void**)&wqkvh, g_wqkvh);
    cudaGetSymbolAddress((void**)&woh,   g_woh);
    cudaGetSymbolAddress((void**)&qh,    g_qh);
    cudaGetSymbolAddress((void**)&kh,    g_kh);
    cudaGetSymbolAddress((void**)&vn,    g_vn);
    cudaGetSymbolAddress((void**)&vh,    g_vh);
    cudaGetSymbolAddress((void**)&attnh, g_attnh);
    cudaGetSymbolAddress((void**)&ctab,  g_ctab);

    cudaFuncSetAttribute(h16_gemm<1>,
                         cudaFuncAttributeMaxDynamicSharedMemorySize, GEMM_SMEM);
    cudaFuncSetAttribute(h16_gemm<0>,
                         cudaFuncAttributeMaxDynamicSharedMemorySize, GEMM_SMEM);
    cudaFuncSetAttribute(flash_h16,
                         cudaFuncAttributeMaxDynamicSharedMemorySize, FLASH_H_SMEM);

    // 0) prep: x -> fp16; weights -> packed fp16 pairs; rope table
    {
        const int nx4 = NTOK * D_MODEL / 4;
        f32_to_h16<<<nx4 / 256, 256>>>((const float4*)x, xh, nx4);
        pack_w16<<<dim3(QKV_N / 256, D_MODEL / 2), 256>>>(w_qkv, wqkvh, QKV_N);
        pack_w16<<<dim3(D_MODEL / 256, D_MODEL / 2), 256>>>(w_o, woh, D_MODEL);
        build_ctab<<<S_LEN, 64>>>(ctab, pos32);
    }

    // 1) QKV projection (fp16 HMMA) with fused RoPE + fp16 epilogue
    h16_gemm<1><<<dim3(QKV_N / TBN, NTOK / TBM), 128, GEMM_SMEM>>>(
        xh, wqkvh, nullptr, qh, kh, vn, ctab, QKV_N, D_MODEL);

    // 2) V pair-pack (fp16 -> kv-paired words)
    vpack_kernel<<<BH * (S_LEN / 2) * HDIM / 256, 256>>>((const __half*)vn, vh);

    // 3) causal flash attention (fp16 HMMA), emits fp16 directly
    flash_h16<<<dim3(S_LEN / FQ, NHEADS, BATCH), 256, FLASH_H_SMEM>>>(
        qh, kh, vh, attnh);

    // 4) output projection (fp16 HMMA) -> f32 out
    h16_gemm<0><<<dim3(D_MODEL / TBN, NTOK / TBM), 128, GEMM_SMEM>>>(
        attnh, woh, out, nullptr, nullptr, nullptr, nullptr, D_MODEL, D_MODEL);
}

// round 15
// speedup vs baseline: 8.3043x; 1.0570x over previous
#include <cuda_runtime.h>
#include <cuda_fp16.h>
#include <math.h>
#include <stdint.h>

// ---------------------------------------------------------------------------
// Problem constants
// ---------------------------------------------------------------------------
#define S_LEN   2048
#define D_MODEL 2048
#define NHEADS  16
#define HDIM    128
#define BATCH   2
#define NTOK    (BATCH * S_LEN)   // 4096
#define QKV_N   (3 * D_MODEL)     // 6144
#define BH      (BATCH * NHEADS)  // 32

// ---------------------------------------------------------------------------
// Scratch (device globals -- no allocation allowed in kernel_launch)
// ---------------------------------------------------------------------------
__device__ uint32_t g_xh[NTOK * D_MODEL / 2];        // x fp16 pairs [M][K/2]
__device__ uint32_t g_wqkvh[QKV_N * (D_MODEL / 2)];  // w_qkv T-packed [N][K/2]
__device__ uint32_t g_woh[D_MODEL * (D_MODEL / 2)];  // w_o  T-packed [N][K/2]
__device__ uint32_t g_qh[BH * S_LEN * HDIM / 2];     // Q fp16 [row][64] (roped)
__device__ uint32_t g_kh[BH * S_LEN * HDIM / 2];     // K fp16 [row][64] (roped)
__device__ uint32_t g_vn[BH * S_LEN * HDIM / 2];     // V fp16 natural [row][64]
__device__ uint32_t g_vt[BH * HDIM * (S_LEN / 2)];   // V transposed [d][s/2]
__device__ uint32_t g_attnh[NTOK * D_MODEL / 2];     // attn out fp16 pairs
__device__ float2   g_ctab[S_LEN * 64];              // (cos,sin) per (s, j)

// ---------------------------------------------------------------------------
// helpers
// ---------------------------------------------------------------------------
__device__ __forceinline__ void mma_f16(float c[4],
                                        uint32_t a0, uint32_t a1,
                                        uint32_t a2, uint32_t a3,
                                        uint32_t b0, uint32_t b1) {
    asm volatile(
        "mma.sync.aligned.m16n8k16.row.col.f32.f16.f16.f32 "
        "{%0,%1,%2,%3}, {%4,%5,%6,%7}, {%8,%9}, {%0,%1,%2,%3};"
        : "+f"(c[0]), "+f"(c[1]), "+f"(c[2]), "+f"(c[3])
        : "r"(a0), "r"(a1), "r"(a2), "r"(a3), "r"(b0), "r"(b1));
}
__device__ __forceinline__ void cp16(uint32_t dst, const void* src) {
    asm volatile("cp.async.cg.shared.global [%0], [%1], 16;"
                 :: "r"(dst), "l"(src));
}
__device__ __forceinline__ uint32_t packh2(float a, float b) {
    __half2 h = __floats2half2_rn(a, b);
    return *(uint32_t*)&h;
}
__device__ __forceinline__ void ldsm4(uint32_t r[4], uint32_t addr) {
    asm volatile("ldmatrix.sync.aligned.m8n8.x4.shared.b16 {%0,%1,%2,%3}, [%4];"
                 : "=r"(r[0]), "=r"(r[1]), "=r"(r[2]), "=r"(r[3]) : "r"(addr));
}

// ---------------------------------------------------------------------------
// Prep kernels
// ---------------------------------------------------------------------------
__global__ void f32_to_h16(const float4* __restrict__ in,
                           uint32_t* __restrict__ out, int n4)
{
    int i = blockIdx.x * blockDim.x + threadIdx.x;
    if (i < n4) {
        float4 v = in[i];
        out[2 * i + 0] = packh2(v.x, v.y);
        out[2 * i + 1] = packh2(v.z, v.w);
    }
}

// Transposing weight pack: in [K][N] f32 -> out [N][K/2] fp16-pair words.
// Block: 64 k x 32 n tile via smem.
__global__ void pack_w16t(const float* __restrict__ in,
                          uint32_t* __restrict__ out, int N, int K)
{
    __shared__ float sm[64][33];
    const int n0 = blockIdx.x * 32;
    const int k0 = blockIdx.y * 64;
    const int tid = threadIdx.x;
#pragma unroll
    for (int i = 0; i < 8; i++) {
        int r = i * 8 + (tid >> 5);
        int n = tid & 31;
        sm[r][n] = in[(size_t)(k0 + r) * N + n0 + n];
    }
    __syncthreads();
    const int Kw = K >> 1;
#pragma unroll
    for (int i = 0; i < 4; i++) {
        int idx = i * 256 + tid;
        int n = idx >> 5, kkl = idx & 31;
        out[(size_t)(n0 + n) * Kw + (k0 >> 1) + kkl] =
            packh2(sm[2 * kkl][n], sm[2 * kkl + 1][n]);
    }
}

// cos/sin table (positions int64/int32 auto-detect)
__global__ void build_ctab(float2* __restrict__ ctab,
                           const int* __restrict__ pos32)
{
    const int s = blockIdx.x;
    const int j = threadIdx.x;
    const bool is64 = (pos32[1] == 0);
    const int  p    = is64 ? pos32[2 * s] : pos32[s];
    float inv = powf(10000.0f, -(float)(2 * j) * (1.0f / 128.0f));
    float sn, cs;
    sincosf((float)p * inv, &sn, &cs);
    ctab[s * 64 + j] = make_float2(cs, sn);
}

// V transpose-pack: Vn [bh][s][64 dwords] -> Vt [bh][d][s/2 spair-words].
// Block handles (bh, 64-s slab): smem transpose.
__global__ void vpack_t(const uint32_t* __restrict__ Vn,
                        uint32_t* __restrict__ Vt)
{
    __shared__ uint32_t sm[64][68];
    const int bh   = blockIdx.y;
    const int sblk = blockIdx.x;
    const int tid  = threadIdx.x;
    const uint32_t* src = Vn + ((size_t)bh * S_LEN + sblk * 64) * 64;
#pragma unroll
    for (int i = 0; i < 16; i++) {
        int idx = i * 256 + tid;
        int r = idx >> 6, wd = idx & 63;
        sm[r][wd] = src[(size_t)r * 64 + wd];
    }
    __syncthreads();
    uint32_t* dst = Vt + (size_t)bh * HDIM * (S_LEN / 2) + sblk * 32;
#pragma unroll
    for (int i = 0; i < 16; i++) {
        int idx = i * 256 + tid;
        int d = idx >> 5, s2l = idx & 31;
        __half lo = ((const __half*)&sm[2 * s2l][d >> 1])[d & 1];
        __half hi = ((const __half*)&sm[2 * s2l + 1][d >> 1])[d & 1];
        __half2 h = __halves2half2(lo, hi);
        dst[(size_t)d * (S_LEN / 2) + s2l] = *(uint32_t*)&h;
    }
}

// ---------------------------------------------------------------------------
// fp16 HMMA GEMM (m16n8k16), cp.async 3-stage, BK=64, ldmatrix fragments.
// A: [M][K/2] words.  B: T-packed [N][K/2] words (same tile shape as A).
// 128 threads, 4 warps (2x2) of 64x64, manual fragment double-buffer.
// MODE 0: plain f32 store.  MODE 1: fused RoPE -> fp16 Q/K/V.
// ---------------------------------------------------------------------------
#define TBM 128
#define TBN 128
#define TBKW 32          // 64 k-elements = 32 pair-words
#define TSTR 36          // tile row stride (words): (r+c)%8 distinct for LDSM
#define STG  3
#define AS_W (TBM * TSTR)            // 4608
#define BS_W (TBN * TSTR)            // 4608
#define STAGE_W (AS_W + BS_W)        // 9216
#define GEMM_SMEM (STG * STAGE_W * 4)  // 110592 B

template <int MODE>
__global__ __launch_bounds__(128, 2)
void h16_gemm(const uint32_t* __restrict__ A, const uint32_t* __restrict__ B,
              float* __restrict__ C,
              uint32_t* __restrict__ Qh, uint32_t* __restrict__ Kh,
              uint32_t* __restrict__ Vn,
              const float2* __restrict__ ctab,
              int N, int K)
{
    extern __shared__ uint32_t smw[];
    const uint32_t sb = (uint32_t)__cvta_generic_to_shared(smw);

    const int tid  = threadIdx.x;
    const int lane = tid & 31;
    const int wid  = tid >> 5;
    const int wm   = wid >> 1;
    const int wn   = wid & 1;
    const int g    = lane >> 2;
    const int q    = lane & 3;
    const int l7   = lane & 7;
    const int lb8  = (lane >> 3) & 1;
    const int lb16 = (lane >> 4) & 1;

    const int brow = blockIdx.y;
    const int bcol = blockIdx.x;
    const int Kw   = K >> 1;
    const uint32_t* Ab = A + (size_t)brow * TBM * Kw;
    const uint32_t* Bb = B + (size_t)bcol * TBN * Kw;

    // ldmatrix per-thread base offsets (words)
    int aoff[4], boff[4];
#pragma unroll
    for (int tm = 0; tm < 4; tm++)
        aoff[tm] = (wm * 64 + tm * 16 + l7 + 8 * lb8) * TSTR + 4 * lb16;
#pragma unroll
    for (int p = 0; p < 4; p++)
        boff[p] = (wn * 64 + p * 16 + l7 + 8 * lb16) * TSTR + 4 * lb8;

    const int T = K / 64;

    // prefetch first STG-1 tiles: 1024 A + 1024 B chunks, 8+8 per thread
#pragma unroll
    for (int p = 0; p < STG - 1; p++) {
        const uint32_t sa  = sb + (uint32_t)(p * STAGE_W) * 4u;
        const uint32_t sbb = sa + (uint32_t)AS_W * 4u;
        const int ktw = p * TBKW;
#pragma unroll
        for (int i = 0; i < 8; i++) {
            const int c   = tid + i * 128;
            const int row = c >> 3, cw = (c & 7) << 2;
            cp16(sa  + (uint32_t)(row * TSTR + cw) * 4u,
                 Ab + (size_t)row * Kw + ktw + cw);
            cp16(sbb + (uint32_t)(row * TSTR + cw) * 4u,
                 Bb + (size_t)row * Kw + ktw + cw);
        }
        asm volatile("cp.async.commit_group;");
    }

    float acc[4][8][4];
#pragma unroll
    for (int i = 0; i < 4; i++)
#pragma unroll
        for (int j = 0; j < 8; j++)
#pragma unroll
            for (int r = 0; r < 4; r++) acc[i][j][r] = 0.0f;

    uint32_t af[2][4][4], bf[2][8][2];

    int stage = 0;
    for (int t = 0; t < T; t++) {
        asm volatile("cp.async.wait_group %0;" :: "n"(STG - 2));
        __syncthreads();

        {
            const int tn = t + STG - 1;
            if (tn < T) {
                int st = stage + (STG - 1);
                if (st >= STG) st -= STG;
                const uint32_t sa  = sb + (uint32_t)(st * STAGE_W) * 4u;
                const uint32_t sbb = sa + (uint32_t)AS_W * 4u;
                const int ktw = tn * TBKW;
#pragma unroll
                for (int i = 0; i < 8; i++) {
                    const int c   = tid + i * 128;
                    const int row = c >> 3, cw = (c & 7) << 2;
                    cp16(sa  + (uint32_t)(row * TSTR + cw) * 4u,
                         Ab + (size_t)row * Kw + ktw + cw);
                    cp16(sbb + (uint32_t)(row * TSTR + cw) * 4u,
                         Bb + (size_t)row * Kw + ktw + cw);
                }
            }
            asm volatile("cp.async.commit_group;");
        }

        const uint32_t sa  = sb + (uint32_t)(stage * STAGE_W) * 4u;
        const uint32_t sbb = sa + (uint32_t)AS_W * 4u;

        // ldmatrix fragment load for step kw
        auto ldfrag = [&](uint32_t afr[4][4], uint32_t bfr[8][2], int kw) {
#pragma unroll
            for (int tm = 0; tm < 4; tm++)
                ldsm4(afr[tm], sa + (uint32_t)(aoff[tm] + kw) * 4u);
#pragma unroll
            for (int p = 0; p < 4; p++) {
                uint32_t tmp[4];
                ldsm4(tmp, sbb + (uint32_t)(boff[p] + kw) * 4u);
                bfr[2 * p][0] = tmp[0]; bfr[2 * p][1] = tmp[1];
                bfr[2 * p + 1][0] = tmp[2]; bfr[2 * p + 1][1] = tmp[3];
            }
        };

        ldfrag(af[0], bf[0], 0);
#pragma unroll
        for (int s = 0; s < 4; s++) {
            const int cur = s & 1;
            const int nxt = cur ^ 1;
            if (s + 1 < 4) ldfrag(af[nxt], bf[nxt], (s + 1) * 8);
#pragma unroll
            for (int tm = 0; tm < 4; tm++)
#pragma unroll
                for (int tn2 = 0; tn2 < 8; tn2++)
                    mma_f16(acc[tm][tn2],
                            af[cur][tm][0], af[cur][tm][1],
                            af[cur][tm][2], af[cur][tm][3],
                            bf[cur][tn2][0], bf[cur][tn2][1]);
        }
        if (++stage == STG) stage = 0;
    }

    // ---------------- epilogue ----------------
    if (MODE == 0) {
#pragma unroll
        for (int tm = 0; tm < 4; tm++) {
            const int row = brow * TBM + wm * 64 + tm * 16 + g;
#pragma unroll
            for (int tn2 = 0; tn2 < 8; tn2++) {
                const int col = bcol * TBN + wn * 64 + tn2 * 8 + 2 * q;
                *(float2*)&C[(size_t)row * N + col] =
                    make_float2(acc[tm][tn2][0], acc[tm][tn2][1]);
                *(float2*)&C[(size_t)(row + 8) * N + col] =
                    make_float2(acc[tm][tn2][2], acc[tm][tn2][3]);
            }
        }
    } else {
        const int col0  = bcol * TBN;
        const int which = col0 >> 11;
        const int h     = (col0 & 2047) >> 7;
        uint32_t* dst = (which == 0) ? Qh : ((which == 1) ? Kh : Vn);
#pragma unroll
        for (int tm = 0; tm < 4; tm++) {
            const int rowtok = brow * TBM + wm * 64 + tm * 16 + g;
            const int bb  = rowtok >> 11;
            const int ss  = rowtok & 2047;
            const int rt8 = rowtok + 8;
            const int bb8 = rt8 >> 11;
            const int ss8 = rt8 & 2047;
            uint32_t* b0 = dst + ((size_t)(bb  * NHEADS + h) * S_LEN + ss)  * 64;
            uint32_t* b8 = dst + ((size_t)(bb8 * NHEADS + h) * S_LEN + ss8) * 64;
#pragma unroll
            for (int tn2 = 0; tn2 < 8; tn2++) {
                const int jl = wn * 32 + tn2 * 4 + q;
                if (which < 2) {
                    const float2 c0 = ctab[ss  * 64 + jl];
                    const float2 c8 = ctab[ss8 * 64 + jl];
                    float x1 = acc[tm][tn2][0], x2 = acc[tm][tn2][1];
                    b0[jl] = packh2(x1 * c0.x - x2 * c0.y, x1 * c0.y + x2 * c0.x);
                    x1 = acc[tm][tn2][2]; x2 = acc[tm][tn2][3];
                    b8[jl] = packh2(x1 * c8.x - x2 * c8.y, x1 * c8.y + x2 * c8.x);
                } else {
                    b0[jl] = packh2(acc[tm][tn2][0], acc[tm][tn2][1]);
                    b8[jl] = packh2(acc[tm][tn2][2], acc[tm][tn2][3]);
                }
            }
        }
    }
}

// ---------------------------------------------------------------------------
// Flash attention, fp16 HMMA + ldmatrix, causal, online softmax.
// Q/K smem [row][64+pad] k-contiguous; V smem [d][spair] (transposed layout).
// Block: 128 q-rows, 8 warps x 16 rows, 256 threads.  Output fp16 pairs.
// ---------------------------------------------------------------------------
#define FQ   128
#define FKT  64
#define QSH  68     // Q/K row stride (words): (r+c)%8 distinct for LDSM
#define VTS  36     // V tile row stride (words)
#define SW_K0 (FQ * QSH)                  // 8704
#define SW_V0 (SW_K0 + 2 * FKT * QSH)     // 17408
#define FLASH_H_SMEM ((SW_V0 + 2 * HDIM * VTS) * 4)   // 106496 B

__global__ __launch_bounds__(256, 1)
void flash_h16(const uint32_t* __restrict__ Qh, const uint32_t* __restrict__ Kh,
               const uint32_t* __restrict__ Vt, uint32_t* __restrict__ Oh)
{
    extern __shared__ uint32_t smw[];
    const int tid  = threadIdx.x;
    const int lane = tid & 31;
    const int w    = tid >> 5;
    const int g    = lane >> 2;
    const int q    = lane & 3;
    const int l7   = lane & 7;
    const int lb8  = (lane >> 3) & 1;
    const int lb16 = (lane >> 4) & 1;

    const int qb = blockIdx.x;
    const int h  = blockIdx.y;
    const int b  = blockIdx.z;
    const int bh = b * NHEADS + h;

    const uint32_t* Qg = Qh + ((size_t)bh * S_LEN + (size_t)qb * FQ) * 64;
    const uint32_t* Kg = Kh + (size_t)bh * S_LEN * 64;
    const uint32_t* Vg = Vt + (size_t)bh * HDIM * (S_LEN / 2);

    const uint32_t sb = (uint32_t)__cvta_generic_to_shared(smw);

    // ldmatrix base offsets
    const int qoff = (w * 16 + l7 + 8 * lb8) * QSH + 4 * lb16;
    int koff[4], voff[8];
#pragma unroll
    for (int p = 0; p < 4; p++)
        koff[p] = (p * 16 + l7 + 8 * lb16) * QSH + 4 * lb8;
#pragma unroll
    for (int p = 0; p < 8; p++)
        voff[p] = (p * 16 + l7 + 8 * lb16) * VTS + 4 * lb8;

    // Q tile: 2048 chunks, 8/thread
#pragma unroll
    for (int i = 0; i < 8; i++) {
        int c   = i * 256 + tid;
        int row = c >> 4, cw = (c & 15) << 2;
        cp16(sb + (uint32_t)(row * QSH + cw) * 4u, Qg + (size_t)row * 64 + cw);
    }
    // K tile 0 (1024 chunks) + V tile 0 (1024 chunks), 4+4/thread
#pragma unroll
    for (int i = 0; i < 4; i++) {
        int c = i * 256 + tid;
        {
            int row = c >> 4, cw = (c & 15) << 2;
            cp16(sb + (uint32_t)(SW_K0 + row * QSH + cw) * 4u,
                 Kg + (size_t)row * 64 + cw);
        }
        {
            int d = c >> 3, cw = (c & 7) << 2;
            cp16(sb + (uint32_t)(SW_V0 + d * VTS + cw) * 4u,
                 Vg + (size_t)d * (S_LEN / 2) + cw);
        }
    }
    asm volatile("cp.async.commit_group;");

    float m0 = -1e30f, m1 = -1e30f, l0 = 0.0f, l1 = 0.0f;
    float acc[16][4];
#pragma unroll
    for (int nf = 0; nf < 16; nf++)
#pragma unroll
        for (int c = 0; c < 4; c++) acc[nf][c] = 0.0f;

    const float SC = 0.088388347648318447f;
    const int ntiles = 2 * qb + 2;
    const int r0 = qb * FQ + w * 16 + g;
    const int r1 = r0 + 8;

    for (int kt = 0; kt < ntiles; kt++) {
        asm volatile("cp.async.wait_group 0;");
        __syncthreads();

        if (kt + 1 < ntiles) {
            const int nb = (kt + 1) & 1;
            const uint32_t* Ks = Kg + (size_t)(kt + 1) * FKT * 64;
            const uint32_t* Vs = Vg + (size_t)(kt + 1) * (FKT / 2);
#pragma unroll
            for (int i = 0; i < 4; i++) {
                int c = i * 256 + tid;
                {
                    int row = c >> 4, cw = (c & 15) << 2;
                    cp16(sb + (uint32_t)(SW_K0 + nb * FKT * QSH + row * QSH + cw) * 4u,
                         Ks + (size_t)row * 64 + cw);
                }
                {
                    int d = c >> 3, cw = (c & 7) << 2;
                    cp16(sb + (uint32_t)(SW_V0 + nb * HDIM * VTS + d * VTS + cw) * 4u,
                         Vs + (size_t)d * (S_LEN / 2) + cw);
                }
            }
            asm volatile("cp.async.commit_group;");
        }

        if (kt * FKT <= qb * FQ + w * 16 + 15) {
            const uint32_t sqb = sb;
            const uint32_t skb = sb + (uint32_t)(SW_K0 + (kt & 1) * FKT * QSH) * 4u;
            const uint32_t svb = sb + (uint32_t)(SW_V0 + (kt & 1) * HDIM * VTS) * 4u;

            // ---- S = Q K^T : 8 d-steps; LDSM fragments ----
            float sc[8][4];
#pragma unroll
            for (int nf = 0; nf < 8; nf++)
#pragma unroll
                for (int c = 0; c < 4; c++) sc[nf][c] = 0.0f;

#pragma unroll
            for (int ds = 0; ds < 8; ds++) {
                const int kw = ds * 8;
                uint32_t a[4];
                ldsm4(a, sqb + (uint32_t)(qoff + kw) * 4u);
#pragma unroll
                for (int p = 0; p < 4; p++) {
                    uint32_t kb[4];
                    ldsm4(kb, skb + (uint32_t)(koff[p] + kw) * 4u);
                    mma_f16(sc[2 * p],     a[0], a[1], a[2], a[3], kb[0], kb[1]);
                    mma_f16(sc[2 * p + 1], a[0], a[1], a[2], a[3], kb[2], kb[3]);
                }
            }

            // ---- causal mask ----
            if (kt * FKT + FKT - 1 > r0) {
#pragma unroll
                for (int nf = 0; nf < 8; nf++) {
#pragma unroll
                    for (int cb = 0; cb < 2; cb++) {
                        int kcol = kt * FKT + nf * 8 + 2 * q + cb;
                        if (kcol > r0) sc[nf][cb]     = -1e30f;
                        if (kcol > r1) sc[nf][2 + cb] = -1e30f;
                    }
                }
            }

            // ---- online softmax (quad-local) ----
            float mx0 = -1e30f, mx1 = -1e30f;
#pragma unroll
            for (int nf = 0; nf < 8; nf++) {
                mx0 = fmaxf(mx0, fmaxf(sc[nf][0], sc[nf][1]));
                mx1 = fmaxf(mx1, fmaxf(sc[nf][2], sc[nf][3]));
            }
            mx0 = fmaxf(mx0, __shfl_xor_sync(0xffffffffu, mx0, 1));
            mx0 = fmaxf(mx0, __shfl_xor_sync(0xffffffffu, mx0, 2));
            mx1 = fmaxf(mx1, __shfl_xor_sync(0xffffffffu, mx1, 1));
            mx1 = fmaxf(mx1, __shfl_xor_sync(0xffffffffu, mx1, 2));

            float mn0 = fmaxf(m0, mx0), mn1 = fmaxf(m1, mx1);
            float al0 = __expf(SC * (m0 - mn0));
            float al1 = __expf(SC * (m1 - mn1));
            m0 = mn0; m1 = mn1;

            float rs0 = 0.0f, rs1 = 0.0f;
#pragma unroll
            for (int nf = 0; nf < 8; nf++) {
                float p0 = __half2float(__float2half_rn(__expf(SC * (sc[nf][0] - m0))));
                float p1 = __half2float(__float2half_rn(__expf(SC * (sc[nf][1] - m0))));
                float p2 = __half2float(__float2half_rn(__expf(SC * (sc[nf][2] - m1))));
                float p3 = __half2float(__float2half_rn(__expf(SC * (sc[nf][3] - m1))));
                sc[nf][0] = p0; sc[nf][1] = p1; sc[nf][2] = p2; sc[nf][3] = p3;
                rs0 += p0 + p1;
                rs1 += p2 + p3;
            }
            rs0 += __shfl_xor_sync(0xffffffffu, rs0, 1);
            rs0 += __shfl_xor_sync(0xffffffffu, rs0, 2);
            rs1 += __shfl_xor_sync(0xffffffffu, rs1, 1);
            rs1 += __shfl_xor_sync(0xffffffffu, rs1, 2);
            l0 = l0 * al0 + rs0;
            l1 = l1 * al1 + rs1;

#pragma unroll
            for (int nf = 0; nf < 16; nf++) {
                acc[nf][0] *= al0; acc[nf][1] *= al0;
                acc[nf][2] *= al1; acc[nf][3] *= al1;
            }

            // ---- O += P V : LDSM V fragments ----
#pragma unroll
            for (int j = 0; j < 4; j++) {
                uint32_t pa0 = packh2(sc[2 * j][0],     sc[2 * j][1]);
                uint32_t pa1 = packh2(sc[2 * j][2],     sc[2 * j][3]);
                uint32_t pa2 = packh2(sc[2 * j + 1][0], sc[2 * j + 1][1]);
                uint32_t pa3 = packh2(sc[2 * j + 1][2], sc[2 * j + 1][3]);
#pragma unroll
                for (int p = 0; p < 8; p++) {
                    uint32_t vb[4];
                    ldsm4(vb, svb + (uint32_t)(voff[p] + j * 8) * 4u);
                    mma_f16(acc[2 * p],     pa0, pa1, pa2, pa3, vb[0], vb[1]);
                    mma_f16(acc[2 * p + 1], pa0, pa1, pa2, pa3, vb[2], vb[3]);
                }
            }
        }
    }

    // ---- epilogue: normalize, emit fp16 pair-words ----
    const float inv0 = 1.0f / l0;
    const float inv1 = 1.0f / l1;
    uint32_t* o0 = Oh + (size_t)(b * S_LEN + r0) * (D_MODEL / 2) + h * 64;
    uint32_t* o1 = o0 + (size_t)8 * (D_MODEL / 2);
#pragma unroll
    for (int nf = 0; nf < 16; nf++) {
        const int wc = nf * 4 + q;
        o0[wc] = packh2(acc[nf][0] * inv0, acc[nf][1] * inv0);
        o1[wc] = packh2(acc[nf][2] * inv1, acc[nf][3] * inv1);
    }
}

// ---------------------------------------------------------------------------
// Launch
// ---------------------------------------------------------------------------
extern "C" void kernel_launch(void* const* d_in, const int* in_sizes, int n_in,
                              void* d_out, int out_size)
{
    const float* x     = (const float*)d_in[0];
    const int*   pos32 = (const int*)d_in[1];
    const float* w_qkv = (const float*)d_in[2];
    const float* w_o   = (const float*)d_in[3];
    float* out         = (float*)d_out;

    uint32_t *xh, *wqkvh, *woh, *qh, *kh, *vn, *vt, *attnh;
    float2* ctab;
    cudaGetSymbolAddress((void**)&xh,    g_xh);
    cudaGetSymbolAddress((void**)&wqkvh, g_wqkvh);
    cudaGetSymbolAddress((void**)&woh,   g_woh);
    cudaGetSymbolAddress((void**)&qh,    g_qh);
    cudaGetSymbolAddress((void**)&kh,    g_kh);
    cudaGetSymbolAddress((void**)&vn,    g_vn);
    cudaGetSymbolAddress((void**)&vt,    g_vt);
    cudaGetSymbolAddress((void**)&attnh, g_attnh);
    cudaGetSymbolAddress((void**)&ctab,  g_ctab);

    cudaFuncSetAttribute(h16_gemm<1>,
                         cudaFuncAttributeMaxDynamicSharedMemorySize, GEMM_SMEM);
    cudaFuncSetAttribute(h16_gemm<0>,
                         cudaFuncAttributeMaxDynamicSharedMemorySize, GEMM_SMEM);
    cudaFuncSetAttribute(flash_h16,
                         cudaFuncAttributeMaxDynamicSharedMemorySize, FLASH_H_SMEM);

    // 0) prep: x -> fp16; weights -> transposed-packed fp16; rope table
    {
        const int nx4 = NTOK * D_MODEL / 4;
        f32_to_h16<<<nx4 / 256, 256>>>((const float4*)x, xh, nx4);
        pack_w16t<<<dim3(QKV_N / 32, D_MODEL / 64), 256>>>(w_qkv, wqkvh,
                                                           QKV_N, D_MODEL);
        pack_w16t<<<dim3(D_MODEL / 32, D_MODEL / 64), 256>>>(w_o, woh,
                                                             D_MODEL, D_MODEL);
        build_ctab<<<S_LEN, 64>>>(ctab, pos32);
    }

    // 1) QKV projection (fp16 HMMA + ldmatrix) with fused RoPE epilogue
    h16_gemm<1><<<dim3(QKV_N / TBN, NTOK / TBM), 128, GEMM_SMEM>>>(
        xh, wqkvh, nullptr, qh, kh, vn, ctab, QKV_N, D_MODEL);

    // 2) V transpose-pack ([row][d] -> [d][spair])
    vpack_t<<<dim3(S_LEN / 64, BH), 256>>>(vn, vt);

    // 3) causal flash attention (fp16 HMMA + ldmatrix)
    flash_h16<<<dim3(S_LEN / FQ, NHEADS, BATCH), 256, FLASH_H_SMEM>>>(
        qh, kh, vt, attnh);

    // 4) output projection (fp16 HMMA + ldmatrix) -> f32 out
    h16_gemm<0><<<dim3(D_MODEL / TBN, NTOK / TBM), 128, GEMM_SMEM>>>(
        attnh, woh, out, nullptr, nullptr, nullptr, nullptr, D_MODEL, D_MODEL);
}

// round 16
// speedup vs baseline: 8.4720x; 1.0202x over previous
#include <cuda_runtime.h>
#include <cuda_fp16.h>
#include <math.h>
#include <stdint.h>

// ---------------------------------------------------------------------------
// Problem constants
// ---------------------------------------------------------------------------
#define S_LEN   2048
#define D_MODEL 2048
#define NHEADS  16
#define HDIM    128
#define BATCH   2
#define NTOK    (BATCH * S_LEN)   // 4096
#define QKV_N   (3 * D_MODEL)     // 6144
#define BH      (BATCH * NHEADS)  // 32

// ---------------------------------------------------------------------------
// Scratch (device globals -- no allocation allowed in kernel_launch)
// ---------------------------------------------------------------------------
__device__ uint32_t g_xh[NTOK * D_MODEL / 2];        // x fp16 pairs [M][K/2]
__device__ uint32_t g_wqkvh[QKV_N * (D_MODEL / 2)];  // w_qkv T-packed [N][K/2]
__device__ uint32_t g_woh[D_MODEL * (D_MODEL / 2)];  // w_o  T-packed [N][K/2]
__device__ uint32_t g_qh[BH * S_LEN * HDIM / 2];     // Q fp16 [row][64] (roped)
__device__ uint32_t g_kh[BH * S_LEN * HDIM / 2];     // K fp16 [row][64] (roped)
__device__ uint32_t g_vn[BH * S_LEN * HDIM / 2];     // V fp16 natural [row][64]
__device__ uint32_t g_attnh[NTOK * D_MODEL / 2];     // attn out fp16 pairs
__device__ float2   g_ctab[S_LEN * 64];              // (cos,sin) per (s, j)

// ---------------------------------------------------------------------------
// helpers
// ---------------------------------------------------------------------------
__device__ __forceinline__ void mma_f16(float c[4],
                                        uint32_t a0, uint32_t a1,
                                        uint32_t a2, uint32_t a3,
                                        uint32_t b0, uint32_t b1) {
    asm volatile(
        "mma.sync.aligned.m16n8k16.row.col.f32.f16.f16.f32 "
        "{%0,%1,%2,%3}, {%4,%5,%6,%7}, {%8,%9}, {%0,%1,%2,%3};"
        : "+f"(c[0]), "+f"(c[1]), "+f"(c[2]), "+f"(c[3])
        : "r"(a0), "r"(a1), "r"(a2), "r"(a3), "r"(b0), "r"(b1));
}
__device__ __forceinline__ void cp16(uint32_t dst, const void* src) {
    asm volatile("cp.async.cg.shared.global [%0], [%1], 16;"
                 :: "r"(dst), "l"(src));
}
__device__ __forceinline__ uint32_t packh2(float a, float b) {
    __half2 h = __floats2half2_rn(a, b);
    return *(uint32_t*)&h;
}
__device__ __forceinline__ void ldsm4(uint32_t r[4], uint32_t addr) {
    asm volatile("ldmatrix.sync.aligned.m8n8.x4.shared.b16 {%0,%1,%2,%3}, [%4];"
                 : "=r"(r[0]), "=r"(r[1]), "=r"(r[2]), "=r"(r[3]) : "r"(addr));
}
__device__ __forceinline__ void ldsm4t(uint32_t r[4], uint32_t addr) {
    asm volatile("ldmatrix.sync.aligned.m8n8.x4.trans.shared.b16 {%0,%1,%2,%3}, [%4];"
                 : "=r"(r[0]), "=r"(r[1]), "=r"(r[2]), "=r"(r[3]) : "r"(addr));
}

// ---------------------------------------------------------------------------
// Prep kernels
// ---------------------------------------------------------------------------
__global__ void f32_to_h16(const float4* __restrict__ in,
                           uint32_t* __restrict__ out, int n4)
{
    int i = blockIdx.x * blockDim.x + threadIdx.x;
    if (i < n4) {
        float4 v = in[i];
        out[2 * i + 0] = packh2(v.x, v.y);
        out[2 * i + 1] = packh2(v.z, v.w);
    }
}

// Transposing weight pack: in [K][N] f32 -> out [N][K/2] fp16-pair words.
__global__ void pack_w16t(const float* __restrict__ in,
                          uint32_t* __restrict__ out, int N, int K)
{
    __shared__ float sm[64][33];
    const int n0 = blockIdx.x * 32;
    const int k0 = blockIdx.y * 64;
    const int tid = threadIdx.x;
#pragma unroll
    for (int i = 0; i < 8; i++) {
        int r = i * 8 + (tid >> 5);
        int n = tid & 31;
        sm[r][n] = in[(size_t)(k0 + r) * N + n0 + n];
    }
    __syncthreads();
    const int Kw = K >> 1;
#pragma unroll
    for (int i = 0; i < 4; i++) {
        int idx = i * 256 + tid;
        int n = idx >> 5, kkl = idx & 31;
        out[(size_t)(n0 + n) * Kw + (k0 >> 1) + kkl] =
            packh2(sm[2 * kkl][n], sm[2 * kkl + 1][n]);
    }
}

// cos/sin table (positions int64/int32 auto-detect)
__global__ void build_ctab(float2* __restrict__ ctab,
                           const int* __restrict__ pos32)
{
    const int s = blockIdx.x;
    const int j = threadIdx.x;
    const bool is64 = (pos32[1] == 0);
    const int  p    = is64 ? pos32[2 * s] : pos32[s];
    float inv = powf(10000.0f, -(float)(2 * j) * (1.0f / 128.0f));
    float sn, cs;
    sincosf((float)p * inv, &sn, &cs);
    ctab[s * 64 + j] = make_float2(cs, sn);
}

// ---------------------------------------------------------------------------
// fp16 HMMA GEMM (m16n8k16), cp.async 3-stage, BK=64, ldmatrix fragments.
// A: [M][K/2] words.  B: T-packed [N][K/2] words (same tile shape as A).
// 128 threads, 4 warps (2x2) of 64x64, manual fragment double-buffer.
// MODE 0: plain f32 store.  MODE 1: fused RoPE -> fp16 Q/K/V.
// ---------------------------------------------------------------------------
#define TBM 128
#define TBN 128
#define TBKW 32          // 64 k-elements = 32 pair-words
#define TSTR 36          // tile row stride (words)
#define STG  3
#define AS_W (TBM * TSTR)            // 4608
#define BS_W (TBN * TSTR)            // 4608
#define STAGE_W (AS_W + BS_W)        // 9216
#define GEMM_SMEM (STG * STAGE_W * 4)  // 110592 B

template <int MODE>
__global__ __launch_bounds__(128, 2)
void h16_gemm(const uint32_t* __restrict__ A, const uint32_t* __restrict__ B,
              float* __restrict__ C,
              uint32_t* __restrict__ Qh, uint32_t* __restrict__ Kh,
              uint32_t* __restrict__ Vn,
              const float2* __restrict__ ctab,
              int N, int K)
{
    extern __shared__ uint32_t smw[];
    const uint32_t sb = (uint32_t)__cvta_generic_to_shared(smw);

    const int tid  = threadIdx.x;
    const int lane = tid & 31;
    const int wid  = tid >> 5;
    const int wm   = wid >> 1;
    const int wn   = wid & 1;
    const int g    = lane >> 2;
    const int q    = lane & 3;
    const int l7   = lane & 7;
    const int lb8  = (lane >> 3) & 1;
    const int lb16 = (lane >> 4) & 1;

    const int brow = blockIdx.y;
    const int bcol = blockIdx.x;
    const int Kw   = K >> 1;
    const uint32_t* Ab = A + (size_t)brow * TBM * Kw;
    const uint32_t* Bb = B + (size_t)bcol * TBN * Kw;

    int aoff[4], boff[4];
#pragma unroll
    for (int tm = 0; tm < 4; tm++)
        aoff[tm] = (wm * 64 + tm * 16 + l7 + 8 * lb8) * TSTR + 4 * lb16;
#pragma unroll
    for (int p = 0; p < 4; p++)
        boff[p] = (wn * 64 + p * 16 + l7 + 8 * lb16) * TSTR + 4 * lb8;

    const int T = K / 64;

#pragma unroll
    for (int p = 0; p < STG - 1; p++) {
        const uint32_t sa  = sb + (uint32_t)(p * STAGE_W) * 4u;
        const uint32_t sbb = sa + (uint32_t)AS_W * 4u;
        const int ktw = p * TBKW;
#pragma unroll
        for (int i = 0; i < 8; i++) {
            const int c   = tid + i * 128;
            const int row = c >> 3, cw = (c & 7) << 2;
            cp16(sa  + (uint32_t)(row * TSTR + cw) * 4u,
                 Ab + (size_t)row * Kw + ktw + cw);
            cp16(sbb + (uint32_t)(row * TSTR + cw) * 4u,
                 Bb + (size_t)row * Kw + ktw + cw);
        }
        asm volatile("cp.async.commit_group;");
    }

    float acc[4][8][4];
#pragma unroll
    for (int i = 0; i < 4; i++)
#pragma unroll
        for (int j = 0; j < 8; j++)
#pragma unroll
            for (int r = 0; r < 4; r++) acc[i][j][r] = 0.0f;

    uint32_t af[2][4][4], bf[2][8][2];

    int stage = 0;
    for (int t = 0; t < T; t++) {
        asm volatile("cp.async.wait_group %0;" :: "n"(STG - 2));
        __syncthreads();

        {
            const int tn = t + STG - 1;
            if (tn < T) {
                int st = stage + (STG - 1);
                if (st >= STG) st -= STG;
                const uint32_t sa  = sb + (uint32_t)(st * STAGE_W) * 4u;
                const uint32_t sbb = sa + (uint32_t)AS_W * 4u;
                const int ktw = tn * TBKW;
#pragma unroll
                for (int i = 0; i < 8; i++) {
                    const int c   = tid + i * 128;
                    const int row = c >> 3, cw = (c & 7) << 2;
                    cp16(sa  + (uint32_t)(row * TSTR + cw) * 4u,
                         Ab + (size_t)row * Kw + ktw + cw);
                    cp16(sbb + (uint32_t)(row * TSTR + cw) * 4u,
                         Bb + (size_t)row * Kw + ktw + cw);
                }
            }
            asm volatile("cp.async.commit_group;");
        }

        const uint32_t sa  = sb + (uint32_t)(stage * STAGE_W) * 4u;
        const uint32_t sbb = sa + (uint32_t)AS_W * 4u;

        auto ldfrag = [&](uint32_t afr[4][4], uint32_t bfr[8][2], int kw) {
#pragma unroll
            for (int tm = 0; tm < 4; tm++)
                ldsm4(afr[tm], sa + (uint32_t)(aoff[tm] + kw) * 4u);
#pragma unroll
            for (int p = 0; p < 4; p++) {
                uint32_t tmp[4];
                ldsm4(tmp, sbb + (uint32_t)(boff[p] + kw) * 4u);
                bfr[2 * p][0] = tmp[0]; bfr[2 * p][1] = tmp[1];
                bfr[2 * p + 1][0] = tmp[2]; bfr[2 * p + 1][1] = tmp[3];
            }
        };

        ldfrag(af[0], bf[0], 0);
#pragma unroll
        for (int s = 0; s < 4; s++) {
            const int cur = s & 1;
            const int nxt = cur ^ 1;
            if (s + 1 < 4) ldfrag(af[nxt], bf[nxt], (s + 1) * 8);
#pragma unroll
            for (int tm = 0; tm < 4; tm++)
#pragma unroll
                for (int tn2 = 0; tn2 < 8; tn2++)
                    mma_f16(acc[tm][tn2],
                            af[cur][tm][0], af[cur][tm][1],
                            af[cur][tm][2], af[cur][tm][3],
                            bf[cur][tn2][0], bf[cur][tn2][1]);
        }
        if (++stage == STG) stage = 0;
    }

    // ---------------- epilogue ----------------
    if (MODE == 0) {
#pragma unroll
        for (int tm = 0; tm < 4; tm++) {
            const int row = brow * TBM + wm * 64 + tm * 16 + g;
#pragma unroll
            for (int tn2 = 0; tn2 < 8; tn2++) {
                const int col = bcol * TBN + wn * 64 + tn2 * 8 + 2 * q;
                *(float2*)&C[(size_t)row * N + col] =
                    make_float2(acc[tm][tn2][0], acc[tm][tn2][1]);
                *(float2*)&C[(size_t)(row + 8) * N + col] =
                    make_float2(acc[tm][tn2][2], acc[tm][tn2][3]);
            }
        }
    } else {
        const int col0  = bcol * TBN;
        const int which = col0 >> 11;
        const int h     = (col0 & 2047) >> 7;
        uint32_t* dst = (which == 0) ? Qh : ((which == 1) ? Kh : Vn);
#pragma unroll
        for (int tm = 0; tm < 4; tm++) {
            const int rowtok = brow * TBM + wm * 64 + tm * 16 + g;
            const int bb  = rowtok >> 11;
            const int ss  = rowtok & 2047;
            const int rt8 = rowtok + 8;
            const int bb8 = rt8 >> 11;
            const int ss8 = rt8 & 2047;
            uint32_t* b0 = dst + ((size_t)(bb  * NHEADS + h) * S_LEN + ss)  * 64;
            uint32_t* b8 = dst + ((size_t)(bb8 * NHEADS + h) * S_LEN + ss8) * 64;
#pragma unroll
            for (int tn2 = 0; tn2 < 8; tn2++) {
                const int jl = wn * 32 + tn2 * 4 + q;
                if (which < 2) {
                    const float2 c0 = ctab[ss  * 64 + jl];
                    const float2 c8 = ctab[ss8 * 64 + jl];
                    float x1 = acc[tm][tn2][0], x2 = acc[tm][tn2][1];
                    b0[jl] = packh2(x1 * c0.x - x2 * c0.y, x1 * c0.y + x2 * c0.x);
                    x1 = acc[tm][tn2][2]; x2 = acc[tm][tn2][3];
                    b8[jl] = packh2(x1 * c8.x - x2 * c8.y, x1 * c8.y + x2 * c8.x);
                } else {
                    b0[jl] = packh2(acc[tm][tn2][0], acc[tm][tn2][1]);
                    b8[jl] = packh2(acc[tm][tn2][2], acc[tm][tn2][3]);
                }
            }
        }
    }
}

// ---------------------------------------------------------------------------
// Flash attention, fp16 HMMA + ldmatrix, causal, online softmax.
// Q/K/V smem all [row][QSH] k-/d-contiguous; V fragments via ldmatrix.trans
// straight from the natural [s][d] layout (no transpose pass, no packed V).
// Heavy q-blocks launch first (qb reversed) to pack the final wave.
// Block: 128 q-rows, 8 warps x 16 rows, 256 threads.  Output fp16 pairs.
// ---------------------------------------------------------------------------
#define FQ   128
#define FKT  64
#define QSH  68     // row stride (words)
#define SW_K0 (FQ * QSH)                  // 8704
#define SW_V0 (SW_K0 + 2 * FKT * QSH)     // 17408
#define FLASH_H_SMEM ((SW_V0 + 2 * FKT * QSH) * 4)   // 104448 B

__global__ __launch_bounds__(256, 1)
void flash_h16(const uint32_t* __restrict__ Qh, const uint32_t* __restrict__ Kh,
               const uint32_t* __restrict__ Vn, uint32_t* __restrict__ Oh)
{
    extern __shared__ uint32_t smw[];
    const int tid  = threadIdx.x;
    const int lane = tid & 31;
    const int w    = tid >> 5;
    const int g    = lane >> 2;
    const int q    = lane & 3;
    const int l7   = lane & 7;
    const int lb8  = (lane >> 3) & 1;
    const int lb16 = (lane >> 4) & 1;

    const int qb = (int)(gridDim.x - 1 - blockIdx.x);   // heavy blocks first
    const int h  = blockIdx.y;
    const int b  = blockIdx.z;
    const int bh = b * NHEADS + h;

    const uint32_t* Qg = Qh + ((size_t)bh * S_LEN + (size_t)qb * FQ) * 64;
    const uint32_t* Kg = Kh + (size_t)bh * S_LEN * 64;
    const uint32_t* Vg = Vn + (size_t)bh * S_LEN * 64;

    const uint32_t sb = (uint32_t)__cvta_generic_to_shared(smw);

    // ldmatrix base offsets
    const int qoff = (w * 16 + l7 + 8 * lb8) * QSH + 4 * lb16;
    int koff[4], voff[8];
#pragma unroll
    for (int p = 0; p < 4; p++)
        koff[p] = (p * 16 + l7 + 8 * lb16) * QSH + 4 * lb8;
    // V (.trans): matrices 0/1 = k-rows 0-7/8-15 at d0; 2/3 = same at d0+8
#pragma unroll
    for (int p = 0; p < 8; p++)
        voff[p] = (l7 + 8 * lb8) * QSH + p * 8 + 4 * lb16;

    // Q tile: 2048 chunks, 8/thread
#pragma unroll
    for (int i = 0; i < 8; i++) {
        int c   = i * 256 + tid;
        int row = c >> 4, cw = (c & 15) << 2;
        cp16(sb + (uint32_t)(row * QSH + cw) * 4u, Qg + (size_t)row * 64 + cw);
    }
    // K tile 0 + V tile 0: 1024 chunks each, 4+4/thread
#pragma unroll
    for (int i = 0; i < 4; i++) {
        int c = i * 256 + tid;
        int row = c >> 4, cw = (c & 15) << 2;
        cp16(sb + (uint32_t)(SW_K0 + row * QSH + cw) * 4u,
             Kg + (size_t)row * 64 + cw);
        cp16(sb + (uint32_t)(SW_V0 + row * QSH + cw) * 4u,
             Vg + (size_t)row * 64 + cw);
    }
    asm volatile("cp.async.commit_group;");

    float m0 = -1e30f, m1 = -1e30f, l0 = 0.0f, l1 = 0.0f;
    float acc[16][4];
#pragma unroll
    for (int nf = 0; nf < 16; nf++)
#pragma unroll
        for (int c = 0; c < 4; c++) acc[nf][c] = 0.0f;

    const float SC = 0.088388347648318447f;
    const int ntiles = 2 * qb + 2;
    const int r0 = qb * FQ + w * 16 + g;
    const int r1 = r0 + 8;

    for (int kt = 0; kt < ntiles; kt++) {
        asm volatile("cp.async.wait_group 0;");
        __syncthreads();

        if (kt + 1 < ntiles) {
            const int nb = (kt + 1) & 1;
            const uint32_t* Ks = Kg + (size_t)(kt + 1) * FKT * 64;
            const uint32_t* Vs = Vg + (size_t)(kt + 1) * FKT * 64;
#pragma unroll
            for (int i = 0; i < 4; i++) {
                int c = i * 256 + tid;
                int row = c >> 4, cw = (c & 15) << 2;
                cp16(sb + (uint32_t)(SW_K0 + nb * FKT * QSH + row * QSH + cw) * 4u,
                     Ks + (size_t)row * 64 + cw);
                cp16(sb + (uint32_t)(SW_V0 + nb * FKT * QSH + row * QSH + cw) * 4u,
                     Vs + (size_t)row * 64 + cw);
            }
            asm volatile("cp.async.commit_group;");
        }

        if (kt * FKT <= qb * FQ + w * 16 + 15) {
            const uint32_t sqb = sb;
            const uint32_t skb = sb + (uint32_t)(SW_K0 + (kt & 1) * FKT * QSH) * 4u;
            const uint32_t svb = sb + (uint32_t)(SW_V0 + (kt & 1) * FKT * QSH) * 4u;

            // ---- S = Q K^T ----
            float sc[8][4];
#pragma unroll
            for (int nf = 0; nf < 8; nf++)
#pragma unroll
                for (int c = 0; c < 4; c++) sc[nf][c] = 0.0f;

#pragma unroll
            for (int ds = 0; ds < 8; ds++) {
                const int kw = ds * 8;
                uint32_t a[4];
                ldsm4(a, sqb + (uint32_t)(qoff + kw) * 4u);
#pragma unroll
                for (int p = 0; p < 4; p++) {
                    uint32_t kb[4];
                    ldsm4(kb, skb + (uint32_t)(koff[p] + kw) * 4u);
                    mma_f16(sc[2 * p],     a[0], a[1], a[2], a[3], kb[0], kb[1]);
                    mma_f16(sc[2 * p + 1], a[0], a[1], a[2], a[3], kb[2], kb[3]);
                }
            }

            // ---- causal mask ----
            if (kt * FKT + FKT - 1 > r0) {
#pragma unroll
                for (int nf = 0; nf < 8; nf++) {
#pragma unroll
                    for (int cb = 0; cb < 2; cb++) {
                        int kcol = kt * FKT + nf * 8 + 2 * q + cb;
                        if (kcol > r0) sc[nf][cb]     = -1e30f;
                        if (kcol > r1) sc[nf][2 + cb] = -1e30f;
                    }
                }
            }

            // ---- online softmax (quad-local) ----
            float mx0 = -1e30f, mx1 = -1e30f;
#pragma unroll
            for (int nf = 0; nf < 8; nf++) {
                mx0 = fmaxf(mx0, fmaxf(sc[nf][0], sc[nf][1]));
                mx1 = fmaxf(mx1, fmaxf(sc[nf][2], sc[nf][3]));
            }
            mx0 = fmaxf(mx0, __shfl_xor_sync(0xffffffffu, mx0, 1));
            mx0 = fmaxf(mx0, __shfl_xor_sync(0xffffffffu, mx0, 2));
            mx1 = fmaxf(mx1, __shfl_xor_sync(0xffffffffu, mx1, 1));
            mx1 = fmaxf(mx1, __shfl_xor_sync(0xffffffffu, mx1, 2));

            float mn0 = fmaxf(m0, mx0), mn1 = fmaxf(m1, mx1);
            float al0 = __expf(SC * (m0 - mn0));
            float al1 = __expf(SC * (m1 - mn1));
            m0 = mn0; m1 = mn1;

            float rs0 = 0.0f, rs1 = 0.0f;
#pragma unroll
            for (int nf = 0; nf < 8; nf++) {
                float p0 = __half2float(__float2half_rn(__expf(SC * (sc[nf][0] - m0))));
                float p1 = __half2float(__float2half_rn(__expf(SC * (sc[nf][1] - m0))));
                float p2 = __half2float(__float2half_rn(__expf(SC * (sc[nf][2] - m1))));
                float p3 = __half2float(__float2half_rn(__expf(SC * (sc[nf][3] - m1))));
                sc[nf][0] = p0; sc[nf][1] = p1; sc[nf][2] = p2; sc[nf][3] = p3;
                rs0 += p0 + p1;
                rs1 += p2 + p3;
            }
            rs0 += __shfl_xor_sync(0xffffffffu, rs0, 1);
            rs0 += __shfl_xor_sync(0xffffffffu, rs0, 2);
            rs1 += __shfl_xor_sync(0xffffffffu, rs1, 1);
            rs1 += __shfl_xor_sync(0xffffffffu, rs1, 2);
            l0 = l0 * al0 + rs0;
            l1 = l1 * al1 + rs1;

#pragma unroll
            for (int nf = 0; nf < 16; nf++) {
                acc[nf][0] *= al0; acc[nf][1] *= al0;
                acc[nf][2] *= al1; acc[nf][3] *= al1;
            }

            // ---- O += P V : V B-frags via ldmatrix.trans from [s][d] ----
#pragma unroll
            for (int j = 0; j < 4; j++) {
                uint32_t pa0 = packh2(sc[2 * j][0],     sc[2 * j][1]);
                uint32_t pa1 = packh2(sc[2 * j][2],     sc[2 * j][3]);
                uint32_t pa2 = packh2(sc[2 * j + 1][0], sc[2 * j + 1][1]);
                uint32_t pa3 = packh2(sc[2 * j + 1][2], sc[2 * j + 1][3]);
#pragma unroll
                for (int p = 0; p < 8; p++) {
                    uint32_t vb[4];
                    ldsm4t(vb, svb + (uint32_t)(voff[p] + j * 16 * QSH) * 4u);
                    mma_f16(acc[2 * p],     pa0, pa1, pa2, pa3, vb[0], vb[1]);
                    mma_f16(acc[2 * p + 1], pa0, pa1, pa2, pa3, vb[2], vb[3]);
                }
            }
        }
    }

    // ---- epilogue: normalize, emit fp16 pair-words ----
    const float inv0 = 1.0f / l0;
    const float inv1 = 1.0f / l1;
    uint32_t* o0 = Oh + (size_t)(b * S_LEN + r0) * (D_MODEL / 2) + h * 64;
    uint32_t* o1 = o0 + (size_t)8 * (D_MODEL / 2);
#pragma unroll
    for (int nf = 0; nf < 16; nf++) {
        const int wc = nf * 4 + q;
        o0[wc] = packh2(acc[nf][0] * inv0, acc[nf][1] * inv0);
        o1[wc] = packh2(acc[nf][2] * inv1, acc[nf][3] * inv1);
    }
}

// ---------------------------------------------------------------------------
// Launch
// ---------------------------------------------------------------------------
extern "C" void kernel_launch(void* const* d_in, const int* in_sizes, int n_in,
                              void* d_out, int out_size)
{
    const float* x     = (const float*)d_in[0];
    const int*   pos32 = (const int*)d_in[1];
    const float* w_qkv = (const float*)d_in[2];
    const float* w_o   = (const float*)d_in[3];
    float* out         = (float*)d_out;

    uint32_t *xh, *wqkvh, *woh, *qh, *kh, *vn, *attnh;
    float2* ctab;
    cudaGetSymbolAddress((void**)&xh,    g_xh);
    cudaGetSymbolAddress((void**)&wqkvh, g_wqkvh);
    cudaGetSymbolAddress((void**)&woh,   g_woh);
    cudaGetSymbolAddress((void**)&qh,    g_qh);
    cudaGetSymbolAddress((void**)&kh,    g_kh);
    cudaGetSymbolAddress((void**)&vn,    g_vn);
    cudaGetSymbolAddress((void**)&attnh, g_attnh);
    cudaGetSymbolAddress((void**)&ctab,  g_ctab);

    cudaFuncSetAttribute(h16_gemm<1>,
                         cudaFuncAttributeMaxDynamicSharedMemorySize, GEMM_SMEM);
    cudaFuncSetAttribute(h16_gemm<0>,
                         cudaFuncAttributeMaxDynamicSharedMemorySize, GEMM_SMEM);
    cudaFuncSetAttribute(flash_h16,
                         cudaFuncAttributeMaxDynamicSharedMemorySize, FLASH_H_SMEM);

    // 0) prep: x -> fp16; weights -> transposed-packed fp16; rope table
    {
        const int nx4 = NTOK * D_MODEL / 4;
        f32_to_h16<<<nx4 / 256, 256>>>((const float4*)x, xh, nx4);
        pack_w16t<<<dim3(QKV_N / 32, D_MODEL / 64), 256>>>(w_qkv, wqkvh,
                                                           QKV_N, D_MODEL);
        pack_w16t<<<dim3(D_MODEL / 32, D_MODEL / 64), 256>>>(w_o, woh,
                                                             D_MODEL, D_MODEL);
        build_ctab<<<S_LEN, 64>>>(ctab, pos32);
    }

    // 1) QKV projection (fp16 HMMA + ldmatrix) with fused RoPE epilogue
    h16_gemm<1><<<dim3(QKV_N / TBN, NTOK / TBM), 128, GEMM_SMEM>>>(
        xh, wqkvh, nullptr, qh, kh, vn, ctab, QKV_N, D_MODEL);

    // 2) causal flash attention (fp16 HMMA + ldmatrix, V via .trans)
    flash_h16<<<dim3(S_LEN / FQ, NHEADS, BATCH), 256, FLASH_H_SMEM>>>(
        qh, kh, vn, attnh);

    // 3) output projection (fp16 HMMA + ldmatrix) -> f32 out
    h16_gemm<0><<<dim3(D_MODEL / TBN, NTOK / TBM), 128, GEMM_SMEM>>>(
        attnh, woh, out, nullptr, nullptr, nullptr, nullptr, D_MODEL, D_MODEL);
}